// round 4
// baseline (speedup 1.0000x reference)
#include <cuda_runtime.h>
#include <string.h>

#define BB 8
#define TT 8192
#define SN 8192
#define FF 64
#define DD 64
#define MMF 128
#define TWOM 256
#define EPSF 1e-9f
#define SCALEF 0.0625f   /* 1/sqrt(2*128) */

#define NBLK 148         /* kv blocks == SM count */
#define NTILES 1024      /* 64-row tiles total (128 per batch) */
#define XP 66
#define VP 68
#define KPP 258
#define KVW 66           /* kv row stride (col 64 = normalizer) */

__device__ float g_part[(size_t)NBLK * 2 * TWOM * KVW];   // ~20 MB
__device__ float g_kv[BB * TWOM * KVW];

static __device__ __forceinline__ float2 ffma2(float2 a, float2 b, float2 c) {
    unsigned long long au, bu, cu, du;
    memcpy(&au, &a, 8); memcpy(&bu, &b, 8); memcpy(&cu, &c, 8);
    asm("fma.rn.f32x2 %0, %1, %2, %3;" : "=l"(du) : "l"(au), "l"(bu), "l"(cu));
    float2 d; memcpy(&d, &du, 8);
    return d;
}

// ---------------------------------------------------------------------------
// Kernel 1: 148 balanced blocks over 1024 flattened 64-row tiles. 512 threads.
// Register-staged (pipelined) K/V tile loads. Accumulator flushed per batch
// segment (<=2 per block) into g_part[blk][seg].
// ---------------------------------------------------------------------------
__global__ __launch_bounds__(512, 1)
void kv_kernel(const float* __restrict__ key,
               const float* __restrict__ value,
               const float* __restrict__ omega) {
    extern __shared__ float sm[];
    float* omega_s = sm;                 // 8192
    float* x_s     = sm + 8192;          // 64*XP
    float* v_s     = x_s + 64 * XP;      // 64*VP
    float* kphi    = v_s + 64 * VP;      // 64*KPP

    const int tid = threadIdx.x;
    const int blk = blockIdx.x;
    const int tb = (blk * NTILES) / NBLK;
    const int te = ((blk + 1) * NTILES) / NBLK;

    for (int idx = tid; idx < MMF * FF; idx += 512) {
        int m = idx >> 6, f = idx & 63;
        omega_s[f * MMF + m] = omega[idx];
    }

    const int rg = tid & 15;
    const int mg = (tid >> 4) & 31;
    const int fg = tid & 63;
    const int dgrp = tid >> 6;
    const int ldr = tid >> 4;            // load row base
    const int ldc = (tid & 15) * 4;      // load col

    float2 acc[4][4];
#pragma unroll
    for (int j = 0; j < 4; ++j)
#pragma unroll
        for (int p = 0; p < 4; ++p) acc[j][p] = make_float2(0.f, 0.f);
    float accn[4] = {0.f, 0.f, 0.f, 0.f};
    int seg = 0;

    // prefetch first tile into registers
    float4 px[2], pv[2];
    {
        int t = tb, b = t >> 7, s0 = (t & 127) * 64;
        const float4* kp = (const float4*)(key   + ((size_t)b * SN + s0) * FF);
        const float4* vp = (const float4*)(value + ((size_t)b * SN + s0) * FF);
#pragma unroll
        for (int q = 0; q < 2; ++q) { px[q] = kp[tid + q * 512]; pv[q] = vp[tid + q * 512]; }
    }

    for (int t = tb; t < te; ++t) {
        __syncthreads();   // previous tile fully consumed
#pragma unroll
        for (int q = 0; q < 2; ++q) {
            int r = ldr + q * 32;
            float* xd = &x_s[r * XP + ldc];
            *(float2*)xd       = make_float2(px[q].x, px[q].y);
            *(float2*)(xd + 2) = make_float2(px[q].z, px[q].w);
            *(float4*)&v_s[r * VP + ldc] = pv[q];
        }
        if (t + 1 < te) {   // stage next tile ~13k cycles ahead
            int tn = t + 1, b = tn >> 7, s0 = (tn & 127) * 64;
            const float4* kp = (const float4*)(key   + ((size_t)b * SN + s0) * FF);
            const float4* vp = (const float4*)(value + ((size_t)b * SN + s0) * FF);
#pragma unroll
            for (int q = 0; q < 2; ++q) { px[q] = kp[tid + q * 512]; pv[q] = vp[tid + q * 512]; }
        }
        __syncthreads();

        // phi: 4 rows x 2 m-pairs per thread, ssq fused
        float2 xw[4][2], ss2[4];
#pragma unroll
        for (int k = 0; k < 4; ++k) {
            ss2[k] = make_float2(0.f, 0.f);
            xw[k][0] = make_float2(0.f, 0.f);
            xw[k][1] = make_float2(0.f, 0.f);
        }
#pragma unroll 4
        for (int f = 0; f < FF; f += 2) {
            float2 xv[4];
#pragma unroll
            for (int k = 0; k < 4; ++k)
                xv[k] = *(const float2*)&x_s[(rg + 16 * k) * XP + f];
            const float2* om0 = (const float2*)&omega_s[f * MMF];
            const float2* om1 = (const float2*)&omega_s[(f + 1) * MMF];
            float2 o0[2], o1[2];
#pragma unroll
            for (int i = 0; i < 2; ++i) { o0[i] = om0[mg + 32 * i]; o1[i] = om1[mg + 32 * i]; }
#pragma unroll
            for (int k = 0; k < 4; ++k) {
                ss2[k] = ffma2(xv[k], xv[k], ss2[k]);
                float2 a0 = make_float2(xv[k].x, xv[k].x);
                float2 a1 = make_float2(xv[k].y, xv[k].y);
#pragma unroll
                for (int i = 0; i < 2; ++i) {
                    xw[k][i] = ffma2(a0, o0[i], xw[k][i]);
                    xw[k][i] = ffma2(a1, o1[i], xw[k][i]);
                }
            }
        }
#pragma unroll
        for (int k = 0; k < 4; ++k) {
            int r = rg + 16 * k;
            float sc = 0.5f * (ss2[k].x + ss2[k].y);
            float* kr = &kphi[r * KPP];
#pragma unroll
            for (int i = 0; i < 2; ++i) {
                int m = 2 * (mg + 32 * i);
                float w0 = xw[k][i].x, w1 = xw[k][i].y;
                *(float2*)&kr[m] = make_float2(
                    (__expf(w0 - sc) + EPSF) * SCALEF,
                    (__expf(w1 - sc) + EPSF) * SCALEF);
                *(float2*)&kr[m + MMF] = make_float2(
                    (__expf(-w0 - sc) + EPSF) * SCALEF,
                    (__expf(-w1 - sc) + EPSF) * SCALEF);
            }
        }
        __syncthreads();

        // kv accumulate: 4 features x 8 cols per thread
#pragma unroll 2
        for (int r = 0; r < 64; ++r) {
            const float* kr = &kphi[r * KPP + 2 * fg];
            float2 k01 = *(const float2*)kr;
            float2 k23 = *(const float2*)(kr + MMF);
            const float2* vr = (const float2*)&v_s[r * VP + 8 * dgrp];
            float2 vv[4];
#pragma unroll
            for (int p = 0; p < 4; ++p) vv[p] = vr[p];
            float kk[4] = {k01.x, k01.y, k23.x, k23.y};
#pragma unroll
            for (int j = 0; j < 4; ++j) {
                float2 kj = make_float2(kk[j], kk[j]);
#pragma unroll
                for (int p = 0; p < 4; ++p) acc[j][p] = ffma2(kj, vv[p], acc[j][p]);
            }
            if (dgrp == 0) {
#pragma unroll
                for (int j = 0; j < 4; ++j) accn[j] += kk[j];
            }
        }

        // flush at batch boundary or end
        if (t + 1 == te || ((t + 1) >> 7) != (t >> 7)) {
            float* base = &g_part[(size_t)(blk * 2 + seg) * TWOM * KVW];
#pragma unroll
            for (int j = 0; j < 4; ++j) {
                int feat = 2 * fg + (j & 1) + (j >> 1) * MMF;
                float* dst = base + feat * KVW;
#pragma unroll
                for (int p = 0; p < 4; ++p)
                    *(float2*)&dst[8 * dgrp + 2 * p] = acc[j][p];
                if (dgrp == 0) dst[64] = accn[j];
            }
            ++seg;
#pragma unroll
            for (int j = 0; j < 4; ++j) {
#pragma unroll
                for (int p = 0; p < 4; ++p) acc[j][p] = make_float2(0.f, 0.f);
                accn[j] = 0.f;
            }
        }
    }
}

// ---------------------------------------------------------------------------
// Kernel 2: deterministic reduction. Segment->batch mapping recomputed
// analytically per block. float4 vectorized. grid (17, BB) x 256.
// ---------------------------------------------------------------------------
__global__ void reduce_kernel() {
    const int per_b4 = TWOM * KVW / 4;   // 4224
    int idx = blockIdx.x * blockDim.x + threadIdx.x;
    int b = blockIdx.y;
    if (idx >= per_b4) return;
    float4 s = make_float4(0.f, 0.f, 0.f, 0.f);
    for (int i = 0; i < NBLK; ++i) {
        int tb = (i * NTILES) / NBLK;
        int te = ((i + 1) * NTILES) / NBLK;
        int b0 = tb >> 7;
        int bl = (te - 1) >> 7;
        int slot = -1;
        if (b0 == b) slot = 0;
        else if (bl == b && bl != b0) slot = 1;
        if (slot >= 0) {
            float4 v = ((const float4*)g_part)[(size_t)(i * 2 + slot) * per_b4 + idx];
            s.x += v.x; s.y += v.y; s.z += v.z; s.w += v.w;
        }
    }
    ((float4*)g_kv)[(size_t)b * per_b4 + idx] = s;
}

// ---------------------------------------------------------------------------
// Kernel 3: block = (b, 128 t-rows), 512 threads (16 warps).
// phi(query) transposed in SMEM (2 subpasses) -> qkv GEMM -> normalize.
// ---------------------------------------------------------------------------
__global__ __launch_bounds__(512, 1)
void qkv_kernel(const float* __restrict__ query,
                const float* __restrict__ omega,
                float* __restrict__ out) {
    extern __shared__ float sm[];
    float* qphiT   = sm;                         // [256][130]
    float* unionA  = sm + TWOM * 130;
    float* omega_s = unionA;                     // phase1: 8192
    float* x_s     = unionA + 8192;              // phase1: 64*XP
    float* kv_s    = unionA;                     // phase2: 256*KVW
    float* norm_s  = sm + TWOM * 130 + TWOM * KVW;  // 128

    const int tid = threadIdx.x;
    const int b = blockIdx.y;
    const int t0 = blockIdx.x * 128;

    for (int idx = tid; idx < MMF * FF; idx += 512) {
        int m = idx >> 6, f = idx & 63;
        omega_s[f * MMF + m] = omega[idx];
    }

    const int rg4 = tid & 15;        // rows rg4+16k (k<4)
    const int mgk = tid >> 4;        // pairs mgk+32i (i<2), mgk in 0..31

    for (int sp = 0; sp < 2; ++sp) {
        const int rbase = sp * 64;
        __syncthreads();
        const float4* qp = (const float4*)(query + ((size_t)b * TT + t0 + rbase) * FF);
#pragma unroll
        for (int q = 0; q < 2; ++q) {
            int idx = tid + q * 512;
            int r = idx >> 4, c = (idx & 15) * 4;
            float4 xv = qp[idx];
            float* xd = &x_s[r * XP + c];
            *(float2*)xd       = make_float2(xv.x, xv.y);
            *(float2*)(xd + 2) = make_float2(xv.z, xv.w);
        }
        __syncthreads();

        float2 xw[4][2], ss2[4];
#pragma unroll
        for (int k = 0; k < 4; ++k) {
            ss2[k] = make_float2(0.f, 0.f);
            xw[k][0] = make_float2(0.f, 0.f);
            xw[k][1] = make_float2(0.f, 0.f);
        }
#pragma unroll 4
        for (int f = 0; f < FF; f += 2) {
            float2 xv[4];
#pragma unroll
            for (int k = 0; k < 4; ++k)
                xv[k] = *(const float2*)&x_s[(rg4 + 16 * k) * XP + f];
            const float2* om0 = (const float2*)&omega_s[f * MMF];
            const float2* om1 = (const float2*)&omega_s[(f + 1) * MMF];
            float2 o0[2], o1[2];
#pragma unroll
            for (int i = 0; i < 2; ++i) { o0[i] = om0[mgk + 32 * i]; o1[i] = om1[mgk + 32 * i]; }
#pragma unroll
            for (int k = 0; k < 4; ++k) {
                ss2[k] = ffma2(xv[k], xv[k], ss2[k]);
                float2 a0 = make_float2(xv[k].x, xv[k].x);
                float2 a1 = make_float2(xv[k].y, xv[k].y);
#pragma unroll
                for (int i = 0; i < 2; ++i) {
                    xw[k][i] = ffma2(a0, o0[i], xw[k][i]);
                    xw[k][i] = ffma2(a1, o1[i], xw[k][i]);
                }
            }
        }
#pragma unroll
        for (int k = 0; k < 4; ++k) {
            int r = rbase + rg4 + 16 * k;
            float sc = 0.5f * (ss2[k].x + ss2[k].y);
#pragma unroll
            for (int i = 0; i < 2; ++i) {
                int m = 2 * (mgk + 32 * i);
                float w0 = xw[k][i].x, w1 = xw[k][i].y;
                qphiT[m * 130 + r]             = (__expf(w0 - sc) + EPSF) * SCALEF;
                qphiT[(m + 1) * 130 + r]       = (__expf(w1 - sc) + EPSF) * SCALEF;
                qphiT[(m + MMF) * 130 + r]     = (__expf(-w0 - sc) + EPSF) * SCALEF;
                qphiT[(m + MMF + 1) * 130 + r] = (__expf(-w1 - sc) + EPSF) * SCALEF;
            }
        }
    }
    __syncthreads();

    {
        const float4* src = (const float4*)&g_kv[(size_t)b * TWOM * KVW];
#pragma unroll
        for (int q = 0; q < 9; ++q) {
            int idx = tid + q * 512;
            if (idx < TWOM * KVW / 4) ((float4*)kv_s)[idx] = src[idx];
        }
    }
    __syncthreads();

    // qkv GEMM: thread = rows {rg, rg+64} x cols {8cg..8cg+7}
    const int rg = tid & 63;
    const int cg = tid >> 6;     // 0..7
    float2 aA[4], aB[4];
#pragma unroll
    for (int p = 0; p < 4; ++p) { aA[p] = make_float2(0.f, 0.f); aB[p] = make_float2(0.f, 0.f); }
    float nA = 0.f, nB = 0.f;

#pragma unroll 4
    for (int m = 0; m < TWOM; ++m) {
        float qa = qphiT[m * 130 + rg];
        float qb = qphiT[m * 130 + rg + 64];
        const float2* kr = (const float2*)&kv_s[m * KVW + 8 * cg];
        float2 kvv[4];
#pragma unroll
        for (int p = 0; p < 4; ++p) kvv[p] = kr[p];
        float2 q0 = make_float2(qa, qa);
        float2 q1 = make_float2(qb, qb);
#pragma unroll
        for (int p = 0; p < 4; ++p) {
            aA[p] = ffma2(q0, kvv[p], aA[p]);
            aB[p] = ffma2(q1, kvv[p], aB[p]);
        }
        if (cg == 0) {
            float kn = kv_s[m * KVW + 64];
            nA = fmaf(qa, kn, nA);
            nB = fmaf(qb, kn, nB);
        }
    }
    if (cg == 0) { norm_s[rg] = nA; norm_s[rg + 64] = nB; }
    __syncthreads();

    float iA = 1.0f / norm_s[rg];
    float iB = 1.0f / norm_s[rg + 64];
    float* oA = out + ((size_t)b * TT + t0 + rg) * DD + 8 * cg;
    float* oB = out + ((size_t)b * TT + t0 + rg + 64) * DD + 8 * cg;
#pragma unroll
    for (int p = 0; p < 4; ++p) {
        *(float2*)&oA[2 * p] = make_float2(aA[p].x * iA, aA[p].y * iA);
        *(float2*)&oB[2 * p] = make_float2(aB[p].x * iB, aB[p].y * iB);
    }
}

// ---------------------------------------------------------------------------

#define KV_SMEM  ((8192 + 64*XP + 64*VP + 64*KPP) * 4)
#define QKV_SMEM ((TWOM*130 + TWOM*KVW + 128) * 4)

extern "C" void kernel_launch(void* const* d_in, const int* in_sizes, int n_in,
                              void* d_out, int out_size) {
    const float* query = (const float*)d_in[0];
    const float* value = (const float*)d_in[1];
    const float* key   = (const float*)d_in[2];
    const float* omega = (const float*)d_in[3];
    float* out = (float*)d_out;

    cudaFuncSetAttribute(kv_kernel, cudaFuncAttributeMaxDynamicSharedMemorySize, KV_SMEM);
    cudaFuncSetAttribute(qkv_kernel, cudaFuncAttributeMaxDynamicSharedMemorySize, QKV_SMEM);

    kv_kernel<<<NBLK, 512, KV_SMEM>>>(key, value, omega);
    reduce_kernel<<<dim3((TWOM * KVW / 4 + 255) / 256, BB), 256>>>();
    qkv_kernel<<<dim3(TT / 128, BB), 512, QKV_SMEM>>>(query, omega, out);
}

// round 5
// speedup vs baseline: 1.0667x; 1.0667x over previous
#include <cuda_runtime.h>
#include <string.h>

#define BB 8
#define TT 8192
#define SN 8192
#define FF 64
#define DD 64
#define MMF 128
#define TWOM 256
#define EPSF 1e-9f
#define SCALEF 0.0625f   /* 1/sqrt(2*128) */

#define KVW 66           /* kv row stride: col 64 = normalizer, 65 pad */

/* kv kernel config */
#define NBLK 296         /* 2 blocks per SM */
#define NTIL 2048        /* 32-row tiles (256 per batch) */
#define KXP 66
#define KVP 68
#define KPP 264

/* qkv kernel config */
#define QNB 148
#define QNT 1024         /* 64-row tiles (128 per batch) */
#define QXP 68
#define QPP 72

__device__ float g_part[(size_t)NBLK * 2 * TWOM * KVW];   // ~40 MB, zero-init
__device__ float g_kv[BB * TWOM * KVW];

static __device__ __forceinline__ float2 ffma2(float2 a, float2 b, float2 c) {
    unsigned long long au, bu, cu, du;
    memcpy(&au, &a, 8); memcpy(&bu, &b, 8); memcpy(&cu, &c, 8);
    asm("fma.rn.f32x2 %0, %1, %2, %3;" : "=l"(du) : "l"(au), "l"(bu), "l"(cu));
    float2 d; memcpy(&d, &du, 8);
    return d;
}
static __device__ __forceinline__ float2 fadd2(float2 a, float2 b) {
    unsigned long long au, bu, du;
    memcpy(&au, &a, 8); memcpy(&bu, &b, 8);
    asm("add.rn.f32x2 %0, %1, %2;" : "=l"(du) : "l"(au), "l"(bu));
    float2 d; memcpy(&d, &du, 8);
    return d;
}

// ---------------------------------------------------------------------------
// Kernel 1: 296 balanced blocks (2/SM) x 256 threads over 2048 32-row tiles.
// phi(key) tile in SMEM -> kv partial in registers -> g_part[blk][seg].
// ---------------------------------------------------------------------------
__global__ __launch_bounds__(256, 2)
void kv_kernel(const float* __restrict__ key,
               const float* __restrict__ value,
               const float* __restrict__ omega) {
    extern __shared__ float sm[];
    float* omega_s = sm;                 // 8192
    float* x_s     = sm + 8192;          // 32*KXP
    float* v_s     = x_s + 32 * KXP;     // 32*KVP
    float* kphi    = v_s + 32 * KVP;     // 32*KPP

    const int tid = threadIdx.x;
    const int blk = blockIdx.x;
    const int tb = (blk * NTIL) / NBLK;
    const int te = ((blk + 1) * NTIL) / NBLK;

    // omega transpose load (vectorized): omega_s[f*128+m]
    {
        const float4* om4 = (const float4*)omega;
#pragma unroll
        for (int q = 0; q < 8; ++q) {
            int idx = tid + q * 256;
            float4 v = om4[idx];
            int m = idx >> 4, f = (idx & 15) * 4;
            omega_s[f * MMF + m]       = v.x;
            omega_s[(f + 1) * MMF + m] = v.y;
            omega_s[(f + 2) * MMF + m] = v.z;
            omega_s[(f + 3) * MMF + m] = v.w;
        }
    }

    const int rg = tid & 7;            // phi rows rg+8k (k<4)
    const int mgp = tid >> 3;          // phi pairs mgp+32i (i<2), 0..31
    const int fg = tid & 63;           // acc features 2fg,2fg+1,+128,+129
    const int dgrp = tid >> 6;         // acc cols 16*dgrp..+15 (warp-uniform)
    const int ldr = tid >> 4;          // load rows ldr, ldr+16
    const int ldc = (tid & 15) * 4;

    float2 acc[4][8];
#pragma unroll
    for (int j = 0; j < 4; ++j)
#pragma unroll
        for (int p = 0; p < 8; ++p) acc[j][p] = make_float2(0.f, 0.f);
    float2 accn2[2] = {make_float2(0.f, 0.f), make_float2(0.f, 0.f)};
    int seg = 0;

    float4 px[2], pv[2];
    {
        int t = tb, b = t >> 8, s0 = (t & 255) * 32;
        const float4* kp = (const float4*)(key   + ((size_t)b * SN + s0) * FF);
        const float4* vp = (const float4*)(value + ((size_t)b * SN + s0) * FF);
#pragma unroll
        for (int q = 0; q < 2; ++q) { px[q] = kp[tid + q * 256]; pv[q] = vp[tid + q * 256]; }
    }

    for (int t = tb; t < te; ++t) {
        __syncthreads();   // previous tile fully consumed
#pragma unroll
        for (int q = 0; q < 2; ++q) {
            int r = ldr + q * 16;
            float* xd = &x_s[r * KXP + ldc];
            *(float2*)xd       = make_float2(px[q].x, px[q].y);
            *(float2*)(xd + 2) = make_float2(px[q].z, px[q].w);
            *(float4*)&v_s[r * KVP + ldc] = pv[q];
        }
        if (t + 1 < te) {
            int tn = t + 1, b = tn >> 8, s0 = (tn & 255) * 32;
            const float4* kp = (const float4*)(key   + ((size_t)b * SN + s0) * FF);
            const float4* vp = (const float4*)(value + ((size_t)b * SN + s0) * FF);
#pragma unroll
            for (int q = 0; q < 2; ++q) { px[q] = kp[tid + q * 256]; pv[q] = vp[tid + q * 256]; }
        }
        __syncthreads();

        // phi: 4 rows x 2 pairs per thread, ssq fused
        float2 xw[4][2], ss2[4];
#pragma unroll
        for (int k = 0; k < 4; ++k) {
            ss2[k] = make_float2(0.f, 0.f);
            xw[k][0] = make_float2(0.f, 0.f);
            xw[k][1] = make_float2(0.f, 0.f);
        }
#pragma unroll 4
        for (int f = 0; f < FF; f += 2) {
            float2 xv[4];
#pragma unroll
            for (int k = 0; k < 4; ++k)
                xv[k] = *(const float2*)&x_s[(rg + 8 * k) * KXP + f];
            const float2* om0 = (const float2*)&omega_s[f * MMF];
            const float2* om1 = (const float2*)&omega_s[(f + 1) * MMF];
            float2 o0[2], o1[2];
#pragma unroll
            for (int i = 0; i < 2; ++i) { o0[i] = om0[mgp + 32 * i]; o1[i] = om1[mgp + 32 * i]; }
#pragma unroll
            for (int k = 0; k < 4; ++k) {
                ss2[k] = ffma2(xv[k], xv[k], ss2[k]);
                float2 a0 = make_float2(xv[k].x, xv[k].x);
                float2 a1 = make_float2(xv[k].y, xv[k].y);
#pragma unroll
                for (int i = 0; i < 2; ++i) {
                    xw[k][i] = ffma2(a0, o0[i], xw[k][i]);
                    xw[k][i] = ffma2(a1, o1[i], xw[k][i]);
                }
            }
        }
#pragma unroll
        for (int k = 0; k < 4; ++k) {
            int r = rg + 8 * k;
            float sc = 0.5f * (ss2[k].x + ss2[k].y);
            float* kr = &kphi[r * KPP];
#pragma unroll
            for (int i = 0; i < 2; ++i) {
                int m = 2 * (mgp + 32 * i);           // <= 126
                float w0 = xw[k][i].x, w1 = xw[k][i].y;
                *(float2*)&kr[m] = make_float2(
                    (__expf(w0 - sc) + EPSF) * SCALEF,
                    (__expf(w1 - sc) + EPSF) * SCALEF);
                *(float2*)&kr[m + MMF] = make_float2(
                    (__expf(-w0 - sc) + EPSF) * SCALEF,
                    (__expf(-w1 - sc) + EPSF) * SCALEF);
            }
        }
        __syncthreads();

        // acc: 4 features x 16 cols per thread (v loads warp-broadcast)
#pragma unroll 2
        for (int r = 0; r < 32; ++r) {
            const float* kr = &kphi[r * KPP + 2 * fg];
            float2 k01 = *(const float2*)kr;
            float2 k23 = *(const float2*)(kr + MMF);
            const float2* vr = (const float2*)&v_s[r * KVP + 16 * dgrp];
            float2 vv[8];
#pragma unroll
            for (int p = 0; p < 8; ++p) vv[p] = vr[p];
            float kk[4] = {k01.x, k01.y, k23.x, k23.y};
#pragma unroll
            for (int j = 0; j < 4; ++j) {
                float2 kj = make_float2(kk[j], kk[j]);
#pragma unroll
                for (int p = 0; p < 8; ++p) acc[j][p] = ffma2(kj, vv[p], acc[j][p]);
            }
            if (dgrp == 0) {
                accn2[0] = fadd2(accn2[0], k01);
                accn2[1] = fadd2(accn2[1], k23);
            }
        }

        // flush at batch boundary or end
        if (t + 1 == te || ((t + 1) >> 8) != (t >> 8)) {
            float* base = &g_part[(size_t)(blk * 2 + seg) * TWOM * KVW];
            float an[4] = {accn2[0].x, accn2[0].y, accn2[1].x, accn2[1].y};
#pragma unroll
            for (int j = 0; j < 4; ++j) {
                int feat = 2 * fg + (j & 1) + (j >> 1) * MMF;
                float* dst = base + feat * KVW;
#pragma unroll
                for (int p = 0; p < 8; ++p)
                    *(float2*)&dst[16 * dgrp + 2 * p] = acc[j][p];
                if (dgrp == 0) dst[64] = an[j];
            }
            ++seg;
#pragma unroll
            for (int j = 0; j < 4; ++j)
#pragma unroll
                for (int p = 0; p < 8; ++p) acc[j][p] = make_float2(0.f, 0.f);
            accn2[0] = make_float2(0.f, 0.f);
            accn2[1] = make_float2(0.f, 0.f);
        }
    }
}

// ---------------------------------------------------------------------------
// Kernel 2: deterministic reduction, analytic segment->batch map.
// ---------------------------------------------------------------------------
__global__ void reduce_kernel() {
    const int per_b4 = TWOM * KVW / 4;   // 4224
    int idx = blockIdx.x * blockDim.x + threadIdx.x;
    int b = blockIdx.y;
    if (idx >= per_b4) return;
    float4 s = make_float4(0.f, 0.f, 0.f, 0.f);
    for (int i = 0; i < NBLK; ++i) {
        int tb = (i * NTIL) / NBLK;
        int te = ((i + 1) * NTIL) / NBLK;
        int b0 = tb >> 8;
        int bl = (te - 1) >> 8;
        int slot = (b0 == b) ? 0 : ((bl == b && bl != b0) ? 1 : -1);
        if (slot >= 0) {
            float4 v = ((const float4*)g_part)[(size_t)(i * 2 + slot) * per_b4 + idx];
            s.x += v.x; s.y += v.y; s.z += v.z; s.w += v.w;
        }
    }
    ((float4*)g_kv)[(size_t)b * per_b4 + idx] = s;
}

// ---------------------------------------------------------------------------
// Kernel 3: 148 persistent balanced blocks x 512 threads over 1024 64-row
// tiles. kv_s reloaded per batch (<=2x). phi -> qphiT (transposed) ->
// m-split GEMM -> smem combine -> normalize -> STG.
// ---------------------------------------------------------------------------
__global__ __launch_bounds__(512, 1)
void qkv_kernel(const float* __restrict__ query,
                const float* __restrict__ omega,
                float* __restrict__ out) {
    extern __shared__ float sm[];
    float* omega_s = sm;                     // 8192
    float* kv_s    = sm + 8192;              // 256*KVW = 16896
    float* xpart   = kv_s + TWOM * KVW;      // 64*QXP = 4352 (x tile / partials)
    float* qphiT   = xpart + 64 * QXP;       // 256*QPP = 18432
    float* npart   = qphiT + TWOM * QPP;     // 64

    const int tid = threadIdx.x;
    const int blk = blockIdx.x;
    const int tb = (blk * QNT) / QNB;
    const int te = ((blk + 1) * QNT) / QNB;

    {
        const float4* om4 = (const float4*)omega;
#pragma unroll
        for (int q = 0; q < 4; ++q) {
            int idx = tid + q * 512;
            float4 v = om4[idx];
            int m = idx >> 4, f = (idx & 15) * 4;
            omega_s[f * MMF + m]       = v.x;
            omega_s[(f + 1) * MMF + m] = v.y;
            omega_s[(f + 2) * MMF + m] = v.z;
            omega_s[(f + 3) * MMF + m] = v.w;
        }
    }

    const int prg = tid & 15;        // phi rows prg+16k (k<4)
    const int pmg = tid >> 4;        // phi pairs pmg+32i (i<2), 0..31
    const int ms = tid >> 8;         // m-split half
    const int rem = tid & 255;
    const int rgrp = rem & 15;       // rows 4*rgrp..+3
    const int cgrp = rem >> 4;       // cols 4*cgrp..+3

    int cur_b = -1;
    float4 px[2];
    {
        int t = tb, b = t >> 7, r0 = (t & 127) * 64;
        const float4* qp = (const float4*)(query + ((size_t)b * TT + r0) * FF);
#pragma unroll
        for (int q = 0; q < 2; ++q) px[q] = qp[tid + q * 512];
    }

    for (int t = tb; t < te; ++t) {
        const int b = t >> 7;
        const int r0 = (t & 127) * 64;
        if (b != cur_b) {
            __syncthreads();   // previous GEMM done with kv_s
            const float4* src = (const float4*)&g_kv[(size_t)b * TWOM * KVW];
#pragma unroll
            for (int q = 0; q < 9; ++q) {
                int idx = tid + q * 512;
                if (idx < TWOM * KVW / 4) ((float4*)kv_s)[idx] = src[idx];
            }
            cur_b = b;
        }
        __syncthreads();   // xpart free (prev combine done), kv_s ready
#pragma unroll
        for (int q = 0; q < 2; ++q) {
            int idx = tid + q * 512;
            int r = idx >> 4, c = (idx & 15) * 4;
            float* xd = &xpart[r * QXP + c];
            *(float2*)xd       = make_float2(px[q].x, px[q].y);
            *(float2*)(xd + 2) = make_float2(px[q].z, px[q].w);
        }
        __syncthreads();   // x ready

        // phi
        float2 xw[4][2], ss2[4];
#pragma unroll
        for (int k = 0; k < 4; ++k) {
            ss2[k] = make_float2(0.f, 0.f);
            xw[k][0] = make_float2(0.f, 0.f);
            xw[k][1] = make_float2(0.f, 0.f);
        }
#pragma unroll 4
        for (int f = 0; f < FF; f += 2) {
            float2 xv[4];
#pragma unroll
            for (int k = 0; k < 4; ++k)
                xv[k] = *(const float2*)&xpart[(prg + 16 * k) * QXP + f];
            const float2* om0 = (const float2*)&omega_s[f * MMF];
            const float2* om1 = (const float2*)&omega_s[(f + 1) * MMF];
            float2 o0[2], o1[2];
#pragma unroll
            for (int i = 0; i < 2; ++i) { o0[i] = om0[pmg + 32 * i]; o1[i] = om1[pmg + 32 * i]; }
#pragma unroll
            for (int k = 0; k < 4; ++k) {
                ss2[k] = ffma2(xv[k], xv[k], ss2[k]);
                float2 a0 = make_float2(xv[k].x, xv[k].x);
                float2 a1 = make_float2(xv[k].y, xv[k].y);
#pragma unroll
                for (int i = 0; i < 2; ++i) {
                    xw[k][i] = ffma2(a0, o0[i], xw[k][i]);
                    xw[k][i] = ffma2(a1, o1[i], xw[k][i]);
                }
            }
        }
#pragma unroll
        for (int k = 0; k < 4; ++k) {
            int r = prg + 16 * k;
            float sc = 0.5f * (ss2[k].x + ss2[k].y);
#pragma unroll
            for (int i = 0; i < 2; ++i) {
                int m = 2 * (pmg + 32 * i);
                float w0 = xw[k][i].x, w1 = xw[k][i].y;
                qphiT[m * QPP + r]             = (__expf(w0 - sc) + EPSF) * SCALEF;
                qphiT[(m + 1) * QPP + r]       = (__expf(w1 - sc) + EPSF) * SCALEF;
                qphiT[(m + MMF) * QPP + r]     = (__expf(-w0 - sc) + EPSF) * SCALEF;
                qphiT[(m + MMF + 1) * QPP + r] = (__expf(-w1 - sc) + EPSF) * SCALEF;
            }
        }
        __syncthreads();   // qphiT ready; xpart now reusable as partial buf

        if (t + 1 < te) {
            int tn = t + 1, bn = tn >> 7, rn = (tn & 127) * 64;
            const float4* qp = (const float4*)(query + ((size_t)bn * TT + rn) * FF);
#pragma unroll
            for (int q = 0; q < 2; ++q) px[q] = qp[tid + q * 512];
        }

        // GEMM (2-way m-split): 4 rows x 4 cols per thread
        float2 a[4][2];
#pragma unroll
        for (int j = 0; j < 4; ++j) { a[j][0] = make_float2(0.f, 0.f); a[j][1] = make_float2(0.f, 0.f); }
        float2 an2[2] = {make_float2(0.f, 0.f), make_float2(0.f, 0.f)};
        const int m0 = ms * 128;
#pragma unroll 4
        for (int mm = 0; mm < 128; ++mm) {
            int m = m0 + mm;
            float2 q01 = *(const float2*)&qphiT[m * QPP + 4 * rgrp];
            float2 q23 = *(const float2*)&qphiT[m * QPP + 4 * rgrp + 2];
            float2 kv0 = *(const float2*)&kv_s[m * KVW + 4 * cgrp];
            float2 kv1 = *(const float2*)&kv_s[m * KVW + 4 * cgrp + 2];
            float kn = kv_s[m * KVW + 64];
            float2 kn2 = make_float2(kn, kn);
            float2 qb;
            qb = make_float2(q01.x, q01.x);
            a[0][0] = ffma2(qb, kv0, a[0][0]); a[0][1] = ffma2(qb, kv1, a[0][1]);
            qb = make_float2(q01.y, q01.y);
            a[1][0] = ffma2(qb, kv0, a[1][0]); a[1][1] = ffma2(qb, kv1, a[1][1]);
            qb = make_float2(q23.x, q23.x);
            a[2][0] = ffma2(qb, kv0, a[2][0]); a[2][1] = ffma2(qb, kv1, a[2][1]);
            qb = make_float2(q23.y, q23.y);
            a[3][0] = ffma2(qb, kv0, a[3][0]); a[3][1] = ffma2(qb, kv1, a[3][1]);
            an2[0] = ffma2(q01, kn2, an2[0]);
            an2[1] = ffma2(q23, kn2, an2[1]);
        }

        if (ms == 1) {
#pragma unroll
            for (int row = 0; row < 4; ++row) {
                int r = 4 * rgrp + row;
                *(float2*)&xpart[r * QXP + 4 * cgrp]     = a[row][0];
                *(float2*)&xpart[r * QXP + 4 * cgrp + 2] = a[row][1];
            }
            if (cgrp == 0) {
                npart[4 * rgrp]     = an2[0].x;
                npart[4 * rgrp + 1] = an2[0].y;
                npart[4 * rgrp + 2] = an2[1].x;
                npart[4 * rgrp + 3] = an2[1].y;
            }
        }
        __syncthreads();   // partials ready
        if (ms == 0) {
            float an[4] = {an2[0].x, an2[0].y, an2[1].x, an2[1].y};
#pragma unroll
            for (int row = 0; row < 4; ++row) {
                int r = 4 * rgrp + row;
                float2 p0 = *(const float2*)&xpart[r * QXP + 4 * cgrp];
                float2 p1 = *(const float2*)&xpart[r * QXP + 4 * cgrp + 2];
                float inv = 1.0f / (an[row] + npart[r]);
                float4 o;
                o.x = (a[row][0].x + p0.x) * inv;
                o.y = (a[row][0].y + p0.y) * inv;
                o.z = (a[row][1].x + p1.x) * inv;
                o.w = (a[row][1].y + p1.y) * inv;
                *(float4*)(out + ((size_t)b * TT + r0 + r) * DD + 4 * cgrp) = o;
            }
        }
    }
}

// ---------------------------------------------------------------------------

#define KV_SMEM  ((8192 + 32*KXP + 32*KVP + 32*KPP) * 4)
#define QKV_SMEM ((8192 + TWOM*KVW + 64*QXP + TWOM*QPP + 64) * 4)

extern "C" void kernel_launch(void* const* d_in, const int* in_sizes, int n_in,
                              void* d_out, int out_size) {
    const float* query = (const float*)d_in[0];
    const float* value = (const float*)d_in[1];
    const float* key   = (const float*)d_in[2];
    const float* omega = (const float*)d_in[3];
    float* out = (float*)d_out;

    cudaFuncSetAttribute(kv_kernel, cudaFuncAttributeMaxDynamicSharedMemorySize, KV_SMEM);
    cudaFuncSetAttribute(qkv_kernel, cudaFuncAttributeMaxDynamicSharedMemorySize, QKV_SMEM);

    kv_kernel<<<NBLK, 256, KV_SMEM>>>(key, value, omega);
    reduce_kernel<<<dim3((TWOM * KVW / 4 + 255) / 256, BB), 256>>>();
    qkv_kernel<<<QNB, 512, QKV_SMEM>>>(query, omega, out);
}

// round 7
// speedup vs baseline: 1.2968x; 1.2158x over previous
#include <cuda_runtime.h>
#include <cuda_bf16.h>
#include <string.h>
#include <stdint.h>

#define BB 8
#define TT 8192
#define SN 8192
#define FF 64
#define DD 64
#define MMF 128
#define TWOM 256
#define EPSF 1e-9f
#define SCALEF 0.0625f   /* 1/sqrt(2*128) */
#define KVW 66           /* kv row stride: col 64 = normalizer, 65 pad */

/* kv (fp32) config — round-4 proven */
#define NBLK 148
#define NTILES 1024      /* 64-row tiles, 128 per batch */
#define XP 66
#define VP 68
#define KPP 258

/* qkv config */
#define QTIL 512         /* 128-row t-tiles, 64 per batch */
#define QNB 148
#define QXP 66
#define AW 132           /* A row stride in uint32 words (264 bf16) */
#define BW 72            /* B row stride in uint32 words */

__device__ float g_part[(size_t)NBLK * 2 * TWOM * KVW];
__device__ float g_kv[BB * TWOM * KVW];

static __device__ __forceinline__ float2 ffma2(float2 a, float2 b, float2 c) {
    unsigned long long au, bu, cu, du;
    memcpy(&au, &a, 8); memcpy(&bu, &b, 8); memcpy(&cu, &c, 8);
    asm("fma.rn.f32x2 %0, %1, %2, %3;" : "=l"(du) : "l"(au), "l"(bu), "l"(cu));
    float2 d; memcpy(&d, &du, 8);
    return d;
}
static __device__ __forceinline__ uint32_t smem_u32(const void* p) {
    uint32_t a;
    asm("{ .reg .u64 t; cvta.to.shared.u64 t, %1; cvt.u32.u64 %0, t; }" : "=r"(a) : "l"(p));
    return a;
}
static __device__ __forceinline__ void ldsm_x4(uint32_t& r0, uint32_t& r1,
                                               uint32_t& r2, uint32_t& r3, uint32_t addr) {
    asm volatile("ldmatrix.sync.aligned.m8n8.x4.shared.b16 {%0,%1,%2,%3}, [%4];"
                 : "=r"(r0), "=r"(r1), "=r"(r2), "=r"(r3) : "r"(addr));
}
static __device__ __forceinline__ void mma_bf16(float* c,
                                                uint32_t a0, uint32_t a1, uint32_t a2, uint32_t a3,
                                                uint32_t b0, uint32_t b1) {
    asm volatile("mma.sync.aligned.m16n8k16.row.col.f32.bf16.bf16.f32 "
                 "{%0,%1,%2,%3}, {%4,%5,%6,%7}, {%8,%9}, {%0,%1,%2,%3};"
                 : "+f"(c[0]), "+f"(c[1]), "+f"(c[2]), "+f"(c[3])
                 : "r"(a0), "r"(a1), "r"(a2), "r"(a3), "r"(b0), "r"(b1));
}
static __device__ __forceinline__ uint32_t pack_hi(float e0, float e1) {
    __nv_bfloat162 hp;
    hp.x = __float2bfloat16_rn(e0); hp.y = __float2bfloat16_rn(e1);
    uint32_t u; memcpy(&u, &hp, 4); return u;
}
static __device__ __forceinline__ uint32_t pack_lo(float e0, float e1, uint32_t hi) {
    __nv_bfloat162 hp; memcpy(&hp, &hi, 4);
    __nv_bfloat162 lp;
    lp.x = __float2bfloat16_rn(e0 - __bfloat162float(hp.x));
    lp.y = __float2bfloat16_rn(e1 - __bfloat162float(hp.y));
    uint32_t u; memcpy(&u, &lp, 4); return u;
}

/* qkv smem layout (bytes) */
#define OFF_OM 0                       /* omega fp32 [f][m]  32768 */
#define OFF_AH 32768                   /* 64 x AW uint32     33792 */
#define OFF_AL (OFF_AH + 33792)
#define OFF_BH (OFF_AL + 33792)       /* 128 x BW uint32    36864 */
#define OFF_BL (OFF_BH + 36864)
#define OFF_X  (OFF_BL + 36864)       /* 64 x QXP fp32      16896 */
#define OFF_KN (OFF_X + 16896)        /* 256 fp32            1024 */
#define OFF_NP (OFF_KN + 1024)        /* 32 x 65 fp32        8320 */
#define OFF_NS (OFF_NP + 8320)        /* 64 fp32              256 */
#define QSMEM  (OFF_NS + 256)

// ---------------------------------------------------------------------------
// Kernel 1 (round-4 proven fp32)
// ---------------------------------------------------------------------------
__global__ __launch_bounds__(512, 1)
void kv_kernel(const float* __restrict__ key,
               const float* __restrict__ value,
               const float* __restrict__ omega) {
    extern __shared__ float sm[];
    float* omega_s = sm;
    float* x_s     = sm + 8192;
    float* v_s     = x_s + 64 * XP;
    float* kphi    = v_s + 64 * VP;

    const int tid = threadIdx.x;
    const int blk = blockIdx.x;
    const int tb = (blk * NTILES) / NBLK;
    const int te = ((blk + 1) * NTILES) / NBLK;

    for (int idx = tid; idx < MMF * FF; idx += 512) {
        int m = idx >> 6, f = idx & 63;
        omega_s[f * MMF + m] = omega[idx];
    }

    const int rg = tid & 15;
    const int mg = (tid >> 4) & 31;
    const int fg = tid & 63;
    const int dgrp = tid >> 6;
    const int ldr = tid >> 4;
    const int ldc = (tid & 15) * 4;

    float2 acc[4][4];
#pragma unroll
    for (int j = 0; j < 4; ++j)
#pragma unroll
        for (int p = 0; p < 4; ++p) acc[j][p] = make_float2(0.f, 0.f);
    float accn[4] = {0.f, 0.f, 0.f, 0.f};
    int seg = 0;

    float4 px[2], pv[2];
    {
        int t = tb, b = t >> 7, s0 = (t & 127) * 64;
        const float4* kp = (const float4*)(key   + ((size_t)b * SN + s0) * FF);
        const float4* vp = (const float4*)(value + ((size_t)b * SN + s0) * FF);
#pragma unroll
        for (int q = 0; q < 2; ++q) { px[q] = kp[tid + q * 512]; pv[q] = vp[tid + q * 512]; }
    }

    for (int t = tb; t < te; ++t) {
        __syncthreads();
#pragma unroll
        for (int q = 0; q < 2; ++q) {
            int r = ldr + q * 32;
            float* xd = &x_s[r * XP + ldc];
            *(float2*)xd       = make_float2(px[q].x, px[q].y);
            *(float2*)(xd + 2) = make_float2(px[q].z, px[q].w);
            *(float4*)&v_s[r * VP + ldc] = pv[q];
        }
        if (t + 1 < te) {
            int tn = t + 1, b = tn >> 7, s0 = (tn & 127) * 64;
            const float4* kp = (const float4*)(key   + ((size_t)b * SN + s0) * FF);
            const float4* vp = (const float4*)(value + ((size_t)b * SN + s0) * FF);
#pragma unroll
            for (int q = 0; q < 2; ++q) { px[q] = kp[tid + q * 512]; pv[q] = vp[tid + q * 512]; }
        }
        __syncthreads();

        float2 xw[4][2], ss2[4];
#pragma unroll
        for (int k = 0; k < 4; ++k) {
            ss2[k] = make_float2(0.f, 0.f);
            xw[k][0] = make_float2(0.f, 0.f);
            xw[k][1] = make_float2(0.f, 0.f);
        }
#pragma unroll 4
        for (int f = 0; f < FF; f += 2) {
            float2 xv[4];
#pragma unroll
            for (int k = 0; k < 4; ++k)
                xv[k] = *(const float2*)&x_s[(rg + 16 * k) * XP + f];
            const float2* om0 = (const float2*)&omega_s[f * MMF];
            const float2* om1 = (const float2*)&omega_s[(f + 1) * MMF];
            float2 o0[2], o1[2];
#pragma unroll
            for (int i = 0; i < 2; ++i) { o0[i] = om0[mg + 32 * i]; o1[i] = om1[mg + 32 * i]; }
#pragma unroll
            for (int k = 0; k < 4; ++k) {
                ss2[k] = ffma2(xv[k], xv[k], ss2[k]);
                float2 a0 = make_float2(xv[k].x, xv[k].x);
                float2 a1 = make_float2(xv[k].y, xv[k].y);
#pragma unroll
                for (int i = 0; i < 2; ++i) {
                    xw[k][i] = ffma2(a0, o0[i], xw[k][i]);
                    xw[k][i] = ffma2(a1, o1[i], xw[k][i]);
                }
            }
        }
#pragma unroll
        for (int k = 0; k < 4; ++k) {
            int r = rg + 16 * k;
            float sc = 0.5f * (ss2[k].x + ss2[k].y);
            float* kr = &kphi[r * KPP];
#pragma unroll
            for (int i = 0; i < 2; ++i) {
                int m = 2 * (mg + 32 * i);
                float w0 = xw[k][i].x, w1 = xw[k][i].y;
                *(float2*)&kr[m] = make_float2(
                    (__expf(w0 - sc) + EPSF) * SCALEF,
                    (__expf(w1 - sc) + EPSF) * SCALEF);
                *(float2*)&kr[m + MMF] = make_float2(
                    (__expf(-w0 - sc) + EPSF) * SCALEF,
                    (__expf(-w1 - sc) + EPSF) * SCALEF);
            }
        }
        __syncthreads();

#pragma unroll 2
        for (int r = 0; r < 64; ++r) {
            const float* kr = &kphi[r * KPP + 2 * fg];
            float2 k01 = *(const float2*)kr;
            float2 k23 = *(const float2*)(kr + MMF);
            const float2* vr = (const float2*)&v_s[r * VP + 8 * dgrp];
            float2 vv[4];
#pragma unroll
            for (int p = 0; p < 4; ++p) vv[p] = vr[p];
            float kk[4] = {k01.x, k01.y, k23.x, k23.y};
#pragma unroll
            for (int j = 0; j < 4; ++j) {
                float2 kj = make_float2(kk[j], kk[j]);
#pragma unroll
                for (int p = 0; p < 4; ++p) acc[j][p] = ffma2(kj, vv[p], acc[j][p]);
            }
            if (dgrp == 0) {
#pragma unroll
                for (int j = 0; j < 4; ++j) accn[j] += kk[j];
            }
        }

        if (t + 1 == te || ((t + 1) >> 7) != (t >> 7)) {
            float* base = &g_part[(size_t)(blk * 2 + seg) * TWOM * KVW];
#pragma unroll
            for (int j = 0; j < 4; ++j) {
                int feat = 2 * fg + (j & 1) + (j >> 1) * MMF;
                float* dst = base + feat * KVW;
#pragma unroll
                for (int p = 0; p < 4; ++p)
                    *(float2*)&dst[8 * dgrp + 2 * p] = acc[j][p];
                if (dgrp == 0) dst[64] = accn[j];
            }
            ++seg;
#pragma unroll
            for (int j = 0; j < 4; ++j) {
#pragma unroll
                for (int p = 0; p < 4; ++p) acc[j][p] = make_float2(0.f, 0.f);
                accn[j] = 0.f;
            }
        }
    }
}

// ---------------------------------------------------------------------------
// Kernel 2: deterministic reduction
// ---------------------------------------------------------------------------
__global__ void reduce_kernel() {
    const int per_b4 = TWOM * KVW / 4;
    int idx = blockIdx.x * blockDim.x + threadIdx.x;
    int b = blockIdx.y;
    if (idx >= per_b4) return;
    float4 s = make_float4(0.f, 0.f, 0.f, 0.f);
    for (int i = 0; i < NBLK; ++i) {
        int tb = (i * NTILES) / NBLK;
        int te = ((i + 1) * NTILES) / NBLK;
        int b0 = tb >> 7;
        int bl = (te - 1) >> 7;
        int slot = (b0 == b) ? 0 : ((bl == b && bl != b0) ? 1 : -1);
        if (slot >= 0) {
            float4 v = ((const float4*)g_part)[(size_t)(i * 2 + slot) * per_b4 + idx];
            s.x += v.x; s.y += v.y; s.z += v.z; s.w += v.w;
        }
    }
    ((float4*)g_kv)[(size_t)b * per_b4 + idx] = s;
}

// ---------------------------------------------------------------------------
// Kernel 3: mma.sync bf16 hi/lo qkv. 148 persistent blocks x 512 threads over
// 512 128-row tiles (2 subtiles of 64). phi fp32 -> A hi/lo smem -> HMMA.
// ---------------------------------------------------------------------------
__global__ __launch_bounds__(512, 1)
void qkv_kernel(const float* __restrict__ query,
                const float* __restrict__ omega,
                float* __restrict__ out) {
    extern __shared__ char smc[];
    const uint32_t sb = smem_u32(smc);
    float* omega_s = (float*)(smc + OFF_OM);
    float* x_s     = (float*)(smc + OFF_X);
    float* kn_s    = (float*)(smc + OFF_KN);
    float* np_s    = (float*)(smc + OFF_NP);
    float* ns_s    = (float*)(smc + OFF_NS);
    uint32_t* Ah   = (uint32_t*)(smc + OFF_AH);
    uint32_t* Al   = (uint32_t*)(smc + OFF_AL);
    const uint32_t* Bh = (const uint32_t*)(smc + OFF_BH);
    const uint32_t* Bl = (const uint32_t*)(smc + OFF_BL);
    uint32_t* Bhw  = (uint32_t*)(smc + OFF_BH);
    uint32_t* Blw  = (uint32_t*)(smc + OFF_BL);

    const int tid = threadIdx.x;
    const int blk = blockIdx.x;
    const int tb = (blk * QTIL) / QNB;
    const int te = ((blk + 1) * QTIL) / QNB;

    {
        const float4* om4 = (const float4*)omega;
#pragma unroll
        for (int q = 0; q < 4; ++q) {
            int idx = tid + q * 512;
            float4 v = om4[idx];
            int m = idx >> 4, f = (idx & 15) * 4;
            omega_s[f * MMF + m]       = v.x;
            omega_s[(f + 1) * MMF + m] = v.y;
            omega_s[(f + 2) * MMF + m] = v.z;
            omega_s[(f + 3) * MMF + m] = v.w;
        }
    }

    /* phi mapping (64-row subtile) */
    const int rg = tid & 15;       /* rows rg+16k, k<4 */
    const int mg = tid >> 4;       /* m-word pairs mg+32i, i<2 */
    /* mma mapping */
    const int w = tid >> 5, lane = tid & 31;
    const int nt = w & 7, rh = w >> 3;
    const int gid = lane >> 2, tg = lane & 3;
    const int quad = lane >> 3, lrow = lane & 7;
    const int arow = lrow + (quad & 1) * 8;
    const int acolb = (quad >> 1) * 16;

    int cur_b = -1;
    float4 px[4];
    {
        int t = tb, b = t >> 6, r0 = (t & 63) * 128;
        const float4* qp = (const float4*)(query + ((size_t)b * TT + r0) * FF);
#pragma unroll
        for (int q = 0; q < 4; ++q) px[q] = qp[tid + q * 512];
    }

    for (int t = tb; t < te; ++t) {
        const int b = t >> 6;
        const int r0 = (t & 63) * 128;

        if (b != cur_b) {
            __syncthreads();   /* prev tile mma done with B */
            const float* kvp = &g_kv[(size_t)b * TWOM * KVW];
            for (int i = tid; i < 128 * 64; i += 512) {
                int p = i >> 6, n = i & 63;
                float v0 = kvp[(2 * p) * KVW + n];
                float v1 = kvp[(2 * p + 1) * KVW + n];
                uint32_t hw = pack_hi(v0, v1);
                Bhw[p * BW + n] = hw;
                Blw[p * BW + n] = pack_lo(v0, v1, hw);
            }
            if (tid < 256) kn_s[tid] = kvp[tid * KVW + 64];
            cur_b = b;
        }

        for (int sub = 0; sub < 2; ++sub) {
            __syncthreads();   /* A, x free; B/kn ready */
#pragma unroll
            for (int q = 0; q < 2; ++q) {
                float4 xv = px[2 * sub + q];
                int idx = tid + q * 512;
                int r = idx >> 4, c = (idx & 15) * 4;
                float* xd = &x_s[r * QXP + c];
                *(float2*)xd       = make_float2(xv.x, xv.y);
                *(float2*)(xd + 2) = make_float2(xv.z, xv.w);
            }
            if (sub == 1 && t + 1 < te) {
                int tn = t + 1, bn = tn >> 6, rn = (tn & 63) * 128;
                const float4* qp = (const float4*)(query + ((size_t)bn * TT + rn) * FF);
#pragma unroll
                for (int q = 0; q < 4; ++q) px[q] = qp[tid + q * 512];
            }
            __syncthreads();   /* x ready */

            /* phi fp32: 4 rows x 2 word-pairs */
            float2 xw[4][2], ss2[4];
#pragma unroll
            for (int k = 0; k < 4; ++k) {
                ss2[k] = make_float2(0.f, 0.f);
                xw[k][0] = make_float2(0.f, 0.f);
                xw[k][1] = make_float2(0.f, 0.f);
            }
#pragma unroll 4
            for (int f = 0; f < FF; f += 2) {
                float2 xv[4];
#pragma unroll
                for (int k = 0; k < 4; ++k)
                    xv[k] = *(const float2*)&x_s[(rg + 16 * k) * QXP + f];
                const float2* om0 = (const float2*)&omega_s[f * MMF];
                const float2* om1 = (const float2*)&omega_s[(f + 1) * MMF];
                float2 o0[2], o1[2];
#pragma unroll
                for (int i = 0; i < 2; ++i) { o0[i] = om0[mg + 32 * i]; o1[i] = om1[mg + 32 * i]; }
#pragma unroll
                for (int k = 0; k < 4; ++k) {
                    ss2[k] = ffma2(xv[k], xv[k], ss2[k]);
                    float2 a0 = make_float2(xv[k].x, xv[k].x);
                    float2 a1 = make_float2(xv[k].y, xv[k].y);
#pragma unroll
                    for (int i = 0; i < 2; ++i) {
                        xw[k][i] = ffma2(a0, o0[i], xw[k][i]);
                        xw[k][i] = ffma2(a1, o1[i], xw[k][i]);
                    }
                }
            }
            /* kn values for this thread's features (same for all k) */
            float knv[2][4];
#pragma unroll
            for (int i = 0; i < 2; ++i) {
                int m = 2 * (mg + 32 * i);
                knv[i][0] = kn_s[m];       knv[i][1] = kn_s[m + 1];
                knv[i][2] = kn_s[m + 128]; knv[i][3] = kn_s[m + 129];
            }
#pragma unroll
            for (int k = 0; k < 4; ++k) {
                int r = rg + 16 * k;
                float sc = 0.5f * (ss2[k].x + ss2[k].y);
                float npart = 0.f;
#pragma unroll
                for (int i = 0; i < 2; ++i) {
                    int mw = mg + 32 * i;
                    float w0 = xw[k][i].x, w1 = xw[k][i].y;
                    float e0 = (__expf(w0 - sc) + EPSF) * SCALEF;
                    float e1 = (__expf(w1 - sc) + EPSF) * SCALEF;
                    float n0 = (__expf(-w0 - sc) + EPSF) * SCALEF;
                    float n1 = (__expf(-w1 - sc) + EPSF) * SCALEF;
                    uint32_t hp = pack_hi(e0, e1);
                    Ah[r * AW + mw] = hp;
                    Al[r * AW + mw] = pack_lo(e0, e1, hp);
                    uint32_t hn = pack_hi(n0, n1);
                    Ah[r * AW + mw + 64] = hn;
                    Al[r * AW + mw + 64] = pack_lo(n0, n1, hn);
                    npart += e0 * knv[i][0] + e1 * knv[i][1]
                           + n0 * knv[i][2] + n1 * knv[i][3];
                }
                np_s[mg * 65 + r] = npart;
            }
            __syncthreads();   /* A + npart ready */
            if (tid < 64) {
                float s = 0.f;
#pragma unroll 8
                for (int j = 0; j < 32; ++j) s += np_s[j * 65 + tid];
                ns_s[tid] = s;
            }
            __syncthreads();   /* norm ready */

            /* HMMA: warp = (nt, rh); 2 row-tiles x 8 cols, K=256 */
            float acc[2][4];
#pragma unroll
            for (int rt = 0; rt < 2; ++rt)
#pragma unroll
                for (int p = 0; p < 4; ++p) acc[rt][p] = 0.f;

#pragma unroll 2
            for (int kt = 0; kt < 16; ++kt) {
                uint32_t bh0 = Bh[(kt * 8 + tg) * BW + nt * 8 + gid];
                uint32_t bh1 = Bh[(kt * 8 + tg + 4) * BW + nt * 8 + gid];
                uint32_t bl0 = Bl[(kt * 8 + tg) * BW + nt * 8 + gid];
                uint32_t bl1 = Bl[(kt * 8 + tg + 4) * BW + nt * 8 + gid];
#pragma unroll
                for (int rt = 0; rt < 2; ++rt) {
                    int rbase = rh * 32 + rt * 16;
                    uint32_t aaddr = sb + OFF_AH + (uint32_t)((rbase + arow) * 528 + kt * 32 + acolb);
                    uint32_t laddr = aaddr + (OFF_AL - OFF_AH);
                    uint32_t a0, a1, a2, a3, l0, l1, l2, l3;
                    ldsm_x4(a0, a1, a2, a3, aaddr);
                    ldsm_x4(l0, l1, l2, l3, laddr);
                    mma_bf16(acc[rt], a0, a1, a2, a3, bh0, bh1);
                    mma_bf16(acc[rt], l0, l1, l2, l3, bh0, bh1);
                    mma_bf16(acc[rt], a0, a1, a2, a3, bl0, bl1);
                }
            }

            /* epilogue: normalize + store */
#pragma unroll
            for (int rt = 0; rt < 2; ++rt) {
                int rs = rh * 32 + rt * 16;
                int row0 = rs + gid, row1 = rs + gid + 8;
                float inv0 = 1.0f / ns_s[row0];
                float inv1 = 1.0f / ns_s[row1];
                float* o0 = out + ((size_t)b * TT + r0 + sub * 64 + row0) * DD + nt * 8 + 2 * tg;
                float* o1 = out + ((size_t)b * TT + r0 + sub * 64 + row1) * DD + nt * 8 + 2 * tg;
                *(float2*)o0 = make_float2(acc[rt][0] * inv0, acc[rt][1] * inv0);
                *(float2*)o1 = make_float2(acc[rt][2] * inv1, acc[rt][3] * inv1);
            }
        }
    }
}

// ---------------------------------------------------------------------------

#define KV_SMEM  ((8192 + 64*XP + 64*VP + 64*KPP) * 4)

extern "C" void kernel_launch(void* const* d_in, const int* in_sizes, int n_in,
                              void* d_out, int out_size) {
    const float* query = (const float*)d_in[0];
    const float* value = (const float*)d_in[1];
    const float* key   = (const float*)d_in[2];
    const float* omega = (const float*)d_in[3];
    float* out = (float*)d_out;

    cudaFuncSetAttribute(kv_kernel, cudaFuncAttributeMaxDynamicSharedMemorySize, KV_SMEM);
    cudaFuncSetAttribute(qkv_kernel, cudaFuncAttributeMaxDynamicSharedMemorySize, QSMEM);

    kv_kernel<<<NBLK, 512, KV_SMEM>>>(key, value, omega);
    reduce_kernel<<<dim3((TWOM * KVW / 4 + 255) / 256, BB), 256>>>();
    qkv_kernel<<<QNB, 512, QSMEM>>>(query, omega, out);
}

// round 8
// speedup vs baseline: 1.5058x; 1.1611x over previous
#include <cuda_runtime.h>
#include <cuda_bf16.h>
#include <string.h>
#include <stdint.h>

#define BB 8
#define TT 8192
#define SN 8192
#define FF 64
#define DD 64
#define MMF 128
#define TWOM 256
#define EPSF 1e-9f
#define SCALEF 0.0625f   /* 1/sqrt(2*128) */
#define KVW 66           /* kv row stride: col 64 = normalizer, 65 pad */

/* kv config */
#define NBLK 148
#define NTILES 1024      /* 64-row tiles, 128 per batch */
#define XP 66
#define VP 68

/* qkv config (round-7 proven) */
#define QTIL 512
#define QNB 148
#define QXP 66
#define AW 132
#define BW 72

__device__ float g_part[(size_t)NBLK * 2 * TWOM * KVW];
__device__ float g_kv[BB * TWOM * KVW];

static __device__ __forceinline__ float2 ffma2(float2 a, float2 b, float2 c) {
    unsigned long long au, bu, cu, du;
    memcpy(&au, &a, 8); memcpy(&bu, &b, 8); memcpy(&cu, &c, 8);
    asm("fma.rn.f32x2 %0, %1, %2, %3;" : "=l"(du) : "l"(au), "l"(bu), "l"(cu));
    float2 d; memcpy(&d, &du, 8);
    return d;
}
static __device__ __forceinline__ uint32_t smem_u32(const void* p) {
    uint32_t a;
    asm("{ .reg .u64 t; cvta.to.shared.u64 t, %1; cvt.u32.u64 %0, t; }" : "=r"(a) : "l"(p));
    return a;
}
static __device__ __forceinline__ void ldsm_x4(uint32_t& r0, uint32_t& r1,
                                               uint32_t& r2, uint32_t& r3, uint32_t addr) {
    asm volatile("ldmatrix.sync.aligned.m8n8.x4.shared.b16 {%0,%1,%2,%3}, [%4];"
                 : "=r"(r0), "=r"(r1), "=r"(r2), "=r"(r3) : "r"(addr));
}
static __device__ __forceinline__ void mma_bf16(float* c,
                                                uint32_t a0, uint32_t a1, uint32_t a2, uint32_t a3,
                                                uint32_t b0, uint32_t b1) {
    asm volatile("mma.sync.aligned.m16n8k16.row.col.f32.bf16.bf16.f32 "
                 "{%0,%1,%2,%3}, {%4,%5,%6,%7}, {%8,%9}, {%0,%1,%2,%3};"
                 : "+f"(c[0]), "+f"(c[1]), "+f"(c[2]), "+f"(c[3])
                 : "r"(a0), "r"(a1), "r"(a2), "r"(a3), "r"(b0), "r"(b1));
}
static __device__ __forceinline__ uint32_t pack_hi(float e0, float e1) {
    __nv_bfloat162 hp;
    hp.x = __float2bfloat16_rn(e0); hp.y = __float2bfloat16_rn(e1);
    uint32_t u; memcpy(&u, &hp, 4); return u;
}
static __device__ __forceinline__ uint32_t pack_lo(float e0, float e1, uint32_t hi) {
    __nv_bfloat162 hp; memcpy(&hp, &hi, 4);
    __nv_bfloat162 lp;
    lp.x = __float2bfloat16_rn(e0 - __bfloat162float(hp.x));
    lp.y = __float2bfloat16_rn(e1 - __bfloat162float(hp.y));
    uint32_t u; memcpy(&u, &lp, 4); return u;
}
static __device__ __forceinline__ uint16_t bf16_bits(float v) {
    __nv_bfloat16 h = __float2bfloat16_rn(v);
    uint16_t u; memcpy(&u, &h, 2); return u;
}

/* ---------------- kv smem layout (bytes) ---------------- */
#define KOFF_OM 0                          /* omega fp32      32768 */
#define KOFF_X  32768                      /* 64 x XP fp32    16896 */
#define KOFF_V  (KOFF_X + 16896)           /* 64 x VP fp32    17408 */
#define KOFF_AH (KOFF_V + 17408)           /* 256 x 144B bf16 36864 */
#define KOFF_AL (KOFF_AH + 36864)
#define KOFF_BH (KOFF_AL + 36864)          /* 32 x 72 u32      9216 */
#define KOFF_BL (KOFF_BH + 9216)
#define KV_SMEM (KOFF_BL + 9216)

/* ---------------- qkv smem layout (round-7) ---------------- */
#define OFF_OM 0
#define OFF_AH 32768
#define OFF_AL (OFF_AH + 33792)
#define OFF_BH (OFF_AL + 33792)
#define OFF_BL (OFF_BH + 36864)
#define OFF_X  (OFF_BL + 36864)
#define OFF_KN (OFF_X + 16896)
#define OFF_NP (OFF_KN + 1024)
#define OFF_NS (OFF_NP + 8320)
#define QSMEM  (OFF_NS + 256)

// ---------------------------------------------------------------------------
// Kernel 1: kv via HMMA. 148 balanced blocks x 512 threads over 1024 64-row
// tiles. phi fp32 -> A bf16 hi/lo (transposed, [feature][row]); v -> B packed
// hi/lo + ones column; D[256][72] persistent in registers; flush per segment.
// ---------------------------------------------------------------------------
__global__ __launch_bounds__(512, 1)
void kv_kernel(const float* __restrict__ key,
               const float* __restrict__ value,
               const float* __restrict__ omega) {
    extern __shared__ char smc[];
    const uint32_t sb = smem_u32(smc);
    float* omega_s = (float*)(smc + KOFF_OM);
    float* x_s     = (float*)(smc + KOFF_X);
    float* v_s     = (float*)(smc + KOFF_V);
    uint32_t* Bh   = (uint32_t*)(smc + KOFF_BH);
    uint32_t* Bl   = (uint32_t*)(smc + KOFF_BL);

    const int tid = threadIdx.x;
    const int blk = blockIdx.x;
    const int tb = (blk * NTILES) / NBLK;
    const int te = ((blk + 1) * NTILES) / NBLK;

    /* omega transpose load */
    {
        const float4* om4 = (const float4*)omega;
#pragma unroll
        for (int q = 0; q < 4; ++q) {
            int idx = tid + q * 512;
            float4 v = om4[idx];
            int m = idx >> 4, f = (idx & 15) * 4;
            omega_s[f * MMF + m]       = v.x;
            omega_s[(f + 1) * MMF + m] = v.y;
            omega_s[(f + 2) * MMF + m] = v.z;
            omega_s[(f + 3) * MMF + m] = v.w;
        }
    }
    /* constant B pad: cols 64-71 (col 64 = ones) */
    if (tid < 256) {
        int p = tid >> 3, n = 64 + (tid & 7);
        Bh[p * 72 + n] = (n == 64) ? 0x3F803F80u : 0u;
        Bl[p * 72 + n] = 0u;
    }

    /* phi mapping (proven): rows rg+16k, features 2(mg+32i) */
    const int rg = tid & 15;
    const int mg = tid >> 4;
    const int ldr = tid >> 4;
    const int ldc = (tid & 15) * 4;
    /* mma mapping: warp w owns features w*16..+15 */
    const int w = tid >> 5, lane = tid & 31;
    const int gid = lane >> 2, tg = lane & 3;
    const int quad = lane >> 3, lrow = lane & 7;
    const int arow = lrow + (quad & 1) * 8;
    const int acolb = (quad >> 1) * 16;
    const uint32_t aBase = sb + KOFF_AH + (uint32_t)((w * 16 + arow) * 144 + acolb);

    float acc[8][4];
#pragma unroll
    for (int nt = 0; nt < 8; ++nt)
#pragma unroll
        for (int p = 0; p < 4; ++p) acc[nt][p] = 0.f;
    float accN[4] = {0.f, 0.f, 0.f, 0.f};
    int seg = 0;

    float4 px[2], pv[2];
    {
        int t = tb, b = t >> 7, s0 = (t & 127) * 64;
        const float4* kp = (const float4*)(key   + ((size_t)b * SN + s0) * FF);
        const float4* vp = (const float4*)(value + ((size_t)b * SN + s0) * FF);
#pragma unroll
        for (int q = 0; q < 2; ++q) { px[q] = kp[tid + q * 512]; pv[q] = vp[tid + q * 512]; }
    }

    for (int t = tb; t < te; ++t) {
        __syncthreads();   /* prev MMA done with A/B; x/v free */
#pragma unroll
        for (int q = 0; q < 2; ++q) {
            int r = ldr + q * 32;
            float* xd = &x_s[r * XP + ldc];
            *(float2*)xd       = make_float2(px[q].x, px[q].y);
            *(float2*)(xd + 2) = make_float2(px[q].z, px[q].w);
            *(float4*)&v_s[r * VP + ldc] = pv[q];
        }
        if (t + 1 < te) {
            int tn = t + 1, b = tn >> 7, s0 = (tn & 127) * 64;
            const float4* kp = (const float4*)(key   + ((size_t)b * SN + s0) * FF);
            const float4* vp = (const float4*)(value + ((size_t)b * SN + s0) * FF);
#pragma unroll
            for (int q = 0; q < 2; ++q) { px[q] = kp[tid + q * 512]; pv[q] = vp[tid + q * 512]; }
        }
        __syncthreads();   /* x,v ready */

        /* pack B: word[p][n] = {v[2p][n], v[2p+1][n]} hi/lo */
#pragma unroll
        for (int q = 0; q < 4; ++q) {
            int idx = tid + q * 512;
            int p = idx >> 6, n = idx & 63;
            float v0 = v_s[(2 * p) * VP + n];
            float v1 = v_s[(2 * p + 1) * VP + n];
            uint32_t hw = pack_hi(v0, v1);
            Bh[p * 72 + n] = hw;
            Bl[p * 72 + n] = pack_lo(v0, v1, hw);
        }

        /* phi fp32: 4 rows x 2 m-pairs; store bf16 hi/lo transposed */
        float2 xw[4][2], ss2[4];
#pragma unroll
        for (int k = 0; k < 4; ++k) {
            ss2[k] = make_float2(0.f, 0.f);
            xw[k][0] = make_float2(0.f, 0.f);
            xw[k][1] = make_float2(0.f, 0.f);
        }
#pragma unroll 4
        for (int f = 0; f < FF; f += 2) {
            float2 xv[4];
#pragma unroll
            for (int k = 0; k < 4; ++k)
                xv[k] = *(const float2*)&x_s[(rg + 16 * k) * XP + f];
            const float2* om0 = (const float2*)&omega_s[f * MMF];
            const float2* om1 = (const float2*)&omega_s[(f + 1) * MMF];
            float2 o0[2], o1[2];
#pragma unroll
            for (int i = 0; i < 2; ++i) { o0[i] = om0[mg + 32 * i]; o1[i] = om1[mg + 32 * i]; }
#pragma unroll
            for (int k = 0; k < 4; ++k) {
                ss2[k] = ffma2(xv[k], xv[k], ss2[k]);
                float2 a0 = make_float2(xv[k].x, xv[k].x);
                float2 a1 = make_float2(xv[k].y, xv[k].y);
#pragma unroll
                for (int i = 0; i < 2; ++i) {
                    xw[k][i] = ffma2(a0, o0[i], xw[k][i]);
                    xw[k][i] = ffma2(a1, o1[i], xw[k][i]);
                }
            }
        }
#pragma unroll
        for (int k = 0; k < 4; ++k) {
            int r = rg + 16 * k;
            float sc = 0.5f * (ss2[k].x + ss2[k].y);
#pragma unroll
            for (int i = 0; i < 2; ++i) {
                int m = 2 * (mg + 32 * i);
                float w0 = xw[k][i].x, w1 = xw[k][i].y;
                float e0 = (__expf(w0 - sc) + EPSF) * SCALEF;
                float e1 = (__expf(w1 - sc) + EPSF) * SCALEF;
                float n0 = (__expf(-w0 - sc) + EPSF) * SCALEF;
                float n1 = (__expf(-w1 - sc) + EPSF) * SCALEF;
                float vals[4] = {e0, e1, n0, n1};
                int fs[4] = {m, m + 1, m + MMF, m + MMF + 1};
#pragma unroll
                for (int j = 0; j < 4; ++j) {
                    uint16_t hb = bf16_bits(vals[j]);
                    __nv_bfloat16 hh; memcpy(&hh, &hb, 2);
                    uint16_t lb = bf16_bits(vals[j] - __bfloat162float(hh));
                    *(uint16_t*)(smc + KOFF_AH + fs[j] * 144 + r * 2) = hb;
                    *(uint16_t*)(smc + KOFF_AL + fs[j] * 144 + r * 2) = lb;
                }
            }
        }
        __syncthreads();   /* A, B ready */

        /* HMMA: D[feature 16 per warp][72], K = 64 rows */
#pragma unroll
        for (int kt = 0; kt < 4; ++kt) {
            uint32_t ah0, ah1, ah2, ah3, al0, al1, al2, al3;
            ldsm_x4(ah0, ah1, ah2, ah3, aBase + kt * 32);
            ldsm_x4(al0, al1, al2, al3, aBase + (KOFF_AL - KOFF_AH) + kt * 32);
            const int p0 = kt * 8 + tg, p1 = kt * 8 + tg + 4;
#pragma unroll
            for (int nt = 0; nt < 8; ++nt) {
                uint32_t bh0 = Bh[p0 * 72 + nt * 8 + gid];
                uint32_t bh1 = Bh[p1 * 72 + nt * 8 + gid];
                uint32_t bl0 = Bl[p0 * 72 + nt * 8 + gid];
                uint32_t bl1 = Bl[p1 * 72 + nt * 8 + gid];
                mma_bf16(acc[nt], ah0, ah1, ah2, ah3, bh0, bh1);
                mma_bf16(acc[nt], al0, al1, al2, al3, bh0, bh1);
                mma_bf16(acc[nt], ah0, ah1, ah2, ah3, bl0, bl1);
            }
            /* normalizer tile (cols 64-71; Bl pad = 0) */
            {
                uint32_t bn0 = Bh[p0 * 72 + 64 + gid];
                uint32_t bn1 = Bh[p1 * 72 + 64 + gid];
                mma_bf16(accN, ah0, ah1, ah2, ah3, bn0, bn1);
                mma_bf16(accN, al0, al1, al2, al3, bn0, bn1);
            }
        }

        /* flush at batch boundary or end */
        if (t + 1 == te || ((t + 1) >> 7) != (t >> 7)) {
            float* base = &g_part[(size_t)(blk * 2 + seg) * TWOM * KVW];
            const int f0 = w * 16 + gid;
#pragma unroll
            for (int nt = 0; nt < 8; ++nt) {
                int c = nt * 8 + 2 * tg;
                *(float2*)&base[f0 * KVW + c]       = make_float2(acc[nt][0], acc[nt][1]);
                *(float2*)&base[(f0 + 8) * KVW + c] = make_float2(acc[nt][2], acc[nt][3]);
            }
            if (tg == 0) {
                base[f0 * KVW + 64]       = accN[0];
                base[(f0 + 8) * KVW + 64] = accN[2];
            }
            ++seg;
#pragma unroll
            for (int nt = 0; nt < 8; ++nt)
#pragma unroll
                for (int p = 0; p < 4; ++p) acc[nt][p] = 0.f;
#pragma unroll
            for (int p = 0; p < 4; ++p) accN[p] = 0.f;
        }
    }
}

// ---------------------------------------------------------------------------
// Kernel 2: deterministic reduction
// ---------------------------------------------------------------------------
__global__ void reduce_kernel() {
    const int per_b4 = TWOM * KVW / 4;
    int idx = blockIdx.x * blockDim.x + threadIdx.x;
    int b = blockIdx.y;
    if (idx >= per_b4) return;
    float4 s = make_float4(0.f, 0.f, 0.f, 0.f);
    for (int i = 0; i < NBLK; ++i) {
        int tb = (i * NTILES) / NBLK;
        int te = ((i + 1) * NTILES) / NBLK;
        int b0 = tb >> 7;
        int bl = (te - 1) >> 7;
        int slot = (b0 == b) ? 0 : ((bl == b && bl != b0) ? 1 : -1);
        if (slot >= 0) {
            float4 v = ((const float4*)g_part)[(size_t)(i * 2 + slot) * per_b4 + idx];
            s.x += v.x; s.y += v.y; s.z += v.z; s.w += v.w;
        }
    }
    ((float4*)g_kv)[(size_t)b * per_b4 + idx] = s;
}

// ---------------------------------------------------------------------------
// Kernel 3 (round-7 proven): mma.sync bf16 hi/lo qkv.
// ---------------------------------------------------------------------------
__global__ __launch_bounds__(512, 1)
void qkv_kernel(const float* __restrict__ query,
                const float* __restrict__ omega,
                float* __restrict__ out) {
    extern __shared__ char smc[];
    const uint32_t sb = smem_u32(smc);
    float* omega_s = (float*)(smc + OFF_OM);
    float* x_s     = (float*)(smc + OFF_X);
    float* kn_s    = (float*)(smc + OFF_KN);
    float* np_s    = (float*)(smc + OFF_NP);
    float* ns_s    = (float*)(smc + OFF_NS);
    uint32_t* Ah   = (uint32_t*)(smc + OFF_AH);
    uint32_t* Al   = (uint32_t*)(smc + OFF_AL);
    const uint32_t* Bh = (const uint32_t*)(smc + OFF_BH);
    const uint32_t* Bl = (const uint32_t*)(smc + OFF_BL);
    uint32_t* Bhw  = (uint32_t*)(smc + OFF_BH);
    uint32_t* Blw  = (uint32_t*)(smc + OFF_BL);

    const int tid = threadIdx.x;
    const int blk = blockIdx.x;
    const int tb = (blk * QTIL) / QNB;
    const int te = ((blk + 1) * QTIL) / QNB;

    {
        const float4* om4 = (const float4*)omega;
#pragma unroll
        for (int q = 0; q < 4; ++q) {
            int idx = tid + q * 512;
            float4 v = om4[idx];
            int m = idx >> 4, f = (idx & 15) * 4;
            omega_s[f * MMF + m]       = v.x;
            omega_s[(f + 1) * MMF + m] = v.y;
            omega_s[(f + 2) * MMF + m] = v.z;
            omega_s[(f + 3) * MMF + m] = v.w;
        }
    }

    const int rg = tid & 15;
    const int mg = tid >> 4;
    const int w = tid >> 5, lane = tid & 31;
    const int nt = w & 7, rh = w >> 3;
    const int gid = lane >> 2, tg = lane & 3;
    const int quad = lane >> 3, lrow = lane & 7;
    const int arow = lrow + (quad & 1) * 8;
    const int acolb = (quad >> 1) * 16;

    int cur_b = -1;
    float4 px[4];
    {
        int t = tb, b = t >> 6, r0 = (t & 63) * 128;
        const float4* qp = (const float4*)(query + ((size_t)b * TT + r0) * FF);
#pragma unroll
        for (int q = 0; q < 4; ++q) px[q] = qp[tid + q * 512];
    }

    for (int t = tb; t < te; ++t) {
        const int b = t >> 6;
        const int r0 = (t & 63) * 128;

        if (b != cur_b) {
            __syncthreads();
            const float* kvp = &g_kv[(size_t)b * TWOM * KVW];
            for (int i = tid; i < 128 * 64; i += 512) {
                int p = i >> 6, n = i & 63;
                float v0 = kvp[(2 * p) * KVW + n];
                float v1 = kvp[(2 * p + 1) * KVW + n];
                uint32_t hw = pack_hi(v0, v1);
                Bhw[p * BW + n] = hw;
                Blw[p * BW + n] = pack_lo(v0, v1, hw);
            }
            if (tid < 256) kn_s[tid] = kvp[tid * KVW + 64];
            cur_b = b;
        }

        for (int sub = 0; sub < 2; ++sub) {
            __syncthreads();
#pragma unroll
            for (int q = 0; q < 2; ++q) {
                float4 xv = px[2 * sub + q];
                int idx = tid + q * 512;
                int r = idx >> 4, c = (idx & 15) * 4;
                float* xd = &x_s[r * QXP + c];
                *(float2*)xd       = make_float2(xv.x, xv.y);
                *(float2*)(xd + 2) = make_float2(xv.z, xv.w);
            }
            if (sub == 1 && t + 1 < te) {
                int tn = t + 1, bn = tn >> 6, rn = (tn & 63) * 128;
                const float4* qp = (const float4*)(query + ((size_t)bn * TT + rn) * FF);
#pragma unroll
                for (int q = 0; q < 4; ++q) px[q] = qp[tid + q * 512];
            }
            __syncthreads();

            float2 xw[4][2], ss2[4];
#pragma unroll
            for (int k = 0; k < 4; ++k) {
                ss2[k] = make_float2(0.f, 0.f);
                xw[k][0] = make_float2(0.f, 0.f);
                xw[k][1] = make_float2(0.f, 0.f);
            }
#pragma unroll 4
            for (int f = 0; f < FF; f += 2) {
                float2 xv[4];
#pragma unroll
                for (int k = 0; k < 4; ++k)
                    xv[k] = *(const float2*)&x_s[(rg + 16 * k) * QXP + f];
                const float2* om0 = (const float2*)&omega_s[f * MMF];
                const float2* om1 = (const float2*)&omega_s[(f + 1) * MMF];
                float2 o0[2], o1[2];
#pragma unroll
                for (int i = 0; i < 2; ++i) { o0[i] = om0[mg + 32 * i]; o1[i] = om1[mg + 32 * i]; }
#pragma unroll
                for (int k = 0; k < 4; ++k) {
                    ss2[k] = ffma2(xv[k], xv[k], ss2[k]);
                    float2 a0 = make_float2(xv[k].x, xv[k].x);
                    float2 a1 = make_float2(xv[k].y, xv[k].y);
#pragma unroll
                    for (int i = 0; i < 2; ++i) {
                        xw[k][i] = ffma2(a0, o0[i], xw[k][i]);
                        xw[k][i] = ffma2(a1, o1[i], xw[k][i]);
                    }
                }
            }
            float knv[2][4];
#pragma unroll
            for (int i = 0; i < 2; ++i) {
                int m = 2 * (mg + 32 * i);
                knv[i][0] = kn_s[m];       knv[i][1] = kn_s[m + 1];
                knv[i][2] = kn_s[m + 128]; knv[i][3] = kn_s[m + 129];
            }
#pragma unroll
            for (int k = 0; k < 4; ++k) {
                int r = rg + 16 * k;
                float sc = 0.5f * (ss2[k].x + ss2[k].y);
                float npart = 0.f;
#pragma unroll
                for (int i = 0; i < 2; ++i) {
                    int mw = mg + 32 * i;
                    float w0 = xw[k][i].x, w1 = xw[k][i].y;
                    float e0 = (__expf(w0 - sc) + EPSF) * SCALEF;
                    float e1 = (__expf(w1 - sc) + EPSF) * SCALEF;
                    float n0 = (__expf(-w0 - sc) + EPSF) * SCALEF;
                    float n1 = (__expf(-w1 - sc) + EPSF) * SCALEF;
                    uint32_t hp = pack_hi(e0, e1);
                    Ah[r * AW + mw] = hp;
                    Al[r * AW + mw] = pack_lo(e0, e1, hp);
                    uint32_t hn = pack_hi(n0, n1);
                    Ah[r * AW + mw + 64] = hn;
                    Al[r * AW + mw + 64] = pack_lo(n0, n1, hn);
                    npart += e0 * knv[i][0] + e1 * knv[i][1]
                           + n0 * knv[i][2] + n1 * knv[i][3];
                }
                np_s[mg * 65 + r] = npart;
            }
            __syncthreads();
            if (tid < 64) {
                float s = 0.f;
#pragma unroll 8
                for (int j = 0; j < 32; ++j) s += np_s[j * 65 + tid];
                ns_s[tid] = s;
            }
            __syncthreads();

            float acc[2][4];
#pragma unroll
            for (int rt = 0; rt < 2; ++rt)
#pragma unroll
                for (int p = 0; p < 4; ++p) acc[rt][p] = 0.f;

#pragma unroll 2
            for (int kt = 0; kt < 16; ++kt) {
                uint32_t bh0 = Bh[(kt * 8 + tg) * BW + nt * 8 + gid];
                uint32_t bh1 = Bh[(kt * 8 + tg + 4) * BW + nt * 8 + gid];
                uint32_t bl0 = Bl[(kt * 8 + tg) * BW + nt * 8 + gid];
                uint32_t bl1 = Bl[(kt * 8 + tg + 4) * BW + nt * 8 + gid];
#pragma unroll
                for (int rt = 0; rt < 2; ++rt) {
                    int rbase = rh * 32 + rt * 16;
                    uint32_t aaddr = sb + OFF_AH + (uint32_t)((rbase + arow) * 528 + kt * 32 + acolb);
                    uint32_t laddr = aaddr + (OFF_AL - OFF_AH);
                    uint32_t a0, a1, a2, a3, l0, l1, l2, l3;
                    ldsm_x4(a0, a1, a2, a3, aaddr);
                    ldsm_x4(l0, l1, l2, l3, laddr);
                    mma_bf16(acc[rt], a0, a1, a2, a3, bh0, bh1);
                    mma_bf16(acc[rt], l0, l1, l2, l3, bh0, bh1);
                    mma_bf16(acc[rt], a0, a1, a2, a3, bl0, bl1);
                }
            }

#pragma unroll
            for (int rt = 0; rt < 2; ++rt) {
                int rs = rh * 32 + rt * 16;
                int row0 = rs + gid, row1 = rs + gid + 8;
                float inv0 = 1.0f / ns_s[row0];
                float inv1 = 1.0f / ns_s[row1];
                float* o0 = out + ((size_t)b * TT + r0 + sub * 64 + row0) * DD + nt * 8 + 2 * tg;
                float* o1 = out + ((size_t)b * TT + r0 + sub * 64 + row1) * DD + nt * 8 + 2 * tg;
                *(float2*)o0 = make_float2(acc[rt][0] * inv0, acc[rt][1] * inv0);
                *(float2*)o1 = make_float2(acc[rt][2] * inv1, acc[rt][3] * inv1);
            }
        }
    }
}

// ---------------------------------------------------------------------------

extern "C" void kernel_launch(void* const* d_in, const int* in_sizes, int n_in,
                              void* d_out, int out_size) {
    const float* query = (const float*)d_in[0];
    const float* value = (const float*)d_in[1];
    const float* key   = (const float*)d_in[2];
    const float* omega = (const float*)d_in[3];
    float* out = (float*)d_out;

    cudaFuncSetAttribute(kv_kernel, cudaFuncAttributeMaxDynamicSharedMemorySize, KV_SMEM);
    cudaFuncSetAttribute(qkv_kernel, cudaFuncAttributeMaxDynamicSharedMemorySize, QSMEM);

    kv_kernel<<<NBLK, 512, KV_SMEM>>>(key, value, omega);
    reduce_kernel<<<dim3((TWOM * KVW / 4 + 255) / 256, BB), 256>>>();
    qkv_kernel<<<QNB, 512, QSMEM>>>(query, omega, out);
}

// round 9
// speedup vs baseline: 1.6953x; 1.1259x over previous
#include <cuda_runtime.h>
#include <cuda_bf16.h>
#include <string.h>
#include <stdint.h>

#define BB 8
#define TT 8192
#define SN 8192
#define FF 64
#define DD 64
#define MMF 128
#define TWOM 256
#define EPSF 1e-9f
#define SCALEF 0.0625f   /* 1/sqrt(2*128) */
#define KVW 66           /* kv row stride: col 64 = normalizer, 65 pad */

/* kv config */
#define NBLK 148
#define NTILES 1024      /* 64-row tiles, 128 per batch */
#define VP 68

/* qkv config (round-7/8 proven) */
#define QTIL 512
#define QNB 148
#define QXP 66
#define AW 132
#define BW 72

__device__ float g_part[(size_t)NBLK * 2 * TWOM * KVW];
__device__ float g_kv[BB * TWOM * KVW];

static __device__ __forceinline__ float2 ffma2(float2 a, float2 b, float2 c) {
    unsigned long long au, bu, cu, du;
    memcpy(&au, &a, 8); memcpy(&bu, &b, 8); memcpy(&cu, &c, 8);
    asm("fma.rn.f32x2 %0, %1, %2, %3;" : "=l"(du) : "l"(au), "l"(bu), "l"(cu));
    float2 d; memcpy(&d, &du, 8);
    return d;
}
static __device__ __forceinline__ uint32_t smem_u32(const void* p) {
    uint32_t a;
    asm("{ .reg .u64 t; cvta.to.shared.u64 t, %1; cvt.u32.u64 %0, t; }" : "=r"(a) : "l"(p));
    return a;
}
static __device__ __forceinline__ void ldsm_x4(uint32_t& r0, uint32_t& r1,
                                               uint32_t& r2, uint32_t& r3, uint32_t addr) {
    asm volatile("ldmatrix.sync.aligned.m8n8.x4.shared.b16 {%0,%1,%2,%3}, [%4];"
                 : "=r"(r0), "=r"(r1), "=r"(r2), "=r"(r3) : "r"(addr));
}
static __device__ __forceinline__ void mma_bf16(float* c,
                                                uint32_t a0, uint32_t a1, uint32_t a2, uint32_t a3,
                                                uint32_t b0, uint32_t b1) {
    asm volatile("mma.sync.aligned.m16n8k16.row.col.f32.bf16.bf16.f32 "
                 "{%0,%1,%2,%3}, {%4,%5,%6,%7}, {%8,%9}, {%0,%1,%2,%3};"
                 : "+f"(c[0]), "+f"(c[1]), "+f"(c[2]), "+f"(c[3])
                 : "r"(a0), "r"(a1), "r"(a2), "r"(a3), "r"(b0), "r"(b1));
}
static __device__ __forceinline__ uint32_t pack_hi(float e0, float e1) {
    __nv_bfloat162 hp;
    hp.x = __float2bfloat16_rn(e0); hp.y = __float2bfloat16_rn(e1);
    uint32_t u; memcpy(&u, &hp, 4); return u;
}
static __device__ __forceinline__ uint32_t pack_lo(float e0, float e1, uint32_t hi) {
    __nv_bfloat162 hp; memcpy(&hp, &hi, 4);
    __nv_bfloat162 lp;
    lp.x = __float2bfloat16_rn(e0 - __bfloat162float(hp.x));
    lp.y = __float2bfloat16_rn(e1 - __bfloat162float(hp.y));
    uint32_t u; memcpy(&u, &lp, 4); return u;
}

/* ---------------- kv smem layout (bytes) ---------------- */
#define KOFF_WH 0                   /* omega bf16 hi [128][72]  18432 */
#define KOFF_WL 18432               /* omega bf16 lo            18432 */
#define KOFF_V  36864               /* v fp32 [64][VP]          17408 */
#define KOFF_XH 54272               /* x packed hi [32][65] u32  8320 */
#define KOFF_XL 62592               /* x packed lo               8320 */
#define KOFF_AH 70912               /* phi hi [256][144B]       36864 */
#define KOFF_AL 107776              /* phi lo                   36864 */
#define KOFF_BH 144640              /* v packed hi [32][72] u32  9216 */
#define KOFF_BL 153856              /* v packed lo               9216 */
#define KOFF_SQ 163072              /* ssq [64] fp32              256 */
#define KV_SMEM 163328

/* ---------------- qkv smem layout (round-7 proven) ---------------- */
#define OFF_OM 0
#define OFF_AH 32768
#define OFF_AL (OFF_AH + 33792)
#define OFF_BH (OFF_AL + 33792)
#define OFF_BL (OFF_BH + 36864)
#define OFF_X  (OFF_BL + 36864)
#define OFF_KN (OFF_X + 16896)
#define OFF_NP (OFF_KN + 1024)
#define OFF_NS (OFF_NP + 8320)
#define QSMEM  (OFF_NS + 256)

// ---------------------------------------------------------------------------
// Kernel 1: fully tensorized kv. 148 blocks x 512 threads over 1024 64-row
// tiles. phi GEMM on HMMA (A = omega frags hoisted in registers, B = x packed
// hi/lo), exp in registers, phi -> A smem (hi/lo, [feature][row]); kv
// accumulate on HMMA (persistent register accumulators); flush per segment.
// ---------------------------------------------------------------------------
__global__ __launch_bounds__(512, 1)
void kv_kernel(const float* __restrict__ key,
               const float* __restrict__ value,
               const float* __restrict__ omega) {
    extern __shared__ char smc[];
    const uint32_t sb = smem_u32(smc);
    float* v_s    = (float*)(smc + KOFF_V);
    float* ssq_s  = (float*)(smc + KOFF_SQ);
    uint32_t* BXh = (uint32_t*)(smc + KOFF_XH);
    uint32_t* BXl = (uint32_t*)(smc + KOFF_XL);
    uint32_t* Bvh = (uint32_t*)(smc + KOFF_BH);
    uint32_t* Bvl = (uint32_t*)(smc + KOFF_BL);

    const int tid = threadIdx.x;
    const int blk = blockIdx.x;
    const int tb = (blk * NTILES) / NBLK;
    const int te = ((blk + 1) * NTILES) / NBLK;

    /* omega -> bf16 hi/lo smem, native [m][f] layout, 144B row stride */
    {
        const float4* om4 = (const float4*)omega;
#pragma unroll
        for (int q = 0; q < 4; ++q) {
            int idx = tid + q * 512;
            float4 v = om4[idx];
            int m = idx >> 4, f = (idx & 15) * 4;
            uint32_t h01 = pack_hi(v.x, v.y), h23 = pack_hi(v.z, v.w);
            uint32_t* wh = (uint32_t*)(smc + KOFF_WH + m * 144 + f * 2);
            uint32_t* wl = (uint32_t*)(smc + KOFF_WL + m * 144 + f * 2);
            wh[0] = h01; wh[1] = h23;
            wl[0] = pack_lo(v.x, v.y, h01); wl[1] = pack_lo(v.z, v.w, h23);
        }
    }
    /* constant B_v pad: cols 64-71 (col 64 = ones) */
    if (tid < 256) {
        int p = tid >> 3, n = 64 + (tid & 7);
        Bvh[p * 72 + n] = (n == 64) ? 0x3F803F80u : 0u;
        Bvl[p * 72 + n] = 0u;
    }
    __syncthreads();

    const int w = tid >> 5, lane = tid & 31;
    const int gid = lane >> 2, tg = lane & 3;
    const int quad = lane >> 3, lrow = lane & 7;
    const int arow = lrow + (quad & 1) * 8;
    const int acolb = (quad >> 1) * 16;
    const int ldr = tid >> 4;
    const int ldc = (tid & 15) * 4;
    /* phi-MMA: warp w owns m-tile mt = w>>1, n-tiles ntb..ntb+3 (r groups) */
    const int mt = w >> 1;
    const int ntb = (w & 1) * 4;
    /* kv-MMA: warp w owns features w*16..+15 (proven) */
    const uint32_t aBase = sb + KOFF_AH + (uint32_t)((w * 16 + arow) * 144 + acolb);

    /* hoist omega A fragments (constant all loop) */
    uint32_t wfh[4][4], wfl[4][4];
    {
        uint32_t obase = sb + KOFF_WH + (uint32_t)((mt * 16 + arow) * 144 + acolb);
#pragma unroll
        for (int kt = 0; kt < 4; ++kt) {
            ldsm_x4(wfh[kt][0], wfh[kt][1], wfh[kt][2], wfh[kt][3], obase + kt * 32);
            ldsm_x4(wfl[kt][0], wfl[kt][1], wfl[kt][2], wfl[kt][3],
                    obase + (KOFF_WL - KOFF_WH) + kt * 32);
        }
    }

    float acc[8][4];
#pragma unroll
    for (int nt = 0; nt < 8; ++nt)
#pragma unroll
        for (int p = 0; p < 4; ++p) acc[nt][p] = 0.f;
    float accN[4] = {0.f, 0.f, 0.f, 0.f};
    int seg = 0;

    float4 px[2], pv[2];
    {
        int t = tb, b = t >> 7, s0 = (t & 127) * 64;
        const float4* kp = (const float4*)(key   + ((size_t)b * SN + s0) * FF);
        const float4* vp = (const float4*)(value + ((size_t)b * SN + s0) * FF);
#pragma unroll
        for (int q = 0; q < 2; ++q) { px[q] = kp[tid + q * 512]; pv[q] = vp[tid + q * 512]; }
    }

    for (int t = tb; t < te; ++t) {
        __syncthreads();   /* prev MMA done with A_phi/B_v; Bx/v/ssq free */

        /* stage: x packed hi/lo, v fp32, ssq (shfl over 16 chunk lanes) */
#pragma unroll
        for (int q = 0; q < 2; ++q) {
            int r = ldr + q * 32;
            float4 xv = px[q];
            int p0 = ldc >> 1;
            uint32_t h0 = pack_hi(xv.x, xv.y), h1 = pack_hi(xv.z, xv.w);
            BXh[p0 * 65 + r]       = h0;
            BXh[(p0 + 1) * 65 + r] = h1;
            BXl[p0 * 65 + r]       = pack_lo(xv.x, xv.y, h0);
            BXl[(p0 + 1) * 65 + r] = pack_lo(xv.z, xv.w, h1);
            *(float4*)&v_s[r * VP + ldc] = pv[q];
            float sq = xv.x * xv.x + xv.y * xv.y + xv.z * xv.z + xv.w * xv.w;
#pragma unroll
            for (int d = 1; d < 16; d <<= 1)
                sq += __shfl_xor_sync(0xffffffffu, sq, d);
            if ((tid & 15) == 0) ssq_s[r] = 0.5f * sq;
        }
        if (t + 1 < te) {
            int tn = t + 1, b = tn >> 7, s0 = (tn & 127) * 64;
            const float4* kp = (const float4*)(key   + ((size_t)b * SN + s0) * FF);
            const float4* vp = (const float4*)(value + ((size_t)b * SN + s0) * FF);
#pragma unroll
            for (int q = 0; q < 2; ++q) { px[q] = kp[tid + q * 512]; pv[q] = vp[tid + q * 512]; }
        }
        __syncthreads();   /* Bx, v, ssq ready */

        /* pack B_v: word[p][n] = {v[2p][n], v[2p+1][n]} hi/lo */
#pragma unroll
        for (int q = 0; q < 4; ++q) {
            int idx = tid + q * 512;
            int p = idx >> 6, n = idx & 63;
            float v0 = v_s[(2 * p) * VP + n];
            float v1 = v_s[(2 * p + 1) * VP + n];
            uint32_t hw = pack_hi(v0, v1);
            Bvh[p * 72 + n] = hw;
            Bvl[p * 72 + n] = pack_lo(v0, v1, hw);
        }

        /* phi-MMA + exp + store, one n-tile at a time */
#pragma unroll
        for (int nt4 = 0; nt4 < 4; ++nt4) {
            const int nt = ntb + nt4;
            float wa[4] = {0.f, 0.f, 0.f, 0.f};
#pragma unroll
            for (int kt = 0; kt < 4; ++kt) {
                int p0 = kt * 8 + tg, p1 = p0 + 4;
                uint32_t bh0 = BXh[p0 * 65 + nt * 8 + gid];
                uint32_t bh1 = BXh[p1 * 65 + nt * 8 + gid];
                uint32_t bl0 = BXl[p0 * 65 + nt * 8 + gid];
                uint32_t bl1 = BXl[p1 * 65 + nt * 8 + gid];
                mma_bf16(wa, wfh[kt][0], wfh[kt][1], wfh[kt][2], wfh[kt][3], bh0, bh1);
                mma_bf16(wa, wfl[kt][0], wfl[kt][1], wfl[kt][2], wfl[kt][3], bh0, bh1);
                mma_bf16(wa, wfh[kt][0], wfh[kt][1], wfh[kt][2], wfh[kt][3], bl0, bl1);
            }
            /* wa = {w[m0][r0], w[m0][r0+1], w[m1][r0], w[m1][r0+1]} */
            const int r0 = nt * 8 + 2 * tg;
            const float sc0 = ssq_s[r0];
            const float sc1 = ssq_s[r0 + 1];
#pragma unroll
            for (int half = 0; half < 2; ++half) {
                int m = mt * 16 + gid + 8 * half;
                float w0 = wa[2 * half], w1 = wa[2 * half + 1];
                float e0 = (__expf(w0 - sc0) + EPSF) * SCALEF;
                float e1 = (__expf(w1 - sc1) + EPSF) * SCALEF;
                float g0 = (__expf(-w0 - sc0) + EPSF) * SCALEF;
                float g1 = (__expf(-w1 - sc1) + EPSF) * SCALEF;
                uint32_t he = pack_hi(e0, e1);
                uint32_t hg = pack_hi(g0, g1);
                *(uint32_t*)(smc + KOFF_AH + m * 144 + r0 * 2)           = he;
                *(uint32_t*)(smc + KOFF_AL + m * 144 + r0 * 2)           = pack_lo(e0, e1, he);
                *(uint32_t*)(smc + KOFF_AH + (m + 128) * 144 + r0 * 2)   = hg;
                *(uint32_t*)(smc + KOFF_AL + (m + 128) * 144 + r0 * 2)   = pack_lo(g0, g1, hg);
            }
        }
        __syncthreads();   /* A_phi, B_v ready */

        /* kv-MMA: D[feature 16 per warp][72], K = 64 rows (r8 proven) */
#pragma unroll
        for (int kt = 0; kt < 4; ++kt) {
            uint32_t ah0, ah1, ah2, ah3, al0, al1, al2, al3;
            ldsm_x4(ah0, ah1, ah2, ah3, aBase + kt * 32);
            ldsm_x4(al0, al1, al2, al3, aBase + (KOFF_AL - KOFF_AH) + kt * 32);
            const int p0 = kt * 8 + tg, p1 = kt * 8 + tg + 4;
#pragma unroll
            for (int nt = 0; nt < 8; ++nt) {
                uint32_t bh0 = Bvh[p0 * 72 + nt * 8 + gid];
                uint32_t bh1 = Bvh[p1 * 72 + nt * 8 + gid];
                uint32_t bl0 = Bvl[p0 * 72 + nt * 8 + gid];
                uint32_t bl1 = Bvl[p1 * 72 + nt * 8 + gid];
                mma_bf16(acc[nt], ah0, ah1, ah2, ah3, bh0, bh1);
                mma_bf16(acc[nt], al0, al1, al2, al3, bh0, bh1);
                mma_bf16(acc[nt], ah0, ah1, ah2, ah3, bl0, bl1);
            }
            {
                uint32_t bn0 = Bvh[p0 * 72 + 64 + gid];
                uint32_t bn1 = Bvh[p1 * 72 + 64 + gid];
                mma_bf16(accN, ah0, ah1, ah2, ah3, bn0, bn1);
                mma_bf16(accN, al0, al1, al2, al3, bn0, bn1);
            }
        }

        /* flush at batch boundary or end */
        if (t + 1 == te || ((t + 1) >> 7) != (t >> 7)) {
            float* base = &g_part[(size_t)(blk * 2 + seg) * TWOM * KVW];
            const int f0 = w * 16 + gid;
#pragma unroll
            for (int nt = 0; nt < 8; ++nt) {
                int c = nt * 8 + 2 * tg;
                *(float2*)&base[f0 * KVW + c]       = make_float2(acc[nt][0], acc[nt][1]);
                *(float2*)&base[(f0 + 8) * KVW + c] = make_float2(acc[nt][2], acc[nt][3]);
            }
            if (tg == 0) {
                base[f0 * KVW + 64]       = accN[0];
                base[(f0 + 8) * KVW + 64] = accN[2];
            }
            ++seg;
#pragma unroll
            for (int nt = 0; nt < 8; ++nt)
#pragma unroll
                for (int p = 0; p < 4; ++p) acc[nt][p] = 0.f;
#pragma unroll
            for (int p = 0; p < 4; ++p) accN[p] = 0.f;
        }
    }
}

// ---------------------------------------------------------------------------
// Kernel 2: deterministic reduction
// ---------------------------------------------------------------------------
__global__ void reduce_kernel() {
    const int per_b4 = TWOM * KVW / 4;
    int idx = blockIdx.x * blockDim.x + threadIdx.x;
    int b = blockIdx.y;
    if (idx >= per_b4) return;
    float4 s = make_float4(0.f, 0.f, 0.f, 0.f);
    for (int i = 0; i < NBLK; ++i) {
        int tb = (i * NTILES) / NBLK;
        int te = ((i + 1) * NTILES) / NBLK;
        int b0 = tb >> 7;
        int bl = (te - 1) >> 7;
        int slot = (b0 == b) ? 0 : ((bl == b && bl != b0) ? 1 : -1);
        if (slot >= 0) {
            float4 v = ((const float4*)g_part)[(size_t)(i * 2 + slot) * per_b4 + idx];
            s.x += v.x; s.y += v.y; s.z += v.z; s.w += v.w;
        }
    }
    ((float4*)g_kv)[(size_t)b * per_b4 + idx] = s;
}

// ---------------------------------------------------------------------------
// Kernel 3 (round-7/8 proven): mma.sync bf16 hi/lo qkv.
// ---------------------------------------------------------------------------
__global__ __launch_bounds__(512, 1)
void qkv_kernel(const float* __restrict__ query,
                const float* __restrict__ omega,
                float* __restrict__ out) {
    extern __shared__ char smc[];
    const uint32_t sb = smem_u32(smc);
    float* omega_s = (float*)(smc + OFF_OM);
    float* x_s     = (float*)(smc + OFF_X);
    float* kn_s    = (float*)(smc + OFF_KN);
    float* np_s    = (float*)(smc + OFF_NP);
    float* ns_s    = (float*)(smc + OFF_NS);
    uint32_t* Ah   = (uint32_t*)(smc + OFF_AH);
    uint32_t* Al   = (uint32_t*)(smc + OFF_AL);
    const uint32_t* Bh = (const uint32_t*)(smc + OFF_BH);
    const uint32_t* Bl = (const uint32_t*)(smc + OFF_BL);
    uint32_t* Bhw  = (uint32_t*)(smc + OFF_BH);
    uint32_t* Blw  = (uint32_t*)(smc + OFF_BL);

    const int tid = threadIdx.x;
    const int blk = blockIdx.x;
    const int tb = (blk * QTIL) / QNB;
    const int te = ((blk + 1) * QTIL) / QNB;

    {
        const float4* om4 = (const float4*)omega;
#pragma unroll
        for (int q = 0; q < 4; ++q) {
            int idx = tid + q * 512;
            float4 v = om4[idx];
            int m = idx >> 4, f = (idx & 15) * 4;
            omega_s[f * MMF + m]       = v.x;
            omega_s[(f + 1) * MMF + m] = v.y;
            omega_s[(f + 2) * MMF + m] = v.z;
            omega_s[(f + 3) * MMF + m] = v.w;
        }
    }

    const int rg = tid & 15;
    const int mg = tid >> 4;
    const int w = tid >> 5, lane = tid & 31;
    const int nt = w & 7, rh = w >> 3;
    const int gid = lane >> 2, tg = lane & 3;
    const int quad = lane >> 3, lrow = lane & 7;
    const int arow = lrow + (quad & 1) * 8;
    const int acolb = (quad >> 1) * 16;

    int cur_b = -1;
    float4 px[4];
    {
        int t = tb, b = t >> 6, r0 = (t & 63) * 128;
        const float4* qp = (const float4*)(query + ((size_t)b * TT + r0) * FF);
#pragma unroll
        for (int q = 0; q < 4; ++q) px[q] = qp[tid + q * 512];
    }

    for (int t = tb; t < te; ++t) {
        const int b = t >> 6;
        const int r0 = (t & 63) * 128;

        if (b != cur_b) {
            __syncthreads();
            const float* kvp = &g_kv[(size_t)b * TWOM * KVW];
            for (int i = tid; i < 128 * 64; i += 512) {
                int p = i >> 6, n = i & 63;
                float v0 = kvp[(2 * p) * KVW + n];
                float v1 = kvp[(2 * p + 1) * KVW + n];
                uint32_t hw = pack_hi(v0, v1);
                Bhw[p * BW + n] = hw;
                Blw[p * BW + n] = pack_lo(v0, v1, hw);
            }
            if (tid < 256) kn_s[tid] = kvp[tid * KVW + 64];
            cur_b = b;
        }

        for (int sub = 0; sub < 2; ++sub) {
            __syncthreads();
#pragma unroll
            for (int q = 0; q < 2; ++q) {
                float4 xv = px[2 * sub + q];
                int idx = tid + q * 512;
                int r = idx >> 4, c = (idx & 15) * 4;
                float* xd = &x_s[r * QXP + c];
                *(float2*)xd       = make_float2(xv.x, xv.y);
                *(float2*)(xd + 2) = make_float2(xv.z, xv.w);
            }
            if (sub == 1 && t + 1 < te) {
                int tn = t + 1, bn = tn >> 6, rn = (tn & 63) * 128;
                const float4* qp = (const float4*)(query + ((size_t)bn * TT + rn) * FF);
#pragma unroll
                for (int q = 0; q < 4; ++q) px[q] = qp[tid + q * 512];
            }
            __syncthreads();

            float2 xw[4][2], ss2[4];
#pragma unroll
            for (int k = 0; k < 4; ++k) {
                ss2[k] = make_float2(0.f, 0.f);
                xw[k][0] = make_float2(0.f, 0.f);
                xw[k][1] = make_float2(0.f, 0.f);
            }
#pragma unroll 4
            for (int f = 0; f < FF; f += 2) {
                float2 xv[4];
#pragma unroll
                for (int k = 0; k < 4; ++k)
                    xv[k] = *(const float2*)&x_s[(rg + 16 * k) * QXP + f];
                const float2* om0 = (const float2*)&omega_s[f * MMF];
                const float2* om1 = (const float2*)&omega_s[(f + 1) * MMF];
                float2 o0[2], o1[2];
#pragma unroll
                for (int i = 0; i < 2; ++i) { o0[i] = om0[mg + 32 * i]; o1[i] = om1[mg + 32 * i]; }
#pragma unroll
                for (int k = 0; k < 4; ++k) {
                    ss2[k] = ffma2(xv[k], xv[k], ss2[k]);
                    float2 a0 = make_float2(xv[k].x, xv[k].x);
                    float2 a1 = make_float2(xv[k].y, xv[k].y);
#pragma unroll
                    for (int i = 0; i < 2; ++i) {
                        xw[k][i] = ffma2(a0, o0[i], xw[k][i]);
                        xw[k][i] = ffma2(a1, o1[i], xw[k][i]);
                    }
                }
            }
            float knv[2][4];
#pragma unroll
            for (int i = 0; i < 2; ++i) {
                int m = 2 * (mg + 32 * i);
                knv[i][0] = kn_s[m];       knv[i][1] = kn_s[m + 1];
                knv[i][2] = kn_s[m + 128]; knv[i][3] = kn_s[m + 129];
            }
#pragma unroll
            for (int k = 0; k < 4; ++k) {
                int r = rg + 16 * k;
                float sc = 0.5f * (ss2[k].x + ss2[k].y);
                float npart = 0.f;
#pragma unroll
                for (int i = 0; i < 2; ++i) {
                    int mw = mg + 32 * i;
                    float w0 = xw[k][i].x, w1 = xw[k][i].y;
                    float e0 = (__expf(w0 - sc) + EPSF) * SCALEF;
                    float e1 = (__expf(w1 - sc) + EPSF) * SCALEF;
                    float n0 = (__expf(-w0 - sc) + EPSF) * SCALEF;
                    float n1 = (__expf(-w1 - sc) + EPSF) * SCALEF;
                    uint32_t hp = pack_hi(e0, e1);
                    Ah[r * AW + mw] = hp;
                    Al[r * AW + mw] = pack_lo(e0, e1, hp);
                    uint32_t hn = pack_hi(n0, n1);
                    Ah[r * AW + mw + 64] = hn;
                    Al[r * AW + mw + 64] = pack_lo(n0, n1, hn);
                    npart += e0 * knv[i][0] + e1 * knv[i][1]
                           + n0 * knv[i][2] + n1 * knv[i][3];
                }
                np_s[mg * 65 + r] = npart;
            }
            __syncthreads();
            if (tid < 64) {
                float s = 0.f;
#pragma unroll 8
                for (int j = 0; j < 32; ++j) s += np_s[j * 65 + tid];
                ns_s[tid] = s;
            }
            __syncthreads();

            float acc[2][4];
#pragma unroll
            for (int rt = 0; rt < 2; ++rt)
#pragma unroll
                for (int p = 0; p < 4; ++p) acc[rt][p] = 0.f;

#pragma unroll 2
            for (int kt = 0; kt < 16; ++kt) {
                uint32_t bh0 = Bh[(kt * 8 + tg) * BW + nt * 8 + gid];
                uint32_t bh1 = Bh[(kt * 8 + tg + 4) * BW + nt * 8 + gid];
                uint32_t bl0 = Bl[(kt * 8 + tg) * BW + nt * 8 + gid];
                uint32_t bl1 = Bl[(kt * 8 + tg + 4) * BW + nt * 8 + gid];
#pragma unroll
                for (int rt = 0; rt < 2; ++rt) {
                    int rbase = rh * 32 + rt * 16;
                    uint32_t aaddr = sb + OFF_AH + (uint32_t)((rbase + arow) * 528 + kt * 32 + acolb);
                    uint32_t laddr = aaddr + (OFF_AL - OFF_AH);
                    uint32_t a0, a1, a2, a3, l0, l1, l2, l3;
                    ldsm_x4(a0, a1, a2, a3, aaddr);
                    ldsm_x4(l0, l1, l2, l3, laddr);
                    mma_bf16(acc[rt], a0, a1, a2, a3, bh0, bh1);
                    mma_bf16(acc[rt], l0, l1, l2, l3, bh0, bh1);
                    mma_bf16(acc[rt], a0, a1, a2, a3, bl0, bl1);
                }
            }

#pragma unroll
            for (int rt = 0; rt < 2; ++rt) {
                int rs = rh * 32 + rt * 16;
                int row0 = rs + gid, row1 = rs + gid + 8;
                float inv0 = 1.0f / ns_s[row0];
                float inv1 = 1.0f / ns_s[row1];
                float* o0 = out + ((size_t)b * TT + r0 + sub * 64 + row0) * DD + nt * 8 + 2 * tg;
                float* o1 = out + ((size_t)b * TT + r0 + sub * 64 + row1) * DD + nt * 8 + 2 * tg;
                *(float2*)o0 = make_float2(acc[rt][0] * inv0, acc[rt][1] * inv0);
                *(float2*)o1 = make_float2(acc[rt][2] * inv1, acc[rt][3] * inv1);
            }
        }
    }
}

// ---------------------------------------------------------------------------

extern "C" void kernel_launch(void* const* d_in, const int* in_sizes, int n_in,
                              void* d_out, int out_size) {
    const float* query = (const float*)d_in[0];
    const float* value = (const float*)d_in[1];
    const float* key   = (const float*)d_in[2];
    const float* omega = (const float*)d_in[3];
    float* out = (float*)d_out;

    cudaFuncSetAttribute(kv_kernel, cudaFuncAttributeMaxDynamicSharedMemorySize, KV_SMEM);
    cudaFuncSetAttribute(qkv_kernel, cudaFuncAttributeMaxDynamicSharedMemorySize, QSMEM);

    kv_kernel<<<NBLK, 512, KV_SMEM>>>(key, value, omega);
    reduce_kernel<<<dim3((TWOM * KVW / 4 + 255) / 256, BB), 256>>>();
    qkv_kernel<<<QNB, 512, QSMEM>>>(query, omega, out);
}

// round 10
// speedup vs baseline: 1.8573x; 1.0956x over previous
#include <cuda_runtime.h>
#include <cuda_bf16.h>
#include <string.h>
#include <stdint.h>

#define BB 8
#define TT 8192
#define SN 8192
#define FF 64
#define DD 64
#define MMF 128
#define TWOM 256
#define EPSF 1e-9f
#define SCALEF 0.0625f   /* 1/sqrt(2*128) */
#define KVW 66           /* kv row stride: col 64 = normalizer, 65 pad */

/* kv config (round-9 proven) */
#define NBLK 148
#define NTILES 1024      /* 64-row tiles, 128 per batch */
#define VP 68

/* qkv config */
#define QTIL 512         /* 128-row t-tiles, 64 per batch */
#define QNB 148

__device__ float g_part[(size_t)NBLK * 2 * TWOM * KVW];
__device__ float g_kv[BB * TWOM * KVW];

static __device__ __forceinline__ uint32_t smem_u32(const void* p) {
    uint32_t a;
    asm("{ .reg .u64 t; cvta.to.shared.u64 t, %1; cvt.u32.u64 %0, t; }" : "=r"(a) : "l"(p));
    return a;
}
static __device__ __forceinline__ void ldsm_x4(uint32_t& r0, uint32_t& r1,
                                               uint32_t& r2, uint32_t& r3, uint32_t addr) {
    asm volatile("ldmatrix.sync.aligned.m8n8.x4.shared.b16 {%0,%1,%2,%3}, [%4];"
                 : "=r"(r0), "=r"(r1), "=r"(r2), "=r"(r3) : "r"(addr));
}
static __device__ __forceinline__ void ldsm_x4_t(uint32_t& r0, uint32_t& r1,
                                                 uint32_t& r2, uint32_t& r3, uint32_t addr) {
    asm volatile("ldmatrix.sync.aligned.m8n8.x4.trans.shared.b16 {%0,%1,%2,%3}, [%4];"
                 : "=r"(r0), "=r"(r1), "=r"(r2), "=r"(r3) : "r"(addr));
}
static __device__ __forceinline__ void mma_bf16(float* c,
                                                uint32_t a0, uint32_t a1, uint32_t a2, uint32_t a3,
                                                uint32_t b0, uint32_t b1) {
    asm volatile("mma.sync.aligned.m16n8k16.row.col.f32.bf16.bf16.f32 "
                 "{%0,%1,%2,%3}, {%4,%5,%6,%7}, {%8,%9}, {%0,%1,%2,%3};"
                 : "+f"(c[0]), "+f"(c[1]), "+f"(c[2]), "+f"(c[3])
                 : "r"(a0), "r"(a1), "r"(a2), "r"(a3), "r"(b0), "r"(b1));
}
static __device__ __forceinline__ uint32_t pack_hi(float e0, float e1) {
    __nv_bfloat162 hp;
    hp.x = __float2bfloat16_rn(e0); hp.y = __float2bfloat16_rn(e1);
    uint32_t u; memcpy(&u, &hp, 4); return u;
}
static __device__ __forceinline__ uint32_t pack_lo(float e0, float e1, uint32_t hi) {
    __nv_bfloat162 hp; memcpy(&hp, &hi, 4);
    __nv_bfloat162 lp;
    lp.x = __float2bfloat16_rn(e0 - __bfloat162float(hp.x));
    lp.y = __float2bfloat16_rn(e1 - __bfloat162float(hp.y));
    uint32_t u; memcpy(&u, &lp, 4); return u;
}

/* ---------------- kv smem layout (round-9 proven) ---------------- */
#define KOFF_WH 0
#define KOFF_WL 18432
#define KOFF_V  36864
#define KOFF_XH 54272
#define KOFF_XL 62592
#define KOFF_AH 70912
#define KOFF_AL 107776
#define KOFF_BH 144640
#define KOFF_BL 153856
#define KOFF_SQ 163072
#define KV_SMEM 163328

/* ---------------- qkv smem layout (bytes) ---------------- */
#define QOFF_PH 0          /* phiT hi [256][144B]; omega hi during init  36864 */
#define QOFF_PL 36864      /* phiT lo; omega lo during init              36864 */
#define QOFF_BH 73728      /* kv packed hi [128][72] u32                 36864 */
#define QOFF_BL 110592     /* kv packed lo                               36864 */
#define QOFF_XH 147456     /* x packed hi [32][65] u32                    8320 */
#define QOFF_XL 155776     /* x packed lo                                 8320 */
#define QOFF_SQ 164096     /* ssq [64]                                     256 */
#define QOFF_NS 164352     /* norm [64]                                    256 */
#define QSMEM   164608

// ---------------------------------------------------------------------------
// Kernel 1 (round-9 proven): fully tensorized kv.
// ---------------------------------------------------------------------------
__global__ __launch_bounds__(512, 1)
void kv_kernel(const float* __restrict__ key,
               const float* __restrict__ value,
               const float* __restrict__ omega) {
    extern __shared__ char smc[];
    const uint32_t sb = smem_u32(smc);
    float* v_s    = (float*)(smc + KOFF_V);
    float* ssq_s  = (float*)(smc + KOFF_SQ);
    uint32_t* BXh = (uint32_t*)(smc + KOFF_XH);
    uint32_t* BXl = (uint32_t*)(smc + KOFF_XL);
    uint32_t* Bvh = (uint32_t*)(smc + KOFF_BH);
    uint32_t* Bvl = (uint32_t*)(smc + KOFF_BL);

    const int tid = threadIdx.x;
    const int blk = blockIdx.x;
    const int tb = (blk * NTILES) / NBLK;
    const int te = ((blk + 1) * NTILES) / NBLK;

    {
        const float4* om4 = (const float4*)omega;
#pragma unroll
        for (int q = 0; q < 4; ++q) {
            int idx = tid + q * 512;
            float4 v = om4[idx];
            int m = idx >> 4, f = (idx & 15) * 4;
            uint32_t h01 = pack_hi(v.x, v.y), h23 = pack_hi(v.z, v.w);
            uint32_t* wh = (uint32_t*)(smc + KOFF_WH + m * 144 + f * 2);
            uint32_t* wl = (uint32_t*)(smc + KOFF_WL + m * 144 + f * 2);
            wh[0] = h01; wh[1] = h23;
            wl[0] = pack_lo(v.x, v.y, h01); wl[1] = pack_lo(v.z, v.w, h23);
        }
    }
    if (tid < 256) {
        int p = tid >> 3, n = 64 + (tid & 7);
        Bvh[p * 72 + n] = (n == 64) ? 0x3F803F80u : 0u;
        Bvl[p * 72 + n] = 0u;
    }
    __syncthreads();

    const int w = tid >> 5, lane = tid & 31;
    const int gid = lane >> 2, tg = lane & 3;
    const int quad = lane >> 3, lrow = lane & 7;
    const int arow = lrow + (quad & 1) * 8;
    const int acolb = (quad >> 1) * 16;
    const int ldr = tid >> 4;
    const int ldc = (tid & 15) * 4;
    const int mt = w >> 1;
    const int ntb = (w & 1) * 4;
    const uint32_t aBase = sb + KOFF_AH + (uint32_t)((w * 16 + arow) * 144 + acolb);

    uint32_t wfh[4][4], wfl[4][4];
    {
        uint32_t obase = sb + KOFF_WH + (uint32_t)((mt * 16 + arow) * 144 + acolb);
#pragma unroll
        for (int kt = 0; kt < 4; ++kt) {
            ldsm_x4(wfh[kt][0], wfh[kt][1], wfh[kt][2], wfh[kt][3], obase + kt * 32);
            ldsm_x4(wfl[kt][0], wfl[kt][1], wfl[kt][2], wfl[kt][3],
                    obase + (KOFF_WL - KOFF_WH) + kt * 32);
        }
    }

    float acc[8][4];
#pragma unroll
    for (int nt = 0; nt < 8; ++nt)
#pragma unroll
        for (int p = 0; p < 4; ++p) acc[nt][p] = 0.f;
    float accN[4] = {0.f, 0.f, 0.f, 0.f};
    int seg = 0;

    float4 px[2], pv[2];
    {
        int t = tb, b = t >> 7, s0 = (t & 127) * 64;
        const float4* kp = (const float4*)(key   + ((size_t)b * SN + s0) * FF);
        const float4* vp = (const float4*)(value + ((size_t)b * SN + s0) * FF);
#pragma unroll
        for (int q = 0; q < 2; ++q) { px[q] = kp[tid + q * 512]; pv[q] = vp[tid + q * 512]; }
    }

    for (int t = tb; t < te; ++t) {
        __syncthreads();

#pragma unroll
        for (int q = 0; q < 2; ++q) {
            int r = ldr + q * 32;
            float4 xv = px[q];
            int p0 = ldc >> 1;
            uint32_t h0 = pack_hi(xv.x, xv.y), h1 = pack_hi(xv.z, xv.w);
            BXh[p0 * 65 + r]       = h0;
            BXh[(p0 + 1) * 65 + r] = h1;
            BXl[p0 * 65 + r]       = pack_lo(xv.x, xv.y, h0);
            BXl[(p0 + 1) * 65 + r] = pack_lo(xv.z, xv.w, h1);
            *(float4*)&v_s[r * VP + ldc] = pv[q];
            float sq = xv.x * xv.x + xv.y * xv.y + xv.z * xv.z + xv.w * xv.w;
#pragma unroll
            for (int d = 1; d < 16; d <<= 1)
                sq += __shfl_xor_sync(0xffffffffu, sq, d);
            if ((tid & 15) == 0) ssq_s[r] = 0.5f * sq;
        }
        if (t + 1 < te) {
            int tn = t + 1, b = tn >> 7, s0 = (tn & 127) * 64;
            const float4* kp = (const float4*)(key   + ((size_t)b * SN + s0) * FF);
            const float4* vp = (const float4*)(value + ((size_t)b * SN + s0) * FF);
#pragma unroll
            for (int q = 0; q < 2; ++q) { px[q] = kp[tid + q * 512]; pv[q] = vp[tid + q * 512]; }
        }
        __syncthreads();

#pragma unroll
        for (int q = 0; q < 4; ++q) {
            int idx = tid + q * 512;
            int p = idx >> 6, n = idx & 63;
            float v0 = v_s[(2 * p) * VP + n];
            float v1 = v_s[(2 * p + 1) * VP + n];
            uint32_t hw = pack_hi(v0, v1);
            Bvh[p * 72 + n] = hw;
            Bvl[p * 72 + n] = pack_lo(v0, v1, hw);
        }

#pragma unroll
        for (int nt4 = 0; nt4 < 4; ++nt4) {
            const int nt = ntb + nt4;
            float wa[4] = {0.f, 0.f, 0.f, 0.f};
#pragma unroll
            for (int kt = 0; kt < 4; ++kt) {
                int p0 = kt * 8 + tg, p1 = p0 + 4;
                uint32_t bh0 = BXh[p0 * 65 + nt * 8 + gid];
                uint32_t bh1 = BXh[p1 * 65 + nt * 8 + gid];
                uint32_t bl0 = BXl[p0 * 65 + nt * 8 + gid];
                uint32_t bl1 = BXl[p1 * 65 + nt * 8 + gid];
                mma_bf16(wa, wfh[kt][0], wfh[kt][1], wfh[kt][2], wfh[kt][3], bh0, bh1);
                mma_bf16(wa, wfl[kt][0], wfl[kt][1], wfl[kt][2], wfl[kt][3], bh0, bh1);
                mma_bf16(wa, wfh[kt][0], wfh[kt][1], wfh[kt][2], wfh[kt][3], bl0, bl1);
            }
            const int r0 = nt * 8 + 2 * tg;
            const float sc0 = ssq_s[r0];
            const float sc1 = ssq_s[r0 + 1];
#pragma unroll
            for (int half = 0; half < 2; ++half) {
                int m = mt * 16 + gid + 8 * half;
                float w0 = wa[2 * half], w1 = wa[2 * half + 1];
                float e0 = (__expf(w0 - sc0) + EPSF) * SCALEF;
                float e1 = (__expf(w1 - sc1) + EPSF) * SCALEF;
                float g0 = (__expf(-w0 - sc0) + EPSF) * SCALEF;
                float g1 = (__expf(-w1 - sc1) + EPSF) * SCALEF;
                uint32_t he = pack_hi(e0, e1);
                uint32_t hg = pack_hi(g0, g1);
                *(uint32_t*)(smc + KOFF_AH + m * 144 + r0 * 2)         = he;
                *(uint32_t*)(smc + KOFF_AL + m * 144 + r0 * 2)         = pack_lo(e0, e1, he);
                *(uint32_t*)(smc + KOFF_AH + (m + 128) * 144 + r0 * 2) = hg;
                *(uint32_t*)(smc + KOFF_AL + (m + 128) * 144 + r0 * 2) = pack_lo(g0, g1, hg);
            }
        }
        __syncthreads();

#pragma unroll
        for (int kt = 0; kt < 4; ++kt) {
            uint32_t ah0, ah1, ah2, ah3, al0, al1, al2, al3;
            ldsm_x4(ah0, ah1, ah2, ah3, aBase + kt * 32);
            ldsm_x4(al0, al1, al2, al3, aBase + (KOFF_AL - KOFF_AH) + kt * 32);
            const int p0 = kt * 8 + tg, p1 = kt * 8 + tg + 4;
#pragma unroll
            for (int nt = 0; nt < 8; ++nt) {
                uint32_t bh0 = Bvh[p0 * 72 + nt * 8 + gid];
                uint32_t bh1 = Bvh[p1 * 72 + nt * 8 + gid];
                uint32_t bl0 = Bvl[p0 * 72 + nt * 8 + gid];
                uint32_t bl1 = Bvl[p1 * 72 + nt * 8 + gid];
                mma_bf16(acc[nt], ah0, ah1, ah2, ah3, bh0, bh1);
                mma_bf16(acc[nt], al0, al1, al2, al3, bh0, bh1);
                mma_bf16(acc[nt], ah0, ah1, ah2, ah3, bl0, bl1);
            }
            {
                uint32_t bn0 = Bvh[p0 * 72 + 64 + gid];
                uint32_t bn1 = Bvh[p1 * 72 + 64 + gid];
                mma_bf16(accN, ah0, ah1, ah2, ah3, bn0, bn1);
                mma_bf16(accN, al0, al1, al2, al3, bn0, bn1);
            }
        }

        if (t + 1 == te || ((t + 1) >> 7) != (t >> 7)) {
            float* base = &g_part[(size_t)(blk * 2 + seg) * TWOM * KVW];
            const int f0 = w * 16 + gid;
#pragma unroll
            for (int nt = 0; nt < 8; ++nt) {
                int c = nt * 8 + 2 * tg;
                *(float2*)&base[f0 * KVW + c]       = make_float2(acc[nt][0], acc[nt][1]);
                *(float2*)&base[(f0 + 8) * KVW + c] = make_float2(acc[nt][2], acc[nt][3]);
            }
            if (tg == 0) {
                base[f0 * KVW + 64]       = accN[0];
                base[(f0 + 8) * KVW + 64] = accN[2];
            }
            ++seg;
#pragma unroll
            for (int nt = 0; nt < 8; ++nt)
#pragma unroll
                for (int p = 0; p < 4; ++p) acc[nt][p] = 0.f;
#pragma unroll
            for (int p = 0; p < 4; ++p) accN[p] = 0.f;
        }
    }
}

// ---------------------------------------------------------------------------
// Kernel 2: deterministic reduction (proven)
// ---------------------------------------------------------------------------
__global__ void reduce_kernel() {
    const int per_b4 = TWOM * KVW / 4;
    int idx = blockIdx.x * blockDim.x + threadIdx.x;
    int b = blockIdx.y;
    if (idx >= per_b4) return;
    float4 s = make_float4(0.f, 0.f, 0.f, 0.f);
    for (int i = 0; i < NBLK; ++i) {
        int tb = (i * NTILES) / NBLK;
        int te = ((i + 1) * NTILES) / NBLK;
        int b0 = tb >> 7;
        int bl = (te - 1) >> 7;
        int slot = (b0 == b) ? 0 : ((bl == b && bl != b0) ? 1 : -1);
        if (slot >= 0) {
            float4 v = ((const float4*)g_part)[(size_t)(i * 2 + slot) * per_b4 + idx];
            s.x += v.x; s.y += v.y; s.z += v.z; s.w += v.w;
        }
    }
    ((float4*)g_kv)[(size_t)b * per_b4 + idx] = s;
}

// ---------------------------------------------------------------------------
// Kernel 3: fully tensorized qkv. phi GEMM on HMMA (omega frags hoisted),
// phiT[feature][row] hi/lo; qkv GEMM consumes phiT via ldmatrix.trans;
// normalizer = B column 64 (kn) via norm-MMA on warps (nt==rh).
// ---------------------------------------------------------------------------
__global__ __launch_bounds__(512, 1)
void qkv_kernel(const float* __restrict__ query,
                const float* __restrict__ omega,
                float* __restrict__ out) {
    extern __shared__ char smc[];
    const uint32_t sb = smem_u32(smc);
    float* ssq_s  = (float*)(smc + QOFF_SQ);
    float* ns_s   = (float*)(smc + QOFF_NS);
    uint32_t* BXh = (uint32_t*)(smc + QOFF_XH);
    uint32_t* BXl = (uint32_t*)(smc + QOFF_XL);
    uint32_t* Bh  = (uint32_t*)(smc + QOFF_BH);
    uint32_t* Bl  = (uint32_t*)(smc + QOFF_BL);

    const int tid = threadIdx.x;
    const int blk = blockIdx.x;
    const int tb = (blk * QTIL) / QNB;
    const int te = ((blk + 1) * QTIL) / QNB;

    /* omega -> bf16 hi/lo into phiT region (frags hoisted before overwrite) */
    {
        const float4* om4 = (const float4*)omega;
#pragma unroll
        for (int q = 0; q < 4; ++q) {
            int idx = tid + q * 512;
            float4 v = om4[idx];
            int m = idx >> 4, f = (idx & 15) * 4;
            uint32_t h01 = pack_hi(v.x, v.y), h23 = pack_hi(v.z, v.w);
            uint32_t* wh = (uint32_t*)(smc + QOFF_PH + m * 144 + f * 2);
            uint32_t* wl = (uint32_t*)(smc + QOFF_PL + m * 144 + f * 2);
            wh[0] = h01; wh[1] = h23;
            wl[0] = pack_lo(v.x, v.y, h01); wl[1] = pack_lo(v.z, v.w, h23);
        }
    }
    __syncthreads();

    const int w = tid >> 5, lane = tid & 31;
    const int gid = lane >> 2, tg = lane & 3;
    const int quad = lane >> 3, lrow = lane & 7;
    const int arow = lrow + (quad & 1) * 8;
    const int acolb = (quad >> 1) * 16;
    const int krow = lrow + (quad >> 1) * 8;       /* trans-ldsm row within k */
    const int mcol = (quad & 1) * 8;               /* trans-ldsm m offset */
    const int ldr = tid >> 4;
    const int ldc = (tid & 15) * 4;
    const int mt = w >> 1;
    const int ntb = (w & 1) * 4;
    const int nt = w & 7, rh = w >> 3;
    const bool normw = (nt == rh);                 /* w in {0, 9}: different SMSPs */

    uint32_t wfh[4][4], wfl[4][4];
    {
        uint32_t obase = sb + QOFF_PH + (uint32_t)((mt * 16 + arow) * 144 + acolb);
#pragma unroll
        for (int kt = 0; kt < 4; ++kt) {
            ldsm_x4(wfh[kt][0], wfh[kt][1], wfh[kt][2], wfh[kt][3], obase + kt * 32);
            ldsm_x4(wfl[kt][0], wfl[kt][1], wfl[kt][2], wfl[kt][3],
                    obase + (QOFF_PL - QOFF_PH) + kt * 32);
        }
    }

    int cur_b = -1;
    float4 px[4];
    {
        int t = tb, b = t >> 6, r0 = (t & 63) * 128;
        const float4* qp = (const float4*)(query + ((size_t)b * TT + r0) * FF);
#pragma unroll
        for (int q = 0; q < 4; ++q) px[q] = qp[tid + q * 512];
    }

    for (int t = tb; t < te; ++t) {
        const int b = t >> 6;
        const int r0 = (t & 63) * 128;

        if (b != cur_b) {
            __syncthreads();   /* prior qkv-MMA done with B */
            const float* kvp = &g_kv[(size_t)b * TWOM * KVW];
            for (int i = tid; i < 128 * 64; i += 512) {
                int p = i >> 6, n = i & 63;
                float v0 = kvp[(2 * p) * KVW + n];
                float v1 = kvp[(2 * p + 1) * KVW + n];
                uint32_t hw = pack_hi(v0, v1);
                Bh[p * 72 + n] = hw;
                Bl[p * 72 + n] = pack_lo(v0, v1, hw);
            }
            for (int i = tid; i < 1024; i += 512) {   /* cols 64-71: 64 = kn */
                int p = i >> 3, n = 64 + (i & 7);
                uint32_t h = 0, l = 0;
                if (n == 64) {
                    float v0 = kvp[(2 * p) * KVW + 64];
                    float v1 = kvp[(2 * p + 1) * KVW + 64];
                    h = pack_hi(v0, v1); l = pack_lo(v0, v1, h);
                }
                Bh[p * 72 + n] = h;
                Bl[p * 72 + n] = l;
            }
            cur_b = b;
        }

        for (int sub = 0; sub < 2; ++sub) {
            __syncthreads();   /* phiT/Bx/ssq free */

            /* stage x packed hi/lo + ssq */
#pragma unroll
            for (int q = 0; q < 2; ++q) {
                int r = ldr + q * 32;
                float4 xv = px[2 * sub + q];
                int p0 = ldc >> 1;
                uint32_t h0 = pack_hi(xv.x, xv.y), h1 = pack_hi(xv.z, xv.w);
                BXh[p0 * 65 + r]       = h0;
                BXh[(p0 + 1) * 65 + r] = h1;
                BXl[p0 * 65 + r]       = pack_lo(xv.x, xv.y, h0);
                BXl[(p0 + 1) * 65 + r] = pack_lo(xv.z, xv.w, h1);
                float sq = xv.x * xv.x + xv.y * xv.y + xv.z * xv.z + xv.w * xv.w;
#pragma unroll
                for (int d = 1; d < 16; d <<= 1)
                    sq += __shfl_xor_sync(0xffffffffu, sq, d);
                if ((tid & 15) == 0) ssq_s[r] = 0.5f * sq;
            }
            if (sub == 1 && t + 1 < te) {
                int tn = t + 1, bn = tn >> 6, rn = (tn & 63) * 128;
                const float4* qp = (const float4*)(query + ((size_t)bn * TT + rn) * FF);
#pragma unroll
                for (int q = 0; q < 4; ++q) px[q] = qp[tid + q * 512];
            }
            __syncthreads();   /* Bx, ssq ready */

            /* phi-MMA + exp + phiT store */
#pragma unroll
            for (int nt4 = 0; nt4 < 4; ++nt4) {
                const int ntp = ntb + nt4;
                float wa[4] = {0.f, 0.f, 0.f, 0.f};
#pragma unroll
                for (int kt = 0; kt < 4; ++kt) {
                    int p0 = kt * 8 + tg, p1 = p0 + 4;
                    uint32_t bh0 = BXh[p0 * 65 + ntp * 8 + gid];
                    uint32_t bh1 = BXh[p1 * 65 + ntp * 8 + gid];
                    uint32_t bl0 = BXl[p0 * 65 + ntp * 8 + gid];
                    uint32_t bl1 = BXl[p1 * 65 + ntp * 8 + gid];
                    mma_bf16(wa, wfh[kt][0], wfh[kt][1], wfh[kt][2], wfh[kt][3], bh0, bh1);
                    mma_bf16(wa, wfl[kt][0], wfl[kt][1], wfl[kt][2], wfl[kt][3], bh0, bh1);
                    mma_bf16(wa, wfh[kt][0], wfh[kt][1], wfh[kt][2], wfh[kt][3], bl0, bl1);
                }
                const int rr = ntp * 8 + 2 * tg;
                const float sc0 = ssq_s[rr];
                const float sc1 = ssq_s[rr + 1];
#pragma unroll
                for (int half = 0; half < 2; ++half) {
                    int m = mt * 16 + gid + 8 * half;
                    float w0 = wa[2 * half], w1 = wa[2 * half + 1];
                    float e0 = (__expf(w0 - sc0) + EPSF) * SCALEF;
                    float e1 = (__expf(w1 - sc1) + EPSF) * SCALEF;
                    float g0 = (__expf(-w0 - sc0) + EPSF) * SCALEF;
                    float g1 = (__expf(-w1 - sc1) + EPSF) * SCALEF;
                    uint32_t he = pack_hi(e0, e1);
                    uint32_t hg = pack_hi(g0, g1);
                    *(uint32_t*)(smc + QOFF_PH + m * 144 + rr * 2)         = he;
                    *(uint32_t*)(smc + QOFF_PL + m * 144 + rr * 2)         = pack_lo(e0, e1, he);
                    *(uint32_t*)(smc + QOFF_PH + (m + 128) * 144 + rr * 2) = hg;
                    *(uint32_t*)(smc + QOFF_PL + (m + 128) * 144 + rr * 2) = pack_lo(g0, g1, hg);
                }
            }
            __syncthreads();   /* phiT ready */

            /* qkv-MMA: A from phiT via ldsm.trans; B = kv packed; K = 256 */
            float acc[2][4];
            float accN[2][4];
#pragma unroll
            for (int rt = 0; rt < 2; ++rt)
#pragma unroll
                for (int p = 0; p < 4; ++p) { acc[rt][p] = 0.f; accN[rt][p] = 0.f; }

#pragma unroll 2
            for (int kt = 0; kt < 16; ++kt) {
                const int p0 = kt * 8 + tg, p1 = p0 + 4;
                uint32_t bh0 = Bh[p0 * 72 + nt * 8 + gid];
                uint32_t bh1 = Bh[p1 * 72 + nt * 8 + gid];
                uint32_t bl0 = Bl[p0 * 72 + nt * 8 + gid];
                uint32_t bl1 = Bl[p1 * 72 + nt * 8 + gid];
#pragma unroll
                for (int rt = 0; rt < 2; ++rt) {
                    const int rbase = rh * 32 + rt * 16;
                    uint32_t aaddr = sb + QOFF_PH +
                        (uint32_t)((kt * 16 + krow) * 144 + (rbase + mcol) * 2);
                    uint32_t laddr = aaddr + (QOFF_PL - QOFF_PH);
                    uint32_t a0, a1, a2, a3, l0, l1, l2, l3;
                    ldsm_x4_t(a0, a1, a2, a3, aaddr);
                    ldsm_x4_t(l0, l1, l2, l3, laddr);
                    mma_bf16(acc[rt], a0, a1, a2, a3, bh0, bh1);
                    mma_bf16(acc[rt], l0, l1, l2, l3, bh0, bh1);
                    mma_bf16(acc[rt], a0, a1, a2, a3, bl0, bl1);
                    if (normw) {
                        uint32_t bn0 = Bh[p0 * 72 + 64 + gid];
                        uint32_t bn1 = Bh[p1 * 72 + 64 + gid];
                        uint32_t bm0 = Bl[p0 * 72 + 64 + gid];
                        uint32_t bm1 = Bl[p1 * 72 + 64 + gid];
                        mma_bf16(accN[rt], a0, a1, a2, a3, bn0, bn1);
                        mma_bf16(accN[rt], l0, l1, l2, l3, bn0, bn1);
                        mma_bf16(accN[rt], a0, a1, a2, a3, bm0, bm1);
                    }
                }
            }
            if (normw && tg == 0) {
#pragma unroll
                for (int rt = 0; rt < 2; ++rt) {
                    int rbase = rh * 32 + rt * 16;
                    ns_s[rbase + gid]     = accN[rt][0];
                    ns_s[rbase + gid + 8] = accN[rt][2];
                }
            }
            __syncthreads();   /* norm ready */

            /* epilogue */
#pragma unroll
            for (int rt = 0; rt < 2; ++rt) {
                int rbase = rh * 32 + rt * 16;
                int row0 = rbase + gid, row1 = row0 + 8;
                float inv0 = 1.0f / ns_s[row0];
                float inv1 = 1.0f / ns_s[row1];
                float* o0 = out + ((size_t)b * TT + r0 + sub * 64 + row0) * DD + nt * 8 + 2 * tg;
                float* o1 = out + ((size_t)b * TT + r0 + sub * 64 + row1) * DD + nt * 8 + 2 * tg;
                *(float2*)o0 = make_float2(acc[rt][0] * inv0, acc[rt][1] * inv0);
                *(float2*)o1 = make_float2(acc[rt][2] * inv1, acc[rt][3] * inv1);
            }
        }
    }
}

// ---------------------------------------------------------------------------

extern "C" void kernel_launch(void* const* d_in, const int* in_sizes, int n_in,
                              void* d_out, int out_size) {
    const float* query = (const float*)d_in[0];
    const float* value = (const float*)d_in[1];
    const float* key   = (const float*)d_in[2];
    const float* omega = (const float*)d_in[3];
    float* out = (float*)d_out;

    cudaFuncSetAttribute(kv_kernel, cudaFuncAttributeMaxDynamicSharedMemorySize, KV_SMEM);
    cudaFuncSetAttribute(qkv_kernel, cudaFuncAttributeMaxDynamicSharedMemorySize, QSMEM);

    kv_kernel<<<NBLK, 512, KV_SMEM>>>(key, value, omega);
    reduce_kernel<<<dim3((TWOM * KVW / 4 + 255) / 256, BB), 256>>>();
    qkv_kernel<<<QNB, 512, QSMEM>>>(query, omega, out);
}

// round 12
// speedup vs baseline: 1.8608x; 1.0018x over previous
#include <cuda_runtime.h>
#include <cuda_bf16.h>
#include <string.h>
#include <stdint.h>

#define BB 8
#define TT 8192
#define SN 8192
#define FF 64
#define DD 64
#define MMF 128
#define TWOM 256
#define EPSF 1e-9f
#define SCALEF 0.0625f   /* 1/sqrt(2*128) */
#define KVW 66           /* kv row stride: col 64 = normalizer, 65 pad */

/* kv config (round-9 proven) */
#define NBLK 148
#define NTILES 1024      /* 64-row tiles, 128 per batch */
#define VP 68

/* qkv config */
#define QTIL 512         /* 128-row t-tiles, 64 per batch */
#define QNB 148

__device__ float g_part[(size_t)NBLK * 2 * TWOM * KVW];
__device__ float g_kv[BB * TWOM * KVW];

static __device__ __forceinline__ uint32_t smem_u32(const void* p) {
    uint32_t a;
    asm("{ .reg .u64 t; cvta.to.shared.u64 t, %1; cvt.u32.u64 %0, t; }" : "=r"(a) : "l"(p));
    return a;
}
static __device__ __forceinline__ void ldsm_x4(uint32_t& r0, uint32_t& r1,
                                               uint32_t& r2, uint32_t& r3, uint32_t addr) {
    asm volatile("ldmatrix.sync.aligned.m8n8.x4.shared.b16 {%0,%1,%2,%3}, [%4];"
                 : "=r"(r0), "=r"(r1), "=r"(r2), "=r"(r3) : "r"(addr));
}
static __device__ __forceinline__ void ldsm_x4_t(uint32_t& r0, uint32_t& r1,
                                                 uint32_t& r2, uint32_t& r3, uint32_t addr) {
    asm volatile("ldmatrix.sync.aligned.m8n8.x4.trans.shared.b16 {%0,%1,%2,%3}, [%4];"
                 : "=r"(r0), "=r"(r1), "=r"(r2), "=r"(r3) : "r"(addr));
}
static __device__ __forceinline__ void mma_bf16(float* c,
                                                uint32_t a0, uint32_t a1, uint32_t a2, uint32_t a3,
                                                uint32_t b0, uint32_t b1) {
    asm volatile("mma.sync.aligned.m16n8k16.row.col.f32.bf16.bf16.f32 "
                 "{%0,%1,%2,%3}, {%4,%5,%6,%7}, {%8,%9}, {%0,%1,%2,%3};"
                 : "+f"(c[0]), "+f"(c[1]), "+f"(c[2]), "+f"(c[3])
                 : "r"(a0), "r"(a1), "r"(a2), "r"(a3), "r"(b0), "r"(b1));
}
static __device__ __forceinline__ uint32_t pack_hi(float e0, float e1) {
    __nv_bfloat162 hp;
    hp.x = __float2bfloat16_rn(e0); hp.y = __float2bfloat16_rn(e1);
    uint32_t u; memcpy(&u, &hp, 4); return u;
}
static __device__ __forceinline__ uint32_t pack_lo(float e0, float e1, uint32_t hi) {
    __nv_bfloat162 hp; memcpy(&hp, &hi, 4);
    __nv_bfloat162 lp;
    lp.x = __float2bfloat16_rn(e0 - __bfloat162float(hp.x));
    lp.y = __float2bfloat16_rn(e1 - __bfloat162float(hp.y));
    uint32_t u; memcpy(&u, &lp, 4); return u;
}

/* ---------------- kv smem layout (round-9 proven) ---------------- */
#define KOFF_WH 0
#define KOFF_WL 18432
#define KOFF_V  36864
#define KOFF_XH 54272
#define KOFF_XL 62592
#define KOFF_AH 70912
#define KOFF_AL 107776
#define KOFF_BH 144640
#define KOFF_BL 153856
#define KOFF_SQ 163072
#define KV_SMEM 163328

/* ---------------- qkv smem layout (bytes) ---------------- */
#define QOFF_PH 0          /* phiT hi [256][144B]; omega hi during init  36864 */
#define QOFF_PL 36864      /* phiT lo; omega lo during init              36864 */
#define QOFF_BH 73728      /* kv packed hi [128][72] u32                 36864 */
#define QOFF_BL 110592     /* kv packed lo                               36864 */
#define QOFF_XH 147456     /* x packed hi [32][65] u32                    8320 */
#define QOFF_XL 155776     /* x packed lo                                 8320 */
#define QOFF_SQ 164096     /* ssq [64]                                     256 */
#define QOFF_NS 164352     /* norm [64]                                    256 */
#define QOFF_NPB 164608    /* norm partials [8][66]                       2112 */
#define QSMEM   166720

// ---------------------------------------------------------------------------
// Kernel 1: fully tensorized kv (round-9 proven + audited barrier removal;
// accN restored to FULL 2-term — phi hi+lo vs exact ones column).
// ---------------------------------------------------------------------------
__global__ __launch_bounds__(512, 1)
void kv_kernel(const float* __restrict__ key,
               const float* __restrict__ value,
               const float* __restrict__ omega) {
    extern __shared__ char smc[];
    const uint32_t sb = smem_u32(smc);
    float* v_s    = (float*)(smc + KOFF_V);
    float* ssq_s  = (float*)(smc + KOFF_SQ);
    uint32_t* BXh = (uint32_t*)(smc + KOFF_XH);
    uint32_t* BXl = (uint32_t*)(smc + KOFF_XL);
    uint32_t* Bvh = (uint32_t*)(smc + KOFF_BH);
    uint32_t* Bvl = (uint32_t*)(smc + KOFF_BL);

    const int tid = threadIdx.x;
    const int blk = blockIdx.x;
    const int tb = (blk * NTILES) / NBLK;
    const int te = ((blk + 1) * NTILES) / NBLK;

    {
        const float4* om4 = (const float4*)omega;
#pragma unroll
        for (int q = 0; q < 4; ++q) {
            int idx = tid + q * 512;
            float4 v = om4[idx];
            int m = idx >> 4, f = (idx & 15) * 4;
            uint32_t h01 = pack_hi(v.x, v.y), h23 = pack_hi(v.z, v.w);
            uint32_t* wh = (uint32_t*)(smc + KOFF_WH + m * 144 + f * 2);
            uint32_t* wl = (uint32_t*)(smc + KOFF_WL + m * 144 + f * 2);
            wh[0] = h01; wh[1] = h23;
            wl[0] = pack_lo(v.x, v.y, h01); wl[1] = pack_lo(v.z, v.w, h23);
        }
    }
    if (tid < 256) {
        int p = tid >> 3, n = 64 + (tid & 7);
        Bvh[p * 72 + n] = (n == 64) ? 0x3F803F80u : 0u;
        Bvl[p * 72 + n] = 0u;
    }
    __syncthreads();

    const int w = tid >> 5, lane = tid & 31;
    const int gid = lane >> 2, tg = lane & 3;
    const int quad = lane >> 3, lrow = lane & 7;
    const int arow = lrow + (quad & 1) * 8;
    const int acolb = (quad >> 1) * 16;
    const int ldr = tid >> 4;
    const int ldc = (tid & 15) * 4;
    const int mt = w >> 1;
    const int ntb = (w & 1) * 4;
    const uint32_t aBase = sb + KOFF_AH + (uint32_t)((w * 16 + arow) * 144 + acolb);

    uint32_t wfh[4][4], wfl[4][4];
    {
        uint32_t obase = sb + KOFF_WH + (uint32_t)((mt * 16 + arow) * 144 + acolb);
#pragma unroll
        for (int kt = 0; kt < 4; ++kt) {
            ldsm_x4(wfh[kt][0], wfh[kt][1], wfh[kt][2], wfh[kt][3], obase + kt * 32);
            ldsm_x4(wfl[kt][0], wfl[kt][1], wfl[kt][2], wfl[kt][3],
                    obase + (KOFF_WL - KOFF_WH) + kt * 32);
        }
    }

    float acc[8][4];
#pragma unroll
    for (int nt = 0; nt < 8; ++nt)
#pragma unroll
        for (int p = 0; p < 4; ++p) acc[nt][p] = 0.f;
    float accN[4] = {0.f, 0.f, 0.f, 0.f};
    int seg = 0;

    float4 px[2], pv[2];
    {
        int t = tb, b = t >> 7, s0 = (t & 127) * 64;
        const float4* kp = (const float4*)(key   + ((size_t)b * SN + s0) * FF);
        const float4* vp = (const float4*)(value + ((size_t)b * SN + s0) * FF);
#pragma unroll
        for (int q = 0; q < 2; ++q) { px[q] = kp[tid + q * 512]; pv[q] = vp[tid + q * 512]; }
    }

    for (int t = tb; t < te; ++t) {
        /* no barrier: stage buffers' last readers precede prev A-ready barrier */
#pragma unroll
        for (int q = 0; q < 2; ++q) {
            int r = ldr + q * 32;
            float4 xv = px[q];
            int p0 = ldc >> 1;
            uint32_t h0 = pack_hi(xv.x, xv.y), h1 = pack_hi(xv.z, xv.w);
            BXh[p0 * 65 + r]       = h0;
            BXh[(p0 + 1) * 65 + r] = h1;
            BXl[p0 * 65 + r]       = pack_lo(xv.x, xv.y, h0);
            BXl[(p0 + 1) * 65 + r] = pack_lo(xv.z, xv.w, h1);
            *(float4*)&v_s[r * VP + ldc] = pv[q];
            float sq = xv.x * xv.x + xv.y * xv.y + xv.z * xv.z + xv.w * xv.w;
#pragma unroll
            for (int d = 1; d < 16; d <<= 1)
                sq += __shfl_xor_sync(0xffffffffu, sq, d);
            if ((tid & 15) == 0) ssq_s[r] = 0.5f * sq;
        }
        if (t + 1 < te) {
            int tn = t + 1, b = tn >> 7, s0 = (tn & 127) * 64;
            const float4* kp = (const float4*)(key   + ((size_t)b * SN + s0) * FF);
            const float4* vp = (const float4*)(value + ((size_t)b * SN + s0) * FF);
#pragma unroll
            for (int q = 0; q < 2; ++q) { px[q] = kp[tid + q * 512]; pv[q] = vp[tid + q * 512]; }
        }
        __syncthreads();   /* Bx, v, ssq ready; prev kv-MMA complete */

#pragma unroll
        for (int q = 0; q < 4; ++q) {
            int idx = tid + q * 512;
            int p = idx >> 6, n = idx & 63;
            float v0 = v_s[(2 * p) * VP + n];
            float v1 = v_s[(2 * p + 1) * VP + n];
            uint32_t hw = pack_hi(v0, v1);
            Bvh[p * 72 + n] = hw;
            Bvl[p * 72 + n] = pack_lo(v0, v1, hw);
        }

#pragma unroll
        for (int nt4 = 0; nt4 < 4; ++nt4) {
            const int nt = ntb + nt4;
            float wa[4] = {0.f, 0.f, 0.f, 0.f};
#pragma unroll
            for (int kt = 0; kt < 4; ++kt) {
                int p0 = kt * 8 + tg, p1 = p0 + 4;
                uint32_t bh0 = BXh[p0 * 65 + nt * 8 + gid];
                uint32_t bh1 = BXh[p1 * 65 + nt * 8 + gid];
                uint32_t bl0 = BXl[p0 * 65 + nt * 8 + gid];
                uint32_t bl1 = BXl[p1 * 65 + nt * 8 + gid];
                mma_bf16(wa, wfh[kt][0], wfh[kt][1], wfh[kt][2], wfh[kt][3], bh0, bh1);
                mma_bf16(wa, wfl[kt][0], wfl[kt][1], wfl[kt][2], wfl[kt][3], bh0, bh1);
                mma_bf16(wa, wfh[kt][0], wfh[kt][1], wfh[kt][2], wfh[kt][3], bl0, bl1);
            }
            const int r0 = nt * 8 + 2 * tg;
            const float sc0 = ssq_s[r0];
            const float sc1 = ssq_s[r0 + 1];
#pragma unroll
            for (int half = 0; half < 2; ++half) {
                int m = mt * 16 + gid + 8 * half;
                float w0 = wa[2 * half], w1 = wa[2 * half + 1];
                float e0 = (__expf(w0 - sc0) + EPSF) * SCALEF;
                float e1 = (__expf(w1 - sc1) + EPSF) * SCALEF;
                float g0 = (__expf(-w0 - sc0) + EPSF) * SCALEF;
                float g1 = (__expf(-w1 - sc1) + EPSF) * SCALEF;
                uint32_t he = pack_hi(e0, e1);
                uint32_t hg = pack_hi(g0, g1);
                *(uint32_t*)(smc + KOFF_AH + m * 144 + r0 * 2)         = he;
                *(uint32_t*)(smc + KOFF_AL + m * 144 + r0 * 2)         = pack_lo(e0, e1, he);
                *(uint32_t*)(smc + KOFF_AH + (m + 128) * 144 + r0 * 2) = hg;
                *(uint32_t*)(smc + KOFF_AL + (m + 128) * 144 + r0 * 2) = pack_lo(g0, g1, hg);
            }
        }
        __syncthreads();   /* A_phi, B_v ready */

#pragma unroll
        for (int kt = 0; kt < 4; ++kt) {
            uint32_t ah0, ah1, ah2, ah3, al0, al1, al2, al3;
            ldsm_x4(ah0, ah1, ah2, ah3, aBase + kt * 32);
            ldsm_x4(al0, al1, al2, al3, aBase + (KOFF_AL - KOFF_AH) + kt * 32);
            const int p0 = kt * 8 + tg, p1 = kt * 8 + tg + 4;
#pragma unroll
            for (int nt = 0; nt < 8; ++nt) {
                uint32_t bh0 = Bvh[p0 * 72 + nt * 8 + gid];
                uint32_t bh1 = Bvh[p1 * 72 + nt * 8 + gid];
                uint32_t bl0 = Bvl[p0 * 72 + nt * 8 + gid];
                uint32_t bl1 = Bvl[p1 * 72 + nt * 8 + gid];
                mma_bf16(acc[nt], ah0, ah1, ah2, ah3, bh0, bh1);
                mma_bf16(acc[nt], al0, al1, al2, al3, bh0, bh1);
                mma_bf16(acc[nt], ah0, ah1, ah2, ah3, bl0, bl1);
            }
            {   /* normalizer: FULL 2-term (phi hi + lo; ones column exact) */
                uint32_t bn0 = Bvh[p0 * 72 + 64 + gid];
                uint32_t bn1 = Bvh[p1 * 72 + 64 + gid];
                mma_bf16(accN, ah0, ah1, ah2, ah3, bn0, bn1);
                mma_bf16(accN, al0, al1, al2, al3, bn0, bn1);
            }
        }

        if (t + 1 == te || ((t + 1) >> 7) != (t >> 7)) {
            float* base = &g_part[(size_t)(blk * 2 + seg) * TWOM * KVW];
            const int f0 = w * 16 + gid;
#pragma unroll
            for (int nt = 0; nt < 8; ++nt) {
                int c = nt * 8 + 2 * tg;
                *(float2*)&base[f0 * KVW + c]       = make_float2(acc[nt][0], acc[nt][1]);
                *(float2*)&base[(f0 + 8) * KVW + c] = make_float2(acc[nt][2], acc[nt][3]);
            }
            if (tg == 0) {
                base[f0 * KVW + 64]       = accN[0];
                base[(f0 + 8) * KVW + 64] = accN[2];
            }
            ++seg;
#pragma unroll
            for (int nt = 0; nt < 8; ++nt)
#pragma unroll
                for (int p = 0; p < 4; ++p) acc[nt][p] = 0.f;
#pragma unroll
            for (int p = 0; p < 4; ++p) accN[p] = 0.f;
        }
    }
}

// ---------------------------------------------------------------------------
// Kernel 2: deterministic reduction (proven)
// ---------------------------------------------------------------------------
__global__ void reduce_kernel() {
    const int per_b4 = TWOM * KVW / 4;
    int idx = blockIdx.x * blockDim.x + threadIdx.x;
    int b = blockIdx.y;
    if (idx >= per_b4) return;
    float4 s = make_float4(0.f, 0.f, 0.f, 0.f);
    for (int i = 0; i < NBLK; ++i) {
        int tb = (i * NTILES) / NBLK;
        int te = ((i + 1) * NTILES) / NBLK;
        int b0 = tb >> 7;
        int bl = (te - 1) >> 7;
        int slot = (b0 == b) ? 0 : ((bl == b && bl != b0) ? 1 : -1);
        if (slot >= 0) {
            float4 v = ((const float4*)g_part)[(size_t)(i * 2 + slot) * per_b4 + idx];
            s.x += v.x; s.y += v.y; s.z += v.z; s.w += v.w;
        }
    }
    ((float4*)g_kv)[(size_t)b * per_b4 + idx] = s;
}

// ---------------------------------------------------------------------------
// Kernel 3: fully tensorized qkv. Balanced norm-MMA (each warp covers its
// kt slice {2nt, 2nt+1}) with FULL 3-term compensation restored.
// ---------------------------------------------------------------------------
__global__ __launch_bounds__(512, 1)
void qkv_kernel(const float* __restrict__ query,
                const float* __restrict__ omega,
                float* __restrict__ out) {
    extern __shared__ char smc[];
    const uint32_t sb = smem_u32(smc);
    float* ssq_s  = (float*)(smc + QOFF_SQ);
    float* ns_s   = (float*)(smc + QOFF_NS);
    float* npb_s  = (float*)(smc + QOFF_NPB);
    uint32_t* BXh = (uint32_t*)(smc + QOFF_XH);
    uint32_t* BXl = (uint32_t*)(smc + QOFF_XL);
    uint32_t* Bh  = (uint32_t*)(smc + QOFF_BH);
    uint32_t* Bl  = (uint32_t*)(smc + QOFF_BL);

    const int tid = threadIdx.x;
    const int blk = blockIdx.x;
    const int tb = (blk * QTIL) / QNB;
    const int te = ((blk + 1) * QTIL) / QNB;

    {
        const float4* om4 = (const float4*)omega;
#pragma unroll
        for (int q = 0; q < 4; ++q) {
            int idx = tid + q * 512;
            float4 v = om4[idx];
            int m = idx >> 4, f = (idx & 15) * 4;
            uint32_t h01 = pack_hi(v.x, v.y), h23 = pack_hi(v.z, v.w);
            uint32_t* wh = (uint32_t*)(smc + QOFF_PH + m * 144 + f * 2);
            uint32_t* wl = (uint32_t*)(smc + QOFF_PL + m * 144 + f * 2);
            wh[0] = h01; wh[1] = h23;
            wl[0] = pack_lo(v.x, v.y, h01); wl[1] = pack_lo(v.z, v.w, h23);
        }
    }
    __syncthreads();

    const int w = tid >> 5, lane = tid & 31;
    const int gid = lane >> 2, tg = lane & 3;
    const int quad = lane >> 3, lrow = lane & 7;
    const int arow = lrow + (quad & 1) * 8;
    const int acolb = (quad >> 1) * 16;
    const int krow = lrow + (quad >> 1) * 8;
    const int mcol = (quad & 1) * 8;
    const int ldr = tid >> 4;
    const int ldc = (tid & 15) * 4;
    const int mt = w >> 1;
    const int ntb = (w & 1) * 4;
    const int nt = w & 7, rh = w >> 3;

    uint32_t wfh[4][4], wfl[4][4];
    {
        uint32_t obase = sb + QOFF_PH + (uint32_t)((mt * 16 + arow) * 144 + acolb);
#pragma unroll
        for (int kt = 0; kt < 4; ++kt) {
            ldsm_x4(wfh[kt][0], wfh[kt][1], wfh[kt][2], wfh[kt][3], obase + kt * 32);
            ldsm_x4(wfl[kt][0], wfl[kt][1], wfl[kt][2], wfl[kt][3],
                    obase + (QOFF_PL - QOFF_PH) + kt * 32);
        }
    }

    int cur_b = -1;
    float4 px[4];
    {
        int t = tb, b = t >> 6, r0 = (t & 63) * 128;
        const float4* qp = (const float4*)(query + ((size_t)b * TT + r0) * FF);
#pragma unroll
        for (int q = 0; q < 4; ++q) px[q] = qp[tid + q * 512];
    }

    for (int t = tb; t < te; ++t) {
        const int b = t >> 6;
        const int r0 = (t & 63) * 128;

        if (b != cur_b) {
            /* no barrier: prior qkv-MMA reads precede prev partials barrier */
            const float* kvp = &g_kv[(size_t)b * TWOM * KVW];
            for (int i = tid; i < 128 * 64; i += 512) {
                int p = i >> 6, n = i & 63;
                float v0 = kvp[(2 * p) * KVW + n];
                float v1 = kvp[(2 * p + 1) * KVW + n];
                uint32_t hw = pack_hi(v0, v1);
                Bh[p * 72 + n] = hw;
                Bl[p * 72 + n] = pack_lo(v0, v1, hw);
            }
            for (int i = tid; i < 1024; i += 512) {
                int p = i >> 3, n = 64 + (i & 7);
                uint32_t h = 0, l = 0;
                if (n == 64) {
                    float v0 = kvp[(2 * p) * KVW + 64];
                    float v1 = kvp[(2 * p + 1) * KVW + 64];
                    h = pack_hi(v0, v1); l = pack_lo(v0, v1, h);
                }
                Bh[p * 72 + n] = h;
                Bl[p * 72 + n] = l;
            }
            cur_b = b;
        }

        for (int sub = 0; sub < 2; ++sub) {
            /* no top barrier — stage readers precede prev phiT-ready barrier */
#pragma unroll
            for (int q = 0; q < 2; ++q) {
                int r = ldr + q * 32;
                float4 xv = px[2 * sub + q];
                int p0 = ldc >> 1;
                uint32_t h0 = pack_hi(xv.x, xv.y), h1 = pack_hi(xv.z, xv.w);
                BXh[p0 * 65 + r]       = h0;
                BXh[(p0 + 1) * 65 + r] = h1;
                BXl[p0 * 65 + r]       = pack_lo(xv.x, xv.y, h0);
                BXl[(p0 + 1) * 65 + r] = pack_lo(xv.z, xv.w, h1);
                float sq = xv.x * xv.x + xv.y * xv.y + xv.z * xv.z + xv.w * xv.w;
#pragma unroll
                for (int d = 1; d < 16; d <<= 1)
                    sq += __shfl_xor_sync(0xffffffffu, sq, d);
                if ((tid & 15) == 0) ssq_s[r] = 0.5f * sq;
            }
            if (sub == 1 && t + 1 < te) {
                int tn = t + 1, bn = tn >> 6, rn = (tn & 63) * 128;
                const float4* qp = (const float4*)(query + ((size_t)bn * TT + rn) * FF);
#pragma unroll
                for (int q = 0; q < 4; ++q) px[q] = qp[tid + q * 512];
            }
            __syncthreads();   /* Bx, ssq (and B after rebuild) ready */

            /* phi-MMA + exp + phiT store */
#pragma unroll
            for (int nt4 = 0; nt4 < 4; ++nt4) {
                const int ntp = ntb + nt4;
                float wa[4] = {0.f, 0.f, 0.f, 0.f};
#pragma unroll
                for (int kt = 0; kt < 4; ++kt) {
                    int p0 = kt * 8 + tg, p1 = p0 + 4;
                    uint32_t bh0 = BXh[p0 * 65 + ntp * 8 + gid];
                    uint32_t bh1 = BXh[p1 * 65 + ntp * 8 + gid];
                    uint32_t bl0 = BXl[p0 * 65 + ntp * 8 + gid];
                    uint32_t bl1 = BXl[p1 * 65 + ntp * 8 + gid];
                    mma_bf16(wa, wfh[kt][0], wfh[kt][1], wfh[kt][2], wfh[kt][3], bh0, bh1);
                    mma_bf16(wa, wfl[kt][0], wfl[kt][1], wfl[kt][2], wfl[kt][3], bh0, bh1);
                    mma_bf16(wa, wfh[kt][0], wfh[kt][1], wfh[kt][2], wfh[kt][3], bl0, bl1);
                }
                const int rr = ntp * 8 + 2 * tg;
                const float sc0 = ssq_s[rr];
                const float sc1 = ssq_s[rr + 1];
#pragma unroll
                for (int half = 0; half < 2; ++half) {
                    int m = mt * 16 + gid + 8 * half;
                    float w0 = wa[2 * half], w1 = wa[2 * half + 1];
                    float e0 = (__expf(w0 - sc0) + EPSF) * SCALEF;
                    float e1 = (__expf(w1 - sc1) + EPSF) * SCALEF;
                    float g0 = (__expf(-w0 - sc0) + EPSF) * SCALEF;
                    float g1 = (__expf(-w1 - sc1) + EPSF) * SCALEF;
                    uint32_t he = pack_hi(e0, e1);
                    uint32_t hg = pack_hi(g0, g1);
                    *(uint32_t*)(smc + QOFF_PH + m * 144 + rr * 2)         = he;
                    *(uint32_t*)(smc + QOFF_PL + m * 144 + rr * 2)         = pack_lo(e0, e1, he);
                    *(uint32_t*)(smc + QOFF_PH + (m + 128) * 144 + rr * 2) = hg;
                    *(uint32_t*)(smc + QOFF_PL + (m + 128) * 144 + rr * 2) = pack_lo(g0, g1, hg);
                }
            }
            __syncthreads();   /* phiT ready */

            /* qkv-MMA; balanced FULL 3-term norm on kt = 2nt, 2nt+1 */
            float acc[2][4];
            float accN[2][4];
#pragma unroll
            for (int rt = 0; rt < 2; ++rt)
#pragma unroll
                for (int p = 0; p < 4; ++p) { acc[rt][p] = 0.f; accN[rt][p] = 0.f; }

#pragma unroll
            for (int kt = 0; kt < 16; ++kt) {
                const int p0 = kt * 8 + tg, p1 = p0 + 4;
                uint32_t bh0 = Bh[p0 * 72 + nt * 8 + gid];
                uint32_t bh1 = Bh[p1 * 72 + nt * 8 + gid];
                uint32_t bl0 = Bl[p0 * 72 + nt * 8 + gid];
                uint32_t bl1 = Bl[p1 * 72 + nt * 8 + gid];
#pragma unroll
                for (int rt = 0; rt < 2; ++rt) {
                    const int rbase = rh * 32 + rt * 16;
                    uint32_t aaddr = sb + QOFF_PH +
                        (uint32_t)((kt * 16 + krow) * 144 + (rbase + mcol) * 2);
                    uint32_t laddr = aaddr + (QOFF_PL - QOFF_PH);
                    uint32_t a0, a1, a2, a3, l0, l1, l2, l3;
                    ldsm_x4_t(a0, a1, a2, a3, aaddr);
                    ldsm_x4_t(l0, l1, l2, l3, laddr);
                    mma_bf16(acc[rt], a0, a1, a2, a3, bh0, bh1);
                    mma_bf16(acc[rt], l0, l1, l2, l3, bh0, bh1);
                    mma_bf16(acc[rt], a0, a1, a2, a3, bl0, bl1);
                    if ((kt >> 1) == nt) {   /* compile-time after unroll */
                        uint32_t bn0 = Bh[p0 * 72 + 64 + gid];
                        uint32_t bn1 = Bh[p1 * 72 + 64 + gid];
                        uint32_t bm0 = Bl[p0 * 72 + 64 + gid];
                        uint32_t bm1 = Bl[p1 * 72 + 64 + gid];
                        mma_bf16(accN[rt], a0, a1, a2, a3, bn0, bn1);
                        mma_bf16(accN[rt], l0, l1, l2, l3, bn0, bn1);
                        mma_bf16(accN[rt], a0, a1, a2, a3, bm0, bm1);
                    }
                }
            }
            if (tg == 0) {
#pragma unroll
                for (int rt = 0; rt < 2; ++rt) {
                    int rbase = rh * 32 + rt * 16;
                    npb_s[nt * 66 + rbase + gid]     = accN[rt][0];
                    npb_s[nt * 66 + rbase + gid + 8] = accN[rt][2];
                }
            }
            __syncthreads();   /* partials ready */
            if (tid < 64) {
                float s = 0.f;
#pragma unroll
                for (int j = 0; j < 8; ++j) s += npb_s[j * 66 + tid];
                ns_s[tid] = s;
            }
            __syncthreads();   /* norm ready */

            /* epilogue */
#pragma unroll
            for (int rt = 0; rt < 2; ++rt) {
                int rbase = rh * 32 + rt * 16;
                int row0 = rbase + gid, row1 = row0 + 8;
                float inv0 = 1.0f / ns_s[row0];
                float inv1 = 1.0f / ns_s[row1];
                float* o0 = out + ((size_t)b * TT + r0 + sub * 64 + row0) * DD + nt * 8 + 2 * tg;
                float* o1 = out + ((size_t)b * TT + r0 + sub * 64 + row1) * DD + nt * 8 + 2 * tg;
                *(float2*)o0 = make_float2(acc[rt][0] * inv0, acc[rt][1] * inv0);
                *(float2*)o1 = make_float2(acc[rt][2] * inv1, acc[rt][3] * inv1);
            }
        }
    }
}

// ---------------------------------------------------------------------------

extern "C" void kernel_launch(void* const* d_in, const int* in_sizes, int n_in,
                              void* d_out, int out_size) {
    const float* query = (const float*)d_in[0];
    const float* value = (const float*)d_in[1];
    const float* key   = (const float*)d_in[2];
    const float* omega = (const float*)d_in[3];
    float* out = (float*)d_out;

    cudaFuncSetAttribute(kv_kernel, cudaFuncAttributeMaxDynamicSharedMemorySize, KV_SMEM);
    cudaFuncSetAttribute(qkv_kernel, cudaFuncAttributeMaxDynamicSharedMemorySize, QSMEM);

    kv_kernel<<<NBLK, 512, KV_SMEM>>>(key, value, omega);
    reduce_kernel<<<dim3((TWOM * KVW / 4 + 255) / 256, BB), 256>>>();
    qkv_kernel<<<QNB, 512, QSMEM>>>(query, omega, out);
}

// round 13
// speedup vs baseline: 2.0802x; 1.1179x over previous
#include <cuda_runtime.h>
#include <cuda_bf16.h>
#include <string.h>
#include <stdint.h>

#define BB 8
#define TT 8192
#define SN 8192
#define FF 64
#define DD 64
#define MMF 128
#define TWOM 256
#define EPSF 1e-9f
#define SCALEF 0.0625f   /* 1/sqrt(2*128) */
#define KVW 66           /* g_kv row stride: col 64 = normalizer, 65 pad */

#define NBLK 148
#define NTILES 1024      /* 64-row tiles, 128 per batch */
#define QTIL 512         /* 128-row t-tiles, 64 per batch */
#define QNB 148

__device__ float g_part[(size_t)NBLK * 2 * TWOM * KVW];
__device__ float g_kv[BB * TWOM * KVW];

static __device__ __forceinline__ uint32_t smem_u32(const void* p) {
    uint32_t a;
    asm("{ .reg .u64 t; cvta.to.shared.u64 t, %1; cvt.u32.u64 %0, t; }" : "=r"(a) : "l"(p));
    return a;
}
static __device__ __forceinline__ void ldsm_x4(uint32_t& r0, uint32_t& r1,
                                               uint32_t& r2, uint32_t& r3, uint32_t addr) {
    asm volatile("ldmatrix.sync.aligned.m8n8.x4.shared.b16 {%0,%1,%2,%3}, [%4];"
                 : "=r"(r0), "=r"(r1), "=r"(r2), "=r"(r3) : "r"(addr));
}
static __device__ __forceinline__ void ldsm_x4_t(uint32_t& r0, uint32_t& r1,
                                                 uint32_t& r2, uint32_t& r3, uint32_t addr) {
    asm volatile("ldmatrix.sync.aligned.m8n8.x4.trans.shared.b16 {%0,%1,%2,%3}, [%4];"
                 : "=r"(r0), "=r"(r1), "=r"(r2), "=r"(r3) : "r"(addr));
}
static __device__ __forceinline__ void mma_bf16(float* c,
                                                uint32_t a0, uint32_t a1, uint32_t a2, uint32_t a3,
                                                uint32_t b0, uint32_t b1) {
    asm volatile("mma.sync.aligned.m16n8k16.row.col.f32.bf16.bf16.f32 "
                 "{%0,%1,%2,%3}, {%4,%5,%6,%7}, {%8,%9}, {%0,%1,%2,%3};"
                 : "+f"(c[0]), "+f"(c[1]), "+f"(c[2]), "+f"(c[3])
                 : "r"(a0), "r"(a1), "r"(a2), "r"(a3), "r"(b0), "r"(b1));
}
static __device__ __forceinline__ uint32_t pack_hi(float e0, float e1) {
    __nv_bfloat162 hp;
    hp.x = __float2bfloat16_rn(e0); hp.y = __float2bfloat16_rn(e1);
    uint32_t u; memcpy(&u, &hp, 4); return u;
}
static __device__ __forceinline__ uint32_t pack_lo(float e0, float e1, uint32_t hi) {
    __nv_bfloat162 hp; memcpy(&hp, &hi, 4);
    __nv_bfloat162 lp;
    lp.x = __float2bfloat16_rn(e0 - __bfloat162float(hp.x));
    lp.y = __float2bfloat16_rn(e1 - __bfloat162float(hp.y));
    uint32_t u; memcpy(&u, &lp, 4); return u;
}

/* ---------- kv smem (bytes). XT/BT: transposed packed hi/lo, stride 68 words ---------- */
#define KOFF_AH 0          /* phi hi [256][144B]; omega hi at init */
#define KOFF_AL 36864      /* phi lo; omega lo at init */
#define KOFF_V  73728      /* v fp32 [64][68]    17408 */
#define KOFF_XT 91136      /* x  BT [64][68w]    17408 */
#define KOFF_BT 108544     /* v  BT [64][68w]    17408 */
#define KOFF_SQ 125952     /* ssq [64]             256 */
#define KV_SMEM 126208

/* ---------- qkv smem (bytes). BT stride 260 words (K=256) ---------- */
#define QOFF_PH 0          /* phiT hi [256][144B]; omega hi at init */
#define QOFF_PL 36864
#define QOFF_BT 73728      /* kv BT [72][260w]   74880 */
#define QOFF_XT 148608     /* x  BT [64][68w]    17408 */
#define QOFF_SQ 166016
#define QOFF_NS 166272
#define QOFF_NPB 166528    /* norm partials [8][66]  2112 */
#define QSMEM   168640

// ---------------------------------------------------------------------------
// Kernel 1: fully tensorized kv, B fragments via ldmatrix.x4 on transposed
// packed layouts; norm B is a constant fragment (ones column).
// ---------------------------------------------------------------------------
__global__ __launch_bounds__(512, 1)
void kv_kernel(const float* __restrict__ key,
               const float* __restrict__ value,
               const float* __restrict__ omega) {
    extern __shared__ char smc[];
    const uint32_t sb = smem_u32(smc);
    float* v_s    = (float*)(smc + KOFF_V);
    float* ssq_s  = (float*)(smc + KOFF_SQ);
    uint32_t* BT  = (uint32_t*)(smc + KOFF_BT);

    const int tid = threadIdx.x;
    const int blk = blockIdx.x;
    const int tb = (blk * NTILES) / NBLK;
    const int te = ((blk + 1) * NTILES) / NBLK;

    /* omega -> bf16 hi/lo into A region ([m][f], 144B stride) */
    {
        const float4* om4 = (const float4*)omega;
#pragma unroll
        for (int q = 0; q < 4; ++q) {
            int idx = tid + q * 512;
            float4 v = om4[idx];
            int m = idx >> 4, f = (idx & 15) * 4;
            uint32_t h01 = pack_hi(v.x, v.y), h23 = pack_hi(v.z, v.w);
            uint32_t* wh = (uint32_t*)(smc + KOFF_AH + m * 144 + f * 2);
            uint32_t* wl = (uint32_t*)(smc + KOFF_AL + m * 144 + f * 2);
            wh[0] = h01; wh[1] = h23;
            wl[0] = pack_lo(v.x, v.y, h01); wl[1] = pack_lo(v.z, v.w, h23);
        }
    }
    __syncthreads();

    const int w = tid >> 5, lane = tid & 31;
    const int gid = lane >> 2, tg = lane & 3;
    const int quad = lane >> 3, lrow = lane & 7;
    const int arow = lrow + (quad & 1) * 8;
    const int acolb = (quad >> 1) * 16;
    const int ldr = tid >> 4;
    const int ldc = (tid & 15) * 4;
    const int mt = w >> 1;
    const int ntb = (w & 1) * 4;
    const uint32_t aBase = sb + KOFF_AH + (uint32_t)((w * 16 + arow) * 144 + acolb);
    /* ldmatrix.x4 lane offset for stride-68 (272B) hi/lo buffers */
    const uint32_t xq_lane = (uint32_t)((lane & 7) * 272 + ((lane >> 3) & 1) * 16 + (lane >> 4) * 128);
    const uint32_t xtB = sb + KOFF_XT + xq_lane;
    const uint32_t btB = sb + KOFF_BT + xq_lane;
    /* constant ones-column B fragment */
    const uint32_t bnc = (gid == 0) ? 0x3F803F80u : 0u;

    /* hoist omega A fragments */
    uint32_t wfh[4][4], wfl[4][4];
    {
        uint32_t obase = sb + KOFF_AH + (uint32_t)((mt * 16 + arow) * 144 + acolb);
#pragma unroll
        for (int kt = 0; kt < 4; ++kt) {
            ldsm_x4(wfh[kt][0], wfh[kt][1], wfh[kt][2], wfh[kt][3], obase + kt * 32);
            ldsm_x4(wfl[kt][0], wfl[kt][1], wfl[kt][2], wfl[kt][3],
                    obase + (KOFF_AL - KOFF_AH) + kt * 32);
        }
    }

    float acc[8][4];
#pragma unroll
    for (int nt = 0; nt < 8; ++nt)
#pragma unroll
        for (int p = 0; p < 4; ++p) acc[nt][p] = 0.f;
    float accN[4] = {0.f, 0.f, 0.f, 0.f};
    int seg = 0;

    float4 px[2], pv[2];
    {
        int t = tb, b = t >> 7, s0 = (t & 127) * 64;
        const float4* kp = (const float4*)(key   + ((size_t)b * SN + s0) * FF);
        const float4* vp = (const float4*)(value + ((size_t)b * SN + s0) * FF);
#pragma unroll
        for (int q = 0; q < 2; ++q) { px[q] = kp[tid + q * 512]; pv[q] = vp[tid + q * 512]; }
    }

    for (int t = tb; t < te; ++t) {
        /* no barrier: stage buffers' last readers precede prev A-ready barrier */
#pragma unroll
        for (int q = 0; q < 2; ++q) {
            int r = ldr + q * 32;
            float4 xv = px[q];
            int p0 = (tid & 15) * 2;
            uint32_t h0 = pack_hi(xv.x, xv.y), h1 = pack_hi(xv.z, xv.w);
            uint32_t l0 = pack_lo(xv.x, xv.y, h0), l1 = pack_lo(xv.z, xv.w, h1);
            *(uint2*)(smc + KOFF_XT + (size_t)(r * 68 + p0) * 4)      = make_uint2(h0, h1);
            *(uint2*)(smc + KOFF_XT + (size_t)(r * 68 + 32 + p0) * 4) = make_uint2(l0, l1);
            *(float4*)&v_s[r * 68 + ldc] = pv[q];
            float sq = xv.x * xv.x + xv.y * xv.y + xv.z * xv.z + xv.w * xv.w;
#pragma unroll
            for (int d = 1; d < 16; d <<= 1)
                sq += __shfl_xor_sync(0xffffffffu, sq, d);
            if ((tid & 15) == 0) ssq_s[r] = 0.5f * sq;
        }
        if (t + 1 < te) {
            int tn = t + 1, b = tn >> 7, s0 = (tn & 127) * 64;
            const float4* kp = (const float4*)(key   + ((size_t)b * SN + s0) * FF);
            const float4* vp = (const float4*)(value + ((size_t)b * SN + s0) * FF);
#pragma unroll
            for (int q = 0; q < 2; ++q) { px[q] = kp[tid + q * 512]; pv[q] = vp[tid + q * 512]; }
        }
        __syncthreads();   /* XT, v, ssq ready; prev kv-MMA complete */

        /* pack v -> BT[n][p] hi / [n][32+p] lo */
#pragma unroll
        for (int q = 0; q < 4; ++q) {
            int idx = tid + q * 512;
            int p = idx >> 6, n = idx & 63;
            float v0 = v_s[(2 * p) * 68 + n];
            float v1 = v_s[(2 * p + 1) * 68 + n];
            uint32_t hw = pack_hi(v0, v1);
            BT[n * 68 + p]      = hw;
            BT[n * 68 + 32 + p] = pack_lo(v0, v1, hw);
        }

        /* phi-MMA + exp + store */
#pragma unroll
        for (int nt4 = 0; nt4 < 4; ++nt4) {
            const int nt = ntb + nt4;
            float wa[4] = {0.f, 0.f, 0.f, 0.f};
#pragma unroll
            for (int kt = 0; kt < 4; ++kt) {
                uint32_t bh0, bh1, bl0, bl1;
                ldsm_x4(bh0, bh1, bl0, bl1, xtB + nt * 2176 + kt * 32);
                mma_bf16(wa, wfh[kt][0], wfh[kt][1], wfh[kt][2], wfh[kt][3], bh0, bh1);
                mma_bf16(wa, wfl[kt][0], wfl[kt][1], wfl[kt][2], wfl[kt][3], bh0, bh1);
                mma_bf16(wa, wfh[kt][0], wfh[kt][1], wfh[kt][2], wfh[kt][3], bl0, bl1);
            }
            const int r0 = nt * 8 + 2 * tg;
            const float sc0 = ssq_s[r0];
            const float sc1 = ssq_s[r0 + 1];
#pragma unroll
            for (int half = 0; half < 2; ++half) {
                int m = mt * 16 + gid + 8 * half;
                float w0 = wa[2 * half], w1 = wa[2 * half + 1];
                float e0 = (__expf(w0 - sc0) + EPSF) * SCALEF;
                float e1 = (__expf(w1 - sc1) + EPSF) * SCALEF;
                float g0 = (__expf(-w0 - sc0) + EPSF) * SCALEF;
                float g1 = (__expf(-w1 - sc1) + EPSF) * SCALEF;
                uint32_t he = pack_hi(e0, e1);
                uint32_t hg = pack_hi(g0, g1);
                *(uint32_t*)(smc + KOFF_AH + m * 144 + r0 * 2)         = he;
                *(uint32_t*)(smc + KOFF_AL + m * 144 + r0 * 2)         = pack_lo(e0, e1, he);
                *(uint32_t*)(smc + KOFF_AH + (m + 128) * 144 + r0 * 2) = hg;
                *(uint32_t*)(smc + KOFF_AL + (m + 128) * 144 + r0 * 2) = pack_lo(g0, g1, hg);
            }
        }
        __syncthreads();   /* A_phi, BT ready */

        /* kv-MMA: D[16 features per warp][64 + norm] */
#pragma unroll
        for (int kt = 0; kt < 4; ++kt) {
            uint32_t ah0, ah1, ah2, ah3, al0, al1, al2, al3;
            ldsm_x4(ah0, ah1, ah2, ah3, aBase + kt * 32);
            ldsm_x4(al0, al1, al2, al3, aBase + (KOFF_AL - KOFF_AH) + kt * 32);
#pragma unroll
            for (int nt = 0; nt < 8; ++nt) {
                uint32_t bh0, bh1, bl0, bl1;
                ldsm_x4(bh0, bh1, bl0, bl1, btB + nt * 2176 + kt * 32);
                mma_bf16(acc[nt], ah0, ah1, ah2, ah3, bh0, bh1);
                mma_bf16(acc[nt], al0, al1, al2, al3, bh0, bh1);
                mma_bf16(acc[nt], ah0, ah1, ah2, ah3, bl0, bl1);
            }
            /* normalizer: constant ones fragment, full 2-term */
            mma_bf16(accN, ah0, ah1, ah2, ah3, bnc, bnc);
            mma_bf16(accN, al0, al1, al2, al3, bnc, bnc);
        }

        if (t + 1 == te || ((t + 1) >> 7) != (t >> 7)) {
            float* base = &g_part[(size_t)(blk * 2 + seg) * TWOM * KVW];
            const int f0 = w * 16 + gid;
#pragma unroll
            for (int nt = 0; nt < 8; ++nt) {
                int c = nt * 8 + 2 * tg;
                *(float2*)&base[f0 * KVW + c]       = make_float2(acc[nt][0], acc[nt][1]);
                *(float2*)&base[(f0 + 8) * KVW + c] = make_float2(acc[nt][2], acc[nt][3]);
            }
            if (tg == 0) {
                base[f0 * KVW + 64]       = accN[0];
                base[(f0 + 8) * KVW + 64] = accN[2];
            }
            ++seg;
#pragma unroll
            for (int nt = 0; nt < 8; ++nt)
#pragma unroll
                for (int p = 0; p < 4; ++p) acc[nt][p] = 0.f;
#pragma unroll
            for (int p = 0; p < 4; ++p) accN[p] = 0.f;
        }
    }
}

// ---------------------------------------------------------------------------
// Kernel 2: deterministic reduction (proven)
// ---------------------------------------------------------------------------
__global__ void reduce_kernel() {
    const int per_b4 = TWOM * KVW / 4;
    int idx = blockIdx.x * blockDim.x + threadIdx.x;
    int b = blockIdx.y;
    if (idx >= per_b4) return;
    float4 s = make_float4(0.f, 0.f, 0.f, 0.f);
    for (int i = 0; i < NBLK; ++i) {
        int tb = (i * NTILES) / NBLK;
        int te = ((i + 1) * NTILES) / NBLK;
        int b0 = tb >> 7;
        int bl = (te - 1) >> 7;
        int slot = (b0 == b) ? 0 : ((bl == b && bl != b0) ? 1 : -1);
        if (slot >= 0) {
            float4 v = ((const float4*)g_part)[(size_t)(i * 2 + slot) * per_b4 + idx];
            s.x += v.x; s.y += v.y; s.z += v.z; s.w += v.w;
        }
    }
    ((float4*)g_kv)[(size_t)b * per_b4 + idx] = s;
}

// ---------------------------------------------------------------------------
// Kernel 3: fully tensorized qkv; all B fragments via ldmatrix.x4 on
// transposed packed layouts (x stride-68; kv stride-260 incl. norm row 64).
// ---------------------------------------------------------------------------
__global__ __launch_bounds__(512, 1)
void qkv_kernel(const float* __restrict__ query,
                const float* __restrict__ omega,
                float* __restrict__ out) {
    extern __shared__ char smc[];
    const uint32_t sb = smem_u32(smc);
    float* ssq_s  = (float*)(smc + QOFF_SQ);
    float* ns_s   = (float*)(smc + QOFF_NS);
    float* npb_s  = (float*)(smc + QOFF_NPB);
    uint32_t* BT  = (uint32_t*)(smc + QOFF_BT);

    const int tid = threadIdx.x;
    const int blk = blockIdx.x;
    const int tb = (blk * QTIL) / QNB;
    const int te = ((blk + 1) * QTIL) / QNB;

    {
        const float4* om4 = (const float4*)omega;
#pragma unroll
        for (int q = 0; q < 4; ++q) {
            int idx = tid + q * 512;
            float4 v = om4[idx];
            int m = idx >> 4, f = (idx & 15) * 4;
            uint32_t h01 = pack_hi(v.x, v.y), h23 = pack_hi(v.z, v.w);
            uint32_t* wh = (uint32_t*)(smc + QOFF_PH + m * 144 + f * 2);
            uint32_t* wl = (uint32_t*)(smc + QOFF_PL + m * 144 + f * 2);
            wh[0] = h01; wh[1] = h23;
            wl[0] = pack_lo(v.x, v.y, h01); wl[1] = pack_lo(v.z, v.w, h23);
        }
    }
    __syncthreads();

    const int w = tid >> 5, lane = tid & 31;
    const int gid = lane >> 2, tg = lane & 3;
    const int quad = lane >> 3, lrow = lane & 7;
    const int arow = lrow + (quad & 1) * 8;
    const int acolb = (quad >> 1) * 16;
    const int krow = lrow + (quad >> 1) * 8;
    const int mcol = (quad & 1) * 8;
    const int ldr = tid >> 4;
    const int mt = w >> 1;
    const int ntb = (w & 1) * 4;
    const int nt = w & 7, rh = w >> 3;
    const uint32_t xq_lane = (uint32_t)((lane & 7) * 272 + ((lane >> 3) & 1) * 16 + (lane >> 4) * 128);
    const uint32_t bq_lane = (uint32_t)((lane & 7) * 1040 + ((lane >> 3) & 1) * 16 + (lane >> 4) * 512);
    const uint32_t xtB = sb + QOFF_XT + xq_lane;
    const uint32_t btB = sb + QOFF_BT + bq_lane;

    uint32_t wfh[4][4], wfl[4][4];
    {
        uint32_t obase = sb + QOFF_PH + (uint32_t)((mt * 16 + arow) * 144 + acolb);
#pragma unroll
        for (int kt = 0; kt < 4; ++kt) {
            ldsm_x4(wfh[kt][0], wfh[kt][1], wfh[kt][2], wfh[kt][3], obase + kt * 32);
            ldsm_x4(wfl[kt][0], wfl[kt][1], wfl[kt][2], wfl[kt][3],
                    obase + (QOFF_PL - QOFF_PH) + kt * 32);
        }
    }

    int cur_b = -1;
    float4 px[4];
    {
        int t = tb, b = t >> 6, r0 = (t & 63) * 128;
        const float4* qp = (const float4*)(query + ((size_t)b * TT + r0) * FF);
#pragma unroll
        for (int q = 0; q < 4; ++q) px[q] = qp[tid + q * 512];
    }

    for (int t = tb; t < te; ++t) {
        const int b = t >> 6;
        const int r0 = (t & 63) * 128;

        if (b != cur_b) {
            /* rebuild BT: rows 0-63 = kv cols, row 64 = kn, rows 65-71 zero */
            const float* kvp = &g_kv[(size_t)b * TWOM * KVW];
            for (int i = tid; i < 128 * 64; i += 512) {
                int p = i >> 6, n = i & 63;
                float v0 = kvp[(2 * p) * KVW + n];
                float v1 = kvp[(2 * p + 1) * KVW + n];
                uint32_t hw = pack_hi(v0, v1);
                BT[n * 260 + p]       = hw;
                BT[n * 260 + 128 + p] = pack_lo(v0, v1, hw);
            }
            if (tid < 128) {
                int p = tid;
                float v0 = kvp[(2 * p) * KVW + 64];
                float v1 = kvp[(2 * p + 1) * KVW + 64];
                uint32_t hw = pack_hi(v0, v1);
                BT[64 * 260 + p]       = hw;
                BT[64 * 260 + 128 + p] = pack_lo(v0, v1, hw);
            }
            for (int i = tid; i < 7 * 256; i += 512) {
                int r = 65 + (i >> 8), wd = i & 255;
                BT[r * 260 + wd] = 0u;
            }
            cur_b = b;
        }

        for (int sub = 0; sub < 2; ++sub) {
            /* stage x -> XT hi/lo + ssq */
#pragma unroll
            for (int q = 0; q < 2; ++q) {
                int r = ldr + q * 32;
                float4 xv = px[2 * sub + q];
                int p0 = (tid & 15) * 2;
                uint32_t h0 = pack_hi(xv.x, xv.y), h1 = pack_hi(xv.z, xv.w);
                uint32_t l0 = pack_lo(xv.x, xv.y, h0), l1 = pack_lo(xv.z, xv.w, h1);
                *(uint2*)(smc + QOFF_XT + (size_t)(r * 68 + p0) * 4)      = make_uint2(h0, h1);
                *(uint2*)(smc + QOFF_XT + (size_t)(r * 68 + 32 + p0) * 4) = make_uint2(l0, l1);
                float sq = xv.x * xv.x + xv.y * xv.y + xv.z * xv.z + xv.w * xv.w;
#pragma unroll
                for (int d = 1; d < 16; d <<= 1)
                    sq += __shfl_xor_sync(0xffffffffu, sq, d);
                if ((tid & 15) == 0) ssq_s[r] = 0.5f * sq;
            }
            if (sub == 1 && t + 1 < te) {
                int tn = t + 1, bn = tn >> 6, rn = (tn & 63) * 128;
                const float4* qp = (const float4*)(query + ((size_t)bn * TT + rn) * FF);
#pragma unroll
                for (int q = 0; q < 4; ++q) px[q] = qp[tid + q * 512];
            }
            __syncthreads();   /* XT, ssq (and BT after rebuild) ready */

            /* phi-MMA + exp + phiT store */
#pragma unroll
            for (int nt4 = 0; nt4 < 4; ++nt4) {
                const int ntp = ntb + nt4;
                float wa[4] = {0.f, 0.f, 0.f, 0.f};
#pragma unroll
                for (int kt = 0; kt < 4; ++kt) {
                    uint32_t bh0, bh1, bl0, bl1;
                    ldsm_x4(bh0, bh1, bl0, bl1, xtB + ntp * 2176 + kt * 32);
                    mma_bf16(wa, wfh[kt][0], wfh[kt][1], wfh[kt][2], wfh[kt][3], bh0, bh1);
                    mma_bf16(wa, wfl[kt][0], wfl[kt][1], wfl[kt][2], wfl[kt][3], bh0, bh1);
                    mma_bf16(wa, wfh[kt][0], wfh[kt][1], wfh[kt][2], wfh[kt][3], bl0, bl1);
                }
                const int rr = ntp * 8 + 2 * tg;
                const float sc0 = ssq_s[rr];
                const float sc1 = ssq_s[rr + 1];
#pragma unroll
                for (int half = 0; half < 2; ++half) {
                    int m = mt * 16 + gid + 8 * half;
                    float w0 = wa[2 * half], w1 = wa[2 * half + 1];
                    float e0 = (__expf(w0 - sc0) + EPSF) * SCALEF;
                    float e1 = (__expf(w1 - sc1) + EPSF) * SCALEF;
                    float g0 = (__expf(-w0 - sc0) + EPSF) * SCALEF;
                    float g1 = (__expf(-w1 - sc1) + EPSF) * SCALEF;
                    uint32_t he = pack_hi(e0, e1);
                    uint32_t hg = pack_hi(g0, g1);
                    *(uint32_t*)(smc + QOFF_PH + m * 144 + rr * 2)         = he;
                    *(uint32_t*)(smc + QOFF_PL + m * 144 + rr * 2)         = pack_lo(e0, e1, he);
                    *(uint32_t*)(smc + QOFF_PH + (m + 128) * 144 + rr * 2) = hg;
                    *(uint32_t*)(smc + QOFF_PL + (m + 128) * 144 + rr * 2) = pack_lo(g0, g1, hg);
                }
            }
            __syncthreads();   /* phiT ready */

            /* qkv-MMA; balanced full 3-term norm on kt = 2nt, 2nt+1 */
            float acc[2][4];
            float accN[2][4];
#pragma unroll
            for (int rt = 0; rt < 2; ++rt)
#pragma unroll
                for (int p = 0; p < 4; ++p) { acc[rt][p] = 0.f; accN[rt][p] = 0.f; }

#pragma unroll
            for (int kt = 0; kt < 16; ++kt) {
                uint32_t bh0, bh1, bl0, bl1;
                ldsm_x4(bh0, bh1, bl0, bl1, btB + nt * 8320 + kt * 32);
                const bool isn = ((kt >> 1) == nt);   /* compile-time */
                uint32_t bn0 = 0, bn1 = 0, bm0 = 0, bm1 = 0;
                if (isn) ldsm_x4(bn0, bn1, bm0, bm1, btB + 64 * 1040 + kt * 32);
#pragma unroll
                for (int rt = 0; rt < 2; ++rt) {
                    const int rbase = rh * 32 + rt * 16;
                    uint32_t aaddr = sb + QOFF_PH +
                        (uint32_t)((kt * 16 + krow) * 144 + (rbase + mcol) * 2);
                    uint32_t laddr = aaddr + (QOFF_PL - QOFF_PH);
                    uint32_t a0, a1, a2, a3, l0, l1, l2, l3;
                    ldsm_x4_t(a0, a1, a2, a3, aaddr);
                    ldsm_x4_t(l0, l1, l2, l3, laddr);
                    mma_bf16(acc[rt], a0, a1, a2, a3, bh0, bh1);
                    mma_bf16(acc[rt], l0, l1, l2, l3, bh0, bh1);
                    mma_bf16(acc[rt], a0, a1, a2, a3, bl0, bl1);
                    if (isn) {
                        mma_bf16(accN[rt], a0, a1, a2, a3, bn0, bn1);
                        mma_bf16(accN[rt], l0, l1, l2, l3, bn0, bn1);
                        mma_bf16(accN[rt], a0, a1, a2, a3, bm0, bm1);
                    }
                }
            }
            if (tg == 0) {
#pragma unroll
                for (int rt = 0; rt < 2; ++rt) {
                    int rbase = rh * 32 + rt * 16;
                    npb_s[nt * 66 + rbase + gid]     = accN[rt][0];
                    npb_s[nt * 66 + rbase + gid + 8] = accN[rt][2];
                }
            }
            __syncthreads();   /* partials ready */
            if (tid < 64) {
                float s = 0.f;
#pragma unroll
                for (int j = 0; j < 8; ++j) s += npb_s[j * 66 + tid];
                ns_s[tid] = s;
            }
            __syncthreads();   /* norm ready */

            /* epilogue */
#pragma unroll
            for (int rt = 0; rt < 2; ++rt) {
                int rbase = rh * 32 + rt * 16;
                int row0 = rbase + gid, row1 = row0 + 8;
                float inv0 = 1.0f / ns_s[row0];
                float inv1 = 1.0f / ns_s[row1];
                float* o0 = out + ((size_t)b * TT + r0 + sub * 64 + row0) * DD + nt * 8 + 2 * tg;
                float* o1 = out + ((size_t)b * TT + r0 + sub * 64 + row1) * DD + nt * 8 + 2 * tg;
                *(float2*)o0 = make_float2(acc[rt][0] * inv0, acc[rt][1] * inv0);
                *(float2*)o1 = make_float2(acc[rt][2] * inv1, acc[rt][3] * inv1);
            }
        }
    }
}

// ---------------------------------------------------------------------------

extern "C" void kernel_launch(void* const* d_in, const int* in_sizes, int n_in,
                              void* d_out, int out_size) {
    const float* query = (const float*)d_in[0];
    const float* value = (const float*)d_in[1];
    const float* key   = (const float*)d_in[2];
    const float* omega = (const float*)d_in[3];
    float* out = (float*)d_out;

    cudaFuncSetAttribute(kv_kernel, cudaFuncAttributeMaxDynamicSharedMemorySize, KV_SMEM);
    cudaFuncSetAttribute(qkv_kernel, cudaFuncAttributeMaxDynamicSharedMemorySize, QSMEM);

    kv_kernel<<<NBLK, 512, KV_SMEM>>>(key, value, omega);
    reduce_kernel<<<dim3((TWOM * KVW / 4 + 255) / 256, BB), 256>>>();
    qkv_kernel<<<QNB, 512, QSMEM>>>(query, omega, out);
}